// round 1
// baseline (speedup 1.0000x reference)
#include <cuda_runtime.h>
#include <math.h>

// Problem constants
#define Bb 2
#define Ss 4096
#define Dd 1024
#define Hh 16
#define HDh 64
#define Rr 16
#define Mm (Bb*Ss)            // 8192 rows

// ---------------- device scratch (module-load allocated, not runtime alloc) ----------
__device__ float g_Wq[Dd*Dd];
__device__ float g_Wk[Dd*Dd];
__device__ float g_Wv[Dd*Dd];
__device__ float g_Wo[Dd*Dd];
__device__ float g_Q[(size_t)Mm*Dd];
__device__ float g_K[(size_t)Mm*Dd];
__device__ float g_V[(size_t)Mm*Dd];
__device__ float g_AO[(size_t)Mm*Dd];

// ---------------- W_eff = W + l2 @ l1  (fold LoRA into dense weight) ---------------
__global__ void build_weff_kernel(const float* __restrict__ w,
                                  const float* __restrict__ l1,   // (R, D)
                                  const float* __restrict__ l2,   // (D, R)
                                  float* __restrict__ out) {
    int idx = blockIdx.x * blockDim.x + threadIdx.x;   // over D*D
    int n = idx >> 10, k = idx & 1023;
    float acc = w[idx];
#pragma unroll
    for (int r = 0; r < Rr; r++) acc += l2[n*Rr + r] * l1[r*Dd + k];
    out[idx] = acc;
}

// ---------------- SGEMM: C[M,1024] = A[M,1024] @ W[1024,1024]^T (+bias) -------------
// 128x128 block tile, BK=16, 256 threads, 8x8 microtile (split 4+4 for
// conflict-free LDS.128).
__global__ __launch_bounds__(256) void sgemm_kernel(
    const float* __restrict__ A, const float* __restrict__ W,
    const float* __restrict__ bias, float* __restrict__ C)
{
    __shared__ float As[16][128];
    __shared__ float Bs[16][128];
    const int tid = threadIdx.x;
    const int bm = blockIdx.y * 128;
    const int bn = blockIdx.x * 128;
    const int tx = tid & 15, ty = tid >> 4;
    const int lr = tid >> 2;          // 0..63
    const int lc = (tid & 3) << 2;    // 0,4,8,12
    float acc[8][8] = {};
    const float* Aptr = A + (size_t)(bm + lr) * Dd + lc;
    const float* Wptr = W + (size_t)(bn + lr) * Dd + lc;

    for (int k0 = 0; k0 < Dd; k0 += 16) {
        float4 a0 = *(const float4*)(Aptr + k0);
        float4 a1 = *(const float4*)(Aptr + k0 + (size_t)64*Dd);
        float4 b0 = *(const float4*)(Wptr + k0);
        float4 b1 = *(const float4*)(Wptr + k0 + (size_t)64*Dd);
        __syncthreads();
        As[lc+0][lr]    = a0.x; As[lc+1][lr]    = a0.y; As[lc+2][lr]    = a0.z; As[lc+3][lr]    = a0.w;
        As[lc+0][lr+64] = a1.x; As[lc+1][lr+64] = a1.y; As[lc+2][lr+64] = a1.z; As[lc+3][lr+64] = a1.w;
        Bs[lc+0][lr]    = b0.x; Bs[lc+1][lr]    = b0.y; Bs[lc+2][lr]    = b0.z; Bs[lc+3][lr]    = b0.w;
        Bs[lc+0][lr+64] = b1.x; Bs[lc+1][lr+64] = b1.y; Bs[lc+2][lr+64] = b1.z; Bs[lc+3][lr+64] = b1.w;
        __syncthreads();
#pragma unroll
        for (int kk = 0; kk < 16; kk++) {
            float a[8], b[8];
            *(float4*)&a[0] = *(const float4*)&As[kk][ty*4];
            *(float4*)&a[4] = *(const float4*)&As[kk][64 + ty*4];
            *(float4*)&b[0] = *(const float4*)&Bs[kk][tx*4];
            *(float4*)&b[4] = *(const float4*)&Bs[kk][64 + tx*4];
#pragma unroll
            for (int i = 0; i < 8; i++)
#pragma unroll
                for (int j = 0; j < 8; j++)
                    acc[i][j] += a[i] * b[j];
        }
    }

    float bv[8] = {0.f,0.f,0.f,0.f,0.f,0.f,0.f,0.f};
    if (bias) {
#pragma unroll
        for (int j = 0; j < 8; j++) {
            int col = bn + ((j < 4) ? tx*4 + j : 64 + tx*4 + (j-4));
            bv[j] = bias[col];
        }
    }
#pragma unroll
    for (int i = 0; i < 8; i++) {
        int row = bm + ((i < 4) ? ty*4 + i : 64 + ty*4 + (i-4));
        float4 o0 = make_float4(acc[i][0]+bv[0], acc[i][1]+bv[1], acc[i][2]+bv[2], acc[i][3]+bv[3]);
        float4 o1 = make_float4(acc[i][4]+bv[4], acc[i][5]+bv[5], acc[i][6]+bv[6], acc[i][7]+bv[7]);
        *(float4*)&C[(size_t)row*Dd + bn + tx*4]      = o0;
        *(float4*)&C[(size_t)row*Dd + bn + 64 + tx*4] = o1;
    }
}

// ---------------- RoPE on Q and K in-place -----------------------------------------
__global__ void rope_kernel(float* __restrict__ Q, float* __restrict__ Kt,
                            const float* __restrict__ fc, const float* __restrict__ fs) {
    int idx = blockIdx.x * blockDim.x + threadIdx.x;   // Mm * (Dd/2)
    int row  = idx >> 9;          // / 512
    int col2 = idx & 511;         // pair index within D: (h*32 + p)
    int p = col2 & 31;
    int s = row & (Ss - 1);
    float c  = fc[s*32 + p];
    float sn = fs[s*32 + p];
    size_t base = (size_t)row * Dd + 2*col2;
    float2 q = *(float2*)&Q[base];
    float2 k = *(float2*)&Kt[base];
    *(float2*)&Q[base]  = make_float2(q.x*c - q.y*sn, q.x*sn + q.y*c);
    *(float2*)&Kt[base] = make_float2(k.x*c - k.y*sn, k.x*sn + k.y*c);
}

// ---------------- Flash attention (causal, fp32) ------------------------------------
// Tile: 128 queries x 64 keys, HD=64. 128 threads (8x16), 8x8 microtiles.
// Q and K stored transposed in smem so both GEMM phases read LDS.128.
#define ABM 128
#define ABN 64
#define QT_STRIDE 132
#define KV_STRIDE 68
#define ATTN_SMEM ((64*QT_STRIDE + 64*KV_STRIDE + 64*QT_STRIDE) * 4)

__global__ __launch_bounds__(128) void attn_kernel(
    const float* __restrict__ Q, const float* __restrict__ K,
    const float* __restrict__ V, float* __restrict__ O)
{
    extern __shared__ float sm[];
    float* sQt = sm;                      // [64][132]  Q transposed: [d][r]
    float* sKV = sm + 64*QT_STRIDE;       // [64][68]   K transposed [d][j], later V [j][c]
    float* sPt = sKV + 64*KV_STRIDE;      // [64][132]  P transposed: [j][r]

    const int tid = threadIdx.x;
    const int tx = tid & 7, ty = tid >> 3;
    const int qt = blockIdx.x;
    const int bh = blockIdx.y;
    const int b = bh >> 4;
    const int h = bh & 15;
    const float* Qb = Q + (size_t)b * Ss * Dd + (size_t)h * HDh;
    const float* Kb = K + (size_t)b * Ss * Dd + (size_t)h * HDh;
    const float* Vb = V + (size_t)b * Ss * Dd + (size_t)h * HDh;

    // Load Q tile transposed (each thread owns one of the 128 rows)
    {
        const float* src = Qb + (size_t)(qt * ABM + tid) * Dd;
#pragma unroll
        for (int d4 = 0; d4 < 16; d4++) {
            float4 v = *(const float4*)(src + d4*4);
            sQt[(d4*4+0)*QT_STRIDE + tid] = v.x;
            sQt[(d4*4+1)*QT_STRIDE + tid] = v.y;
            sQt[(d4*4+2)*QT_STRIDE + tid] = v.z;
            sQt[(d4*4+3)*QT_STRIDE + tid] = v.w;
        }
    }

    float accO[8][8] = {};
    float mrow[8], lrow[8];
#pragma unroll
    for (int i = 0; i < 8; i++) { mrow[i] = -1e30f; lrow[i] = 0.f; }

    int rowi[8], colj[8];
#pragma unroll
    for (int i = 0; i < 8; i++) rowi[i] = (i < 4) ? ty*4 + i : 64 + ty*4 + (i-4);
#pragma unroll
    for (int j = 0; j < 8; j++) colj[j] = (j < 4) ? tx*4 + j : 32 + tx*4 + (j-4);

    const int nkt = 2*qt + 2;   // causal: tiles 0..2qt+1
    for (int kt = 0; kt < nkt; kt++) {
        __syncthreads();   // prior PV reads of sKV done
        // Load K tile transposed: 64 rows x 64 d
        {
            int row = tid & 63;
            int c0 = (tid >> 6) * 32;
            const float* src = Kb + (size_t)(kt * ABN + row) * Dd + c0;
#pragma unroll
            for (int d4 = 0; d4 < 8; d4++) {
                float4 v = *(const float4*)(src + d4*4);
                int d = c0 + d4*4;
                sKV[(d+0)*KV_STRIDE + row] = v.x;
                sKV[(d+1)*KV_STRIDE + row] = v.y;
                sKV[(d+2)*KV_STRIDE + row] = v.z;
                sKV[(d+3)*KV_STRIDE + row] = v.w;
            }
        }
        __syncthreads();

        // S = Q @ K^T
        float Sc[8][8] = {};
#pragma unroll 8
        for (int d = 0; d < HDh; d++) {
            float a[8], bb[8];
            *(float4*)&a[0]  = *(const float4*)&sQt[d*QT_STRIDE + ty*4];
            *(float4*)&a[4]  = *(const float4*)&sQt[d*QT_STRIDE + 64 + ty*4];
            *(float4*)&bb[0] = *(const float4*)&sKV[d*KV_STRIDE + tx*4];
            *(float4*)&bb[4] = *(const float4*)&sKV[d*KV_STRIDE + 32 + tx*4];
#pragma unroll
            for (int i = 0; i < 8; i++)
#pragma unroll
                for (int j = 0; j < 8; j++)
                    Sc[i][j] += a[i] * bb[j];
        }

        // scale + causal mask (only last two tiles touch the diagonal)
        const bool need_mask = (kt >= 2*qt);
#pragma unroll
        for (int i = 0; i < 8; i++) {
            int qg = qt*ABM + rowi[i];
#pragma unroll
            for (int j = 0; j < 8; j++) {
                float v = Sc[i][j] * 0.125f;
                if (need_mask && (kt*ABN + colj[j] > qg)) v = -1e30f;
                Sc[i][j] = v;
            }
        }

        // online softmax (row groups span 8 consecutive lanes -> shfl width 8)
#pragma unroll
        for (int i = 0; i < 8; i++) {
            float mx = Sc[i][0];
#pragma unroll
            for (int j = 1; j < 8; j++) mx = fmaxf(mx, Sc[i][j]);
            mx = fmaxf(mx, __shfl_xor_sync(0xffffffffu, mx, 1, 8));
            mx = fmaxf(mx, __shfl_xor_sync(0xffffffffu, mx, 2, 8));
            mx = fmaxf(mx, __shfl_xor_sync(0xffffffffu, mx, 4, 8));
            float mnew = fmaxf(mrow[i], mx);
            float corr = __expf(mrow[i] - mnew);
            mrow[i] = mnew;
            float s = 0.f;
#pragma unroll
            for (int j = 0; j < 8; j++) {
                float p = __expf(Sc[i][j] - mnew);
                Sc[i][j] = p;
                s += p;
            }
            s += __shfl_xor_sync(0xffffffffu, s, 1, 8);
            s += __shfl_xor_sync(0xffffffffu, s, 2, 8);
            s += __shfl_xor_sync(0xffffffffu, s, 4, 8);
            lrow[i] = lrow[i]*corr + s;
#pragma unroll
            for (int j = 0; j < 8; j++) accO[i][j] *= corr;
        }

        // write P transposed
#pragma unroll
        for (int i = 0; i < 8; i++)
#pragma unroll
            for (int j = 0; j < 8; j++)
                sPt[colj[j]*QT_STRIDE + rowi[i]] = Sc[i][j];
        __syncthreads();

        // load V over the K buffer: [j][c]
        {
            int row = tid & 63;
            int c0 = (tid >> 6) * 32;
            const float* src = Vb + (size_t)(kt * ABN + row) * Dd + c0;
#pragma unroll
            for (int d4 = 0; d4 < 8; d4++)
                *(float4*)&sKV[row*KV_STRIDE + c0 + d4*4] = *(const float4*)(src + d4*4);
        }
        __syncthreads();

        // O += P @ V
#pragma unroll 8
        for (int j = 0; j < ABN; j++) {
            float p[8], v[8];
            *(float4*)&p[0] = *(const float4*)&sPt[j*QT_STRIDE + ty*4];
            *(float4*)&p[4] = *(const float4*)&sPt[j*QT_STRIDE + 64 + ty*4];
            *(float4*)&v[0] = *(const float4*)&sKV[j*KV_STRIDE + tx*4];
            *(float4*)&v[4] = *(const float4*)&sKV[j*KV_STRIDE + 32 + tx*4];
#pragma unroll
            for (int i = 0; i < 8; i++)
#pragma unroll
                for (int jj = 0; jj < 8; jj++)
                    accO[i][jj] += p[i] * v[jj];
        }
    }

    // epilogue: normalize and store
#pragma unroll
    for (int i = 0; i < 8; i++) {
        float inv = 1.f / lrow[i];
        size_t rbase = ((size_t)b*Ss + (size_t)qt*ABM + rowi[i]) * Dd + (size_t)h*HDh;
        float4 o0 = make_float4(accO[i][0]*inv, accO[i][1]*inv, accO[i][2]*inv, accO[i][3]*inv);
        float4 o1 = make_float4(accO[i][4]*inv, accO[i][5]*inv, accO[i][6]*inv, accO[i][7]*inv);
        *(float4*)&O[rbase + tx*4]      = o0;
        *(float4*)&O[rbase + 32 + tx*4] = o1;
    }
}

// ---------------- launch -------------------------------------------------------------
extern "C" void kernel_launch(void* const* d_in, const int* in_sizes, int n_in,
                              void* d_out, int out_size) {
    const float* x   = (const float*)d_in[0];
    const float* fc  = (const float*)d_in[1];
    const float* fs  = (const float*)d_in[2];
    // d_in[3] = mask (causal, reproduced analytically)
    const float* wq  = (const float*)d_in[4];
    const float* wqb = (const float*)d_in[5];
    const float* wk  = (const float*)d_in[6];
    const float* wv  = (const float*)d_in[7];
    const float* wo  = (const float*)d_in[8];
    const float* wob = (const float*)d_in[9];
    const float* lq1 = (const float*)d_in[10];
    const float* lq2 = (const float*)d_in[11];
    const float* lk1 = (const float*)d_in[12];
    const float* lk2 = (const float*)d_in[13];
    const float* lv1 = (const float*)d_in[14];
    const float* lv2 = (const float*)d_in[15];
    const float* lo1 = (const float*)d_in[16];
    const float* lo2 = (const float*)d_in[17];

    float *Wq, *Wk, *Wv, *Wo, *Qp, *Kp, *Vp, *AO;
    cudaGetSymbolAddress((void**)&Wq, g_Wq);
    cudaGetSymbolAddress((void**)&Wk, g_Wk);
    cudaGetSymbolAddress((void**)&Wv, g_Wv);
    cudaGetSymbolAddress((void**)&Wo, g_Wo);
    cudaGetSymbolAddress((void**)&Qp, g_Q);
    cudaGetSymbolAddress((void**)&Kp, g_K);
    cudaGetSymbolAddress((void**)&Vp, g_V);
    cudaGetSymbolAddress((void**)&AO, g_AO);

    cudaFuncSetAttribute(attn_kernel, cudaFuncAttributeMaxDynamicSharedMemorySize, ATTN_SMEM);

    // 1. Fold LoRA into effective weights
    build_weff_kernel<<<(Dd*Dd)/256, 256>>>(wq, lq1, lq2, Wq);
    build_weff_kernel<<<(Dd*Dd)/256, 256>>>(wk, lk1, lk2, Wk);
    build_weff_kernel<<<(Dd*Dd)/256, 256>>>(wv, lv1, lv2, Wv);
    build_weff_kernel<<<(Dd*Dd)/256, 256>>>(wo, lo1, lo2, Wo);

    // 2. Q/K/V projections
    dim3 gg(Dd/128, Mm/128);
    sgemm_kernel<<<gg, 256>>>(x, Wq, wqb,    Qp);
    sgemm_kernel<<<gg, 256>>>(x, Wk, nullptr, Kp);
    sgemm_kernel<<<gg, 256>>>(x, Wv, nullptr, Vp);

    // 3. RoPE in place on Q and K
    rope_kernel<<<(Mm*(Dd/2))/256, 256>>>(Qp, Kp, fc, fs);

    // 4. Causal flash attention
    dim3 ga(Ss/ABM, Bb*Hh);
    attn_kernel<<<ga, 128, ATTN_SMEM>>>(Qp, Kp, Vp, AO);

    // 5. Output projection straight into d_out
    sgemm_kernel<<<gg, 256>>>(AO, Wo, wob, (float*)d_out);
}

// round 2
// speedup vs baseline: 1.4159x; 1.4159x over previous
#include <cuda_runtime.h>
#include <math.h>
#include <stdint.h>

// Problem constants
#define Bb 2
#define Ss 4096
#define Dd 1024
#define Hh 16
#define HDh 64
#define Rr 16
#define Mm (Bb*Ss)            // 8192 rows

// ---------------- device scratch ----------------------------------------------------
__device__ float g_Wq[Dd*Dd];
__device__ float g_Wk[Dd*Dd];
__device__ float g_Wv[Dd*Dd];
__device__ float g_Wo[Dd*Dd];
__device__ float g_X [(size_t)Mm*Dd];
__device__ float g_Q [(size_t)Mm*Dd];
__device__ float g_K [(size_t)Mm*Dd];
__device__ float g_V [(size_t)Mm*Dd];
__device__ float g_AO[(size_t)Mm*Dd];

__device__ __forceinline__ float tf32r(float x) {
    float y;
    asm("cvt.rna.tf32.f32 %0, %1;" : "=f"(y) : "f"(x));
    return y;
}

// ---------------- W_eff = tf32( W + l2 @ l1 ) ---------------------------------------
__global__ void build_weff_kernel(const float* __restrict__ w,
                                  const float* __restrict__ l1,   // (R, D)
                                  const float* __restrict__ l2,   // (D, R)
                                  float* __restrict__ out) {
    int idx = blockIdx.x * blockDim.x + threadIdx.x;   // over D*D
    int n = idx >> 10, k = idx & 1023;
    float acc = w[idx];
#pragma unroll
    for (int r = 0; r < Rr; r++) acc += l2[n*Rr + r] * l1[r*Dd + k];
    out[idx] = tf32r(acc);
}

// ---------------- x -> tf32-rounded copy ---------------------------------------------
__global__ void round_x_kernel(const float4* __restrict__ in, float4* __restrict__ out) {
    int i = blockIdx.x * blockDim.x + threadIdx.x;
    float4 v = in[i];
    out[i] = make_float4(tf32r(v.x), tf32r(v.y), tf32r(v.z), tf32r(v.w));
}

// ---------------- TF32 tensor-core GEMM: C[M,1024] = A @ W^T (+bias) -----------------
// 128x128 block tile, BK=32, 256 threads (8 warps, 4x2), warp tile 32x64.
// mma.sync.m16n8k8.tf32, cp.async double-buffered smem, stride-36 (conflict-free).
#define BM 128
#define BN 128
#define BK 32
#define SST 36
#define GEMM_SMEM (2 * 2 * BM * SST * 4)

#define CP16(dst, src) asm volatile("cp.async.cg.shared.global [%0], [%1], 16;" :: "r"(dst), "l"(src))

__global__ __launch_bounds__(256) void mma_gemm_kernel(
    const float* __restrict__ A, const float* __restrict__ W,
    const float* __restrict__ bias, float* __restrict__ C)
{
    extern __shared__ float sm[];
    float* sA = sm;                       // [2][128][36]
    float* sB = sm + 2*BM*SST;            // [2][128][36]

    const int tid  = threadIdx.x;
    const int bm   = blockIdx.y * BM;
    const int bn   = blockIdx.x * BN;
    const int warp = tid >> 5, lane = tid & 31;
    const int g = lane >> 2;              // 0..7
    const int q = lane & 3;               // 0..3
    const int wm = (warp >> 1) * 32;
    const int wn = (warp & 1) * 64;

    uint32_t sA_sh = (uint32_t)__cvta_generic_to_shared(sA);
    uint32_t sB_sh = (uint32_t)__cvta_generic_to_shared(sB);

    float acc[2][8][4] = {};

    const int NIT = Dd / BK;   // 32

    // prologue: stage 0
    {
#pragma unroll
        for (int j = 0; j < 4; j++) {
            int cl = tid + 256*j;
            int row = cl >> 3, kc = (cl & 7) * 4;
            uint32_t so = (uint32_t)(row*SST + kc) * 4u;
            CP16(sA_sh + so, A + (size_t)(bm + row) * Dd + kc);
            CP16(sB_sh + so, W + (size_t)(bn + row) * Dd + kc);
        }
        asm volatile("cp.async.commit_group;");
    }

    for (int it = 0; it < NIT; it++) {
        if (it + 1 < NIT) {
            int k0 = (it + 1) * BK;
            uint32_t stg = (uint32_t)((it + 1) & 1) * BM * SST * 4u;
#pragma unroll
            for (int j = 0; j < 4; j++) {
                int cl = tid + 256*j;
                int row = cl >> 3, kc = (cl & 7) * 4;
                uint32_t so = stg + (uint32_t)(row*SST + kc) * 4u;
                CP16(sA_sh + so, A + (size_t)(bm + row) * Dd + k0 + kc);
                CP16(sB_sh + so, W + (size_t)(bn + row) * Dd + k0 + kc);
            }
            asm volatile("cp.async.commit_group;");
            asm volatile("cp.async.wait_group 1;");
        } else {
            asm volatile("cp.async.wait_group 0;");
        }
        __syncthreads();

        const float* cA = sA + (it & 1) * BM * SST;
        const float* cB = sB + (it & 1) * BM * SST;

#pragma unroll
        for (int kk = 0; kk < 4; kk++) {
            const int kb = kk * 8;
            uint32_t af[2][4], bf[8][2];
#pragma unroll
            for (int mi = 0; mi < 2; mi++) {
                int m = wm + mi*16 + g;
                af[mi][0] = __float_as_uint(cA[m      *SST + kb + q]);
                af[mi][1] = __float_as_uint(cA[(m + 8)*SST + kb + q]);
                af[mi][2] = __float_as_uint(cA[m      *SST + kb + q + 4]);
                af[mi][3] = __float_as_uint(cA[(m + 8)*SST + kb + q + 4]);
            }
#pragma unroll
            for (int ni = 0; ni < 8; ni++) {
                int n = wn + ni*8 + g;
                bf[ni][0] = __float_as_uint(cB[n*SST + kb + q]);
                bf[ni][1] = __float_as_uint(cB[n*SST + kb + q + 4]);
            }
#pragma unroll
            for (int mi = 0; mi < 2; mi++)
#pragma unroll
                for (int ni = 0; ni < 8; ni++) {
                    asm volatile(
                        "mma.sync.aligned.m16n8k8.row.col.f32.tf32.tf32.f32 "
                        "{%0,%1,%2,%3}, {%4,%5,%6,%7}, {%8,%9}, {%0,%1,%2,%3};"
                        : "+f"(acc[mi][ni][0]), "+f"(acc[mi][ni][1]),
                          "+f"(acc[mi][ni][2]), "+f"(acc[mi][ni][3])
                        : "r"(af[mi][0]), "r"(af[mi][1]), "r"(af[mi][2]), "r"(af[mi][3]),
                          "r"(bf[ni][0]), "r"(bf[ni][1]));
                }
        }
        __syncthreads();
    }

    // epilogue
#pragma unroll
    for (int mi = 0; mi < 2; mi++) {
        int r0 = bm + wm + mi*16 + g;
#pragma unroll
        for (int ni = 0; ni < 8; ni++) {
            int cn = bn + wn + ni*8 + q*2;
            float b0 = 0.f, b1 = 0.f;
            if (bias) { b0 = bias[cn]; b1 = bias[cn+1]; }
            *(float2*)&C[(size_t)r0     *Dd + cn] = make_float2(acc[mi][ni][0]+b0, acc[mi][ni][1]+b1);
            *(float2*)&C[(size_t)(r0+8) *Dd + cn] = make_float2(acc[mi][ni][2]+b0, acc[mi][ni][3]+b1);
        }
    }
}

// ---------------- RoPE on Q and K in-place -----------------------------------------
__global__ void rope_kernel(float* __restrict__ Q, float* __restrict__ Kt,
                            const float* __restrict__ fc, const float* __restrict__ fs) {
    int idx = blockIdx.x * blockDim.x + threadIdx.x;   // Mm * (Dd/2)
    int row  = idx >> 9;
    int col2 = idx & 511;
    int p = col2 & 31;
    int s = row & (Ss - 1);
    float c  = fc[s*32 + p];
    float sn = fs[s*32 + p];
    size_t base = (size_t)row * Dd + 2*col2;
    float2 qv = *(float2*)&Q[base];
    float2 kv = *(float2*)&Kt[base];
    *(float2*)&Q[base]  = make_float2(qv.x*c - qv.y*sn, qv.x*sn + qv.y*c);
    *(float2*)&Kt[base] = make_float2(kv.x*c - kv.y*sn, kv.x*sn + kv.y*c);
}

// ---------------- Flash attention (causal, fp32) ------------------------------------
#define ABM 128
#define ABN 64
#define QT_STRIDE 132
#define KV_STRIDE 68
#define ATTN_SMEM ((64*QT_STRIDE + 64*KV_STRIDE + 64*QT_STRIDE) * 4)

__global__ __launch_bounds__(128) void attn_kernel(
    const float* __restrict__ Q, const float* __restrict__ K,
    const float* __restrict__ V, float* __restrict__ O)
{
    extern __shared__ float sm[];
    float* sQt = sm;
    float* sKV = sm + 64*QT_STRIDE;
    float* sPt = sKV + 64*KV_STRIDE;

    const int tid = threadIdx.x;
    const int tx = tid & 7, ty = tid >> 3;
    const int qt = blockIdx.x;
    const int bh = blockIdx.y;
    const int b = bh >> 4;
    const int h = bh & 15;
    const float* Qb = Q + (size_t)b * Ss * Dd + (size_t)h * HDh;
    const float* Kb = K + (size_t)b * Ss * Dd + (size_t)h * HDh;
    const float* Vb = V + (size_t)b * Ss * Dd + (size_t)h * HDh;

    {
        const float* src = Qb + (size_t)(qt * ABM + tid) * Dd;
#pragma unroll
        for (int d4 = 0; d4 < 16; d4++) {
            float4 v = *(const float4*)(src + d4*4);
            sQt[(d4*4+0)*QT_STRIDE + tid] = v.x;
            sQt[(d4*4+1)*QT_STRIDE + tid] = v.y;
            sQt[(d4*4+2)*QT_STRIDE + tid] = v.z;
            sQt[(d4*4+3)*QT_STRIDE + tid] = v.w;
        }
    }

    float accO[8][8] = {};
    float mrow[8], lrow[8];
#pragma unroll
    for (int i = 0; i < 8; i++) { mrow[i] = -1e30f; lrow[i] = 0.f; }

    int rowi[8], colj[8];
#pragma unroll
    for (int i = 0; i < 8; i++) rowi[i] = (i < 4) ? ty*4 + i : 64 + ty*4 + (i-4);
#pragma unroll
    for (int j = 0; j < 8; j++) colj[j] = (j < 4) ? tx*4 + j : 32 + tx*4 + (j-4);

    const int nkt = 2*qt + 2;
    for (int kt = 0; kt < nkt; kt++) {
        __syncthreads();
        {
            int row = tid & 63;
            int c0 = (tid >> 6) * 32;
            const float* src = Kb + (size_t)(kt * ABN + row) * Dd + c0;
#pragma unroll
            for (int d4 = 0; d4 < 8; d4++) {
                float4 v = *(const float4*)(src + d4*4);
                int d = c0 + d4*4;
                sKV[(d+0)*KV_STRIDE + row] = v.x;
                sKV[(d+1)*KV_STRIDE + row] = v.y;
                sKV[(d+2)*KV_STRIDE + row] = v.z;
                sKV[(d+3)*KV_STRIDE + row] = v.w;
            }
        }
        __syncthreads();

        float Sc[8][8] = {};
#pragma unroll 8
        for (int d = 0; d < HDh; d++) {
            float a[8], bb[8];
            *(float4*)&a[0]  = *(const float4*)&sQt[d*QT_STRIDE + ty*4];
            *(float4*)&a[4]  = *(const float4*)&sQt[d*QT_STRIDE + 64 + ty*4];
            *(float4*)&bb[0] = *(const float4*)&sKV[d*KV_STRIDE + tx*4];
            *(float4*)&bb[4] = *(const float4*)&sKV[d*KV_STRIDE + 32 + tx*4];
#pragma unroll
            for (int i = 0; i < 8; i++)
#pragma unroll
                for (int j = 0; j < 8; j++)
                    Sc[i][j] += a[i] * bb[j];
        }

        const bool need_mask = (kt >= 2*qt);
#pragma unroll
        for (int i = 0; i < 8; i++) {
            int qg = qt*ABM + rowi[i];
#pragma unroll
            for (int j = 0; j < 8; j++) {
                float v = Sc[i][j] * 0.125f;
                if (need_mask && (kt*ABN + colj[j] > qg)) v = -1e30f;
                Sc[i][j] = v;
            }
        }

#pragma unroll
        for (int i = 0; i < 8; i++) {
            float mx = Sc[i][0];
#pragma unroll
            for (int j = 1; j < 8; j++) mx = fmaxf(mx, Sc[i][j]);
            mx = fmaxf(mx, __shfl_xor_sync(0xffffffffu, mx, 1, 8));
            mx = fmaxf(mx, __shfl_xor_sync(0xffffffffu, mx, 2, 8));
            mx = fmaxf(mx, __shfl_xor_sync(0xffffffffu, mx, 4, 8));
            float mnew = fmaxf(mrow[i], mx);
            float corr = __expf(mrow[i] - mnew);
            mrow[i] = mnew;
            float s = 0.f;
#pragma unroll
            for (int j = 0; j < 8; j++) {
                float p = __expf(Sc[i][j] - mnew);
                Sc[i][j] = p;
                s += p;
            }
            s += __shfl_xor_sync(0xffffffffu, s, 1, 8);
            s += __shfl_xor_sync(0xffffffffu, s, 2, 8);
            s += __shfl_xor_sync(0xffffffffu, s, 4, 8);
            lrow[i] = lrow[i]*corr + s;
#pragma unroll
            for (int j = 0; j < 8; j++) accO[i][j] *= corr;
        }

#pragma unroll
        for (int i = 0; i < 8; i++)
#pragma unroll
            for (int j = 0; j < 8; j++)
                sPt[colj[j]*QT_STRIDE + rowi[i]] = Sc[i][j];
        __syncthreads();

        {
            int row = tid & 63;
            int c0 = (tid >> 6) * 32;
            const float* src = Vb + (size_t)(kt * ABN + row) * Dd + c0;
#pragma unroll
            for (int d4 = 0; d4 < 8; d4++)
                *(float4*)&sKV[row*KV_STRIDE + c0 + d4*4] = *(const float4*)(src + d4*4);
        }
        __syncthreads();

#pragma unroll 8
        for (int j = 0; j < ABN; j++) {
            float p[8], v[8];
            *(float4*)&p[0] = *(const float4*)&sPt[j*QT_STRIDE + ty*4];
            *(float4*)&p[4] = *(const float4*)&sPt[j*QT_STRIDE + 64 + ty*4];
            *(float4*)&v[0] = *(const float4*)&sKV[j*KV_STRIDE + tx*4];
            *(float4*)&v[4] = *(const float4*)&sKV[j*KV_STRIDE + 32 + tx*4];
#pragma unroll
            for (int i = 0; i < 8; i++)
#pragma unroll
                for (int jj = 0; jj < 8; jj++)
                    accO[i][jj] += p[i] * v[jj];
        }
    }

    // epilogue: normalize, round to tf32 (feeds the tf32 O-projection), store
#pragma unroll
    for (int i = 0; i < 8; i++) {
        float inv = 1.f / lrow[i];
        size_t rbase = ((size_t)b*Ss + (size_t)qt*ABM + rowi[i]) * Dd + (size_t)h*HDh;
        float4 o0 = make_float4(tf32r(accO[i][0]*inv), tf32r(accO[i][1]*inv),
                                tf32r(accO[i][2]*inv), tf32r(accO[i][3]*inv));
        float4 o1 = make_float4(tf32r(accO[i][4]*inv), tf32r(accO[i][5]*inv),
                                tf32r(accO[i][6]*inv), tf32r(accO[i][7]*inv));
        *(float4*)&O[rbase + tx*4]      = o0;
        *(float4*)&O[rbase + 32 + tx*4] = o1;
    }
}

// ---------------- launch -------------------------------------------------------------
extern "C" void kernel_launch(void* const* d_in, const int* in_sizes, int n_in,
                              void* d_out, int out_size) {
    const float* x   = (const float*)d_in[0];
    const float* fc  = (const float*)d_in[1];
    const float* fs  = (const float*)d_in[2];
    const float* wq  = (const float*)d_in[4];
    const float* wqb = (const float*)d_in[5];
    const float* wk  = (const float*)d_in[6];
    const float* wv  = (const float*)d_in[7];
    const float* wo  = (const float*)d_in[8];
    const float* wob = (const float*)d_in[9];
    const float* lq1 = (const float*)d_in[10];
    const float* lq2 = (const float*)d_in[11];
    const float* lk1 = (const float*)d_in[12];
    const float* lk2 = (const float*)d_in[13];
    const float* lv1 = (const float*)d_in[14];
    const float* lv2 = (const float*)d_in[15];
    const float* lo1 = (const float*)d_in[16];
    const float* lo2 = (const float*)d_in[17];

    float *Wq, *Wk, *Wv, *Wo, *Xr, *Qp, *Kp, *Vp, *AO;
    cudaGetSymbolAddress((void**)&Wq, g_Wq);
    cudaGetSymbolAddress((void**)&Wk, g_Wk);
    cudaGetSymbolAddress((void**)&Wv, g_Wv);
    cudaGetSymbolAddress((void**)&Wo, g_Wo);
    cudaGetSymbolAddress((void**)&Xr, g_X);
    cudaGetSymbolAddress((void**)&Qp, g_Q);
    cudaGetSymbolAddress((void**)&Kp, g_K);
    cudaGetSymbolAddress((void**)&Vp, g_V);
    cudaGetSymbolAddress((void**)&AO, g_AO);

    cudaFuncSetAttribute(attn_kernel, cudaFuncAttributeMaxDynamicSharedMemorySize, ATTN_SMEM);
    cudaFuncSetAttribute(mma_gemm_kernel, cudaFuncAttributeMaxDynamicSharedMemorySize, GEMM_SMEM);

    // 1. Fold LoRA into effective weights (tf32-rounded), round x to tf32
    build_weff_kernel<<<(Dd*Dd)/256, 256>>>(wq, lq1, lq2, Wq);
    build_weff_kernel<<<(Dd*Dd)/256, 256>>>(wk, lk1, lk2, Wk);
    build_weff_kernel<<<(Dd*Dd)/256, 256>>>(wv, lv1, lv2, Wv);
    build_weff_kernel<<<(Dd*Dd)/256, 256>>>(wo, lo1, lo2, Wo);
    round_x_kernel<<<(Mm*Dd/4)/256, 256>>>((const float4*)x, (float4*)Xr);

    // 2. Q/K/V projections (tensor cores, tf32)
    dim3 gg(Dd/BN, Mm/BM);
    mma_gemm_kernel<<<gg, 256, GEMM_SMEM>>>(Xr, Wq, wqb,    Qp);
    mma_gemm_kernel<<<gg, 256, GEMM_SMEM>>>(Xr, Wk, nullptr, Kp);
    mma_gemm_kernel<<<gg, 256, GEMM_SMEM>>>(Xr, Wv, nullptr, Vp);

    // 3. RoPE in place on Q and K
    rope_kernel<<<(Mm*(Dd/2))/256, 256>>>(Qp, Kp, fc, fs);

    // 4. Causal flash attention (fp32)
    dim3 ga(Ss/ABM, Bb*Hh);
    attn_kernel<<<ga, 128, ATTN_SMEM>>>(Qp, Kp, Vp, AO);

    // 5. Output projection (tensor cores) straight into d_out
    mma_gemm_kernel<<<gg, 256, GEMM_SMEM>>>(AO, Wo, wob, (float*)d_out);
}

// round 3
// speedup vs baseline: 2.5754x; 1.8189x over previous
#include <cuda_runtime.h>
#include <cuda_bf16.h>
#include <math.h>
#include <stdint.h>

// Problem constants
#define Bb 2
#define Ss 4096
#define Dd 1024
#define Hh 16
#define HDh 64
#define Rr 16
#define Mm (Bb*Ss)            // 8192 rows

// ---------------- device scratch ----------------------------------------------------
__device__ float g_Wq[Dd*Dd];
__device__ float g_Wk[Dd*Dd];
__device__ float g_Wv[Dd*Dd];
__device__ float g_Wo[Dd*Dd];
__device__ float g_X [(size_t)Mm*Dd];
__device__ float g_Q [(size_t)Mm*Dd];
__device__ float g_K [(size_t)Mm*Dd];
__device__ float g_V [(size_t)Mm*Dd];
__device__ float g_AO[(size_t)Mm*Dd];
__device__ __nv_bfloat16 g_Qh[(size_t)Mm*Dd];
__device__ __nv_bfloat16 g_Ql[(size_t)Mm*Dd];
__device__ __nv_bfloat16 g_Kh[(size_t)Mm*Dd];
__device__ __nv_bfloat16 g_Kl[(size_t)Mm*Dd];

__device__ __forceinline__ float tf32r(float x) {
    float y;
    asm("cvt.rna.tf32.f32 %0, %1;" : "=f"(y) : "f"(x));
    return y;
}

// ---------------- W_eff = tf32( W + l2 @ l1 ) ---------------------------------------
__global__ void build_weff_kernel(const float* __restrict__ w,
                                  const float* __restrict__ l1,
                                  const float* __restrict__ l2,
                                  float* __restrict__ out) {
    int idx = blockIdx.x * blockDim.x + threadIdx.x;
    int n = idx >> 10, k = idx & 1023;
    float acc = w[idx];
#pragma unroll
    for (int r = 0; r < Rr; r++) acc += l2[n*Rr + r] * l1[r*Dd + k];
    out[idx] = tf32r(acc);
}

__global__ void round_x_kernel(const float4* __restrict__ in, float4* __restrict__ out) {
    int i = blockIdx.x * blockDim.x + threadIdx.x;
    float4 v = in[i];
    out[i] = make_float4(tf32r(v.x), tf32r(v.y), tf32r(v.z), tf32r(v.w));
}

// ---------------- TF32 tensor-core GEMM (round-2, unchanged) ------------------------
#define BM 128
#define BN 128
#define BK 32
#define SST 36
#define GEMM_SMEM (2 * 2 * BM * SST * 4)

#define CP16(dst, src) asm volatile("cp.async.cg.shared.global [%0], [%1], 16;" :: "r"(dst), "l"(src))

__global__ __launch_bounds__(256) void mma_gemm_kernel(
    const float* __restrict__ A, const float* __restrict__ W,
    const float* __restrict__ bias, float* __restrict__ C)
{
    extern __shared__ float sm[];
    float* sA = sm;
    float* sB = sm + 2*BM*SST;

    const int tid  = threadIdx.x;
    const int bm   = blockIdx.y * BM;
    const int bn   = blockIdx.x * BN;
    const int warp = tid >> 5, lane = tid & 31;
    const int g = lane >> 2;
    const int q = lane & 3;
    const int wm = (warp >> 1) * 32;
    const int wn = (warp & 1) * 64;

    uint32_t sA_sh = (uint32_t)__cvta_generic_to_shared(sA);
    uint32_t sB_sh = (uint32_t)__cvta_generic_to_shared(sB);

    float acc[2][8][4] = {};
    const int NIT = Dd / BK;

    {
#pragma unroll
        for (int j = 0; j < 4; j++) {
            int cl = tid + 256*j;
            int row = cl >> 3, kc = (cl & 7) * 4;
            uint32_t so = (uint32_t)(row*SST + kc) * 4u;
            CP16(sA_sh + so, A + (size_t)(bm + row) * Dd + kc);
            CP16(sB_sh + so, W + (size_t)(bn + row) * Dd + kc);
        }
        asm volatile("cp.async.commit_group;");
    }

    for (int it = 0; it < NIT; it++) {
        if (it + 1 < NIT) {
            int k0 = (it + 1) * BK;
            uint32_t stg = (uint32_t)((it + 1) & 1) * BM * SST * 4u;
#pragma unroll
            for (int j = 0; j < 4; j++) {
                int cl = tid + 256*j;
                int row = cl >> 3, kc = (cl & 7) * 4;
                uint32_t so = stg + (uint32_t)(row*SST + kc) * 4u;
                CP16(sA_sh + so, A + (size_t)(bm + row) * Dd + k0 + kc);
                CP16(sB_sh + so, W + (size_t)(bn + row) * Dd + k0 + kc);
            }
            asm volatile("cp.async.commit_group;");
            asm volatile("cp.async.wait_group 1;");
        } else {
            asm volatile("cp.async.wait_group 0;");
        }
        __syncthreads();

        const float* cA = sA + (it & 1) * BM * SST;
        const float* cB = sB + (it & 1) * BM * SST;

#pragma unroll
        for (int kk = 0; kk < 4; kk++) {
            const int kb = kk * 8;
            uint32_t af[2][4], bf[8][2];
#pragma unroll
            for (int mi = 0; mi < 2; mi++) {
                int m = wm + mi*16 + g;
                af[mi][0] = __float_as_uint(cA[m      *SST + kb + q]);
                af[mi][1] = __float_as_uint(cA[(m + 8)*SST + kb + q]);
                af[mi][2] = __float_as_uint(cA[m      *SST + kb + q + 4]);
                af[mi][3] = __float_as_uint(cA[(m + 8)*SST + kb + q + 4]);
            }
#pragma unroll
            for (int ni = 0; ni < 8; ni++) {
                int n = wn + ni*8 + g;
                bf[ni][0] = __float_as_uint(cB[n*SST + kb + q]);
                bf[ni][1] = __float_as_uint(cB[n*SST + kb + q + 4]);
            }
#pragma unroll
            for (int mi = 0; mi < 2; mi++)
#pragma unroll
                for (int ni = 0; ni < 8; ni++) {
                    asm volatile(
                        "mma.sync.aligned.m16n8k8.row.col.f32.tf32.tf32.f32 "
                        "{%0,%1,%2,%3}, {%4,%5,%6,%7}, {%8,%9}, {%0,%1,%2,%3};"
                        : "+f"(acc[mi][ni][0]), "+f"(acc[mi][ni][1]),
                          "+f"(acc[mi][ni][2]), "+f"(acc[mi][ni][3])
                        : "r"(af[mi][0]), "r"(af[mi][1]), "r"(af[mi][2]), "r"(af[mi][3]),
                          "r"(bf[ni][0]), "r"(bf[ni][1]));
                }
        }
        __syncthreads();
    }

#pragma unroll
    for (int mi = 0; mi < 2; mi++) {
        int r0 = bm + wm + mi*16 + g;
#pragma unroll
        for (int ni = 0; ni < 8; ni++) {
            int cn = bn + wn + ni*8 + q*2;
            float b0 = 0.f, b1 = 0.f;
            if (bias) { b0 = bias[cn]; b1 = bias[cn+1]; }
            *(float2*)&C[(size_t)r0     *Dd + cn] = make_float2(acc[mi][ni][0]+b0, acc[mi][ni][1]+b1);
            *(float2*)&C[(size_t)(r0+8) *Dd + cn] = make_float2(acc[mi][ni][2]+b0, acc[mi][ni][3]+b1);
        }
    }
}

// ---------------- RoPE + bf16 hi/lo split --------------------------------------------
__global__ void rope_split_kernel(const float* __restrict__ Q, const float* __restrict__ K,
                                  const float* __restrict__ fc, const float* __restrict__ fs,
                                  __nv_bfloat16* __restrict__ Qh, __nv_bfloat16* __restrict__ Ql,
                                  __nv_bfloat16* __restrict__ Kh, __nv_bfloat16* __restrict__ Kl) {
    int idx = blockIdx.x * blockDim.x + threadIdx.x;   // Mm * 512 pairs
    int row  = idx >> 9;
    int col2 = idx & 511;
    int p = col2 & 31;
    int s = row & (Ss - 1);
    float c  = fc[s*32 + p];
    float sn = fs[s*32 + p];
    size_t base = (size_t)row * Dd + 2*col2;
    float2 qv = *(const float2*)&Q[base];
    float2 kv = *(const float2*)&K[base];
    float q0 = qv.x*c - qv.y*sn, q1 = qv.x*sn + qv.y*c;
    float k0 = kv.x*c - kv.y*sn, k1 = kv.x*sn + kv.y*c;
    __nv_bfloat16 qh0 = __float2bfloat16(q0), qh1 = __float2bfloat16(q1);
    __nv_bfloat16 kh0 = __float2bfloat16(k0), kh1 = __float2bfloat16(k1);
    __nv_bfloat16 ql0 = __float2bfloat16(q0 - __bfloat162float(qh0));
    __nv_bfloat16 ql1 = __float2bfloat16(q1 - __bfloat162float(qh1));
    __nv_bfloat16 kl0 = __float2bfloat16(k0 - __bfloat162float(kh0));
    __nv_bfloat16 kl1 = __float2bfloat16(k1 - __bfloat162float(kh1));
    *(__nv_bfloat162*)&Qh[base] = __nv_bfloat162(qh0, qh1);
    *(__nv_bfloat162*)&Ql[base] = __nv_bfloat162(ql0, ql1);
    *(__nv_bfloat162*)&Kh[base] = __nv_bfloat162(kh0, kh1);
    *(__nv_bfloat162*)&Kl[base] = __nv_bfloat162(kl0, kl1);
}

// ---------------- Tensor-core flash attention ----------------------------------------
// 128 q x 64 k tiles, 8 warps x (16q x 64k). QK^T: bf16 hi/lo split (3 MMAs),
// PV: tf32. P staged through warp-private smem slice.
#define AQ 128
#define AK 64
#define KST 72            // bf16 elements per row (Q/K planes)
#define VST 68            // fp32 stride for Vt and P
#define OFF_KH 0
#define OFF_KL (AK*KST*2)
#define OFF_VT (2*AK*KST*2)
#define OFF_PQ (OFF_VT + AK*VST*4)
#define ATTN_SMEM (OFF_PQ + AQ*KST*2*2)   // Q-plane staging (36864B) >= P (34816B)

#define MMA_BF16(d, a, b0, b1) \
    asm volatile("mma.sync.aligned.m16n8k16.row.col.f32.bf16.bf16.f32 " \
        "{%0,%1,%2,%3}, {%4,%5,%6,%7}, {%8,%9}, {%0,%1,%2,%3};" \
        : "+f"(d[0]), "+f"(d[1]), "+f"(d[2]), "+f"(d[3]) \
        : "r"(a[0]), "r"(a[1]), "r"(a[2]), "r"(a[3]), "r"(b0), "r"(b1))

#define MMA_TF32(d, a, b0, b1) \
    asm volatile("mma.sync.aligned.m16n8k8.row.col.f32.tf32.tf32.f32 " \
        "{%0,%1,%2,%3}, {%4,%5,%6,%7}, {%8,%9}, {%0,%1,%2,%3};" \
        : "+f"(d[0]), "+f"(d[1]), "+f"(d[2]), "+f"(d[3]) \
        : "r"(a[0]), "r"(a[1]), "r"(a[2]), "r"(a[3]), "r"(b0), "r"(b1))

__global__ __launch_bounds__(256) void attn_mma_kernel(
    const __nv_bfloat16* __restrict__ Qh, const __nv_bfloat16* __restrict__ Ql,
    const __nv_bfloat16* __restrict__ Kh, const __nv_bfloat16* __restrict__ Kl,
    const float* __restrict__ V, float* __restrict__ O)
{
    extern __shared__ char smc[];
    __nv_bfloat16* sKh = (__nv_bfloat16*)(smc + OFF_KH);
    __nv_bfloat16* sKl = (__nv_bfloat16*)(smc + OFF_KL);
    float* sVt = (float*)(smc + OFF_VT);
    float* sP  = (float*)(smc + OFF_PQ);
    __nv_bfloat16* sQ = (__nv_bfloat16*)(smc + OFF_PQ);

    const int tid = threadIdx.x;
    const int warp = tid >> 5, lane = tid & 31;
    const int g = lane >> 2, q = lane & 3;
    const int qt = 31 - blockIdx.x;          // heavy tiles first
    const int bh = blockIdx.y;
    const int b = bh >> 4, h = bh & 15;
    const size_t headoff = (size_t)b * Ss * Dd + (size_t)h * HDh;
    const int w16 = warp * 16;

    // ---- stage Q hi/lo planes into smem, then pull fragments into registers ----
    {
        const int r = tid >> 1, half = tid & 1;
        const size_t goff = headoff + (size_t)(qt*AQ + r) * Dd + half*32;
        const uint4* gqh = (const uint4*)(Qh + goff);
        const uint4* gql = (const uint4*)(Ql + goff);
        uint4* s0 = (uint4*)(sQ + r*KST + half*32);
        uint4* s1 = (uint4*)(sQ + AQ*KST + r*KST + half*32);
#pragma unroll
        for (int i = 0; i < 4; i++) { s0[i] = gqh[i]; s1[i] = gql[i]; }
    }
    __syncthreads();

    uint32_t aQh[4][4], aQl[4][4];
    {
        const uint32_t* sQw = (const uint32_t*)sQ;       // 2 bf16/word, row stride 36 words
        const int lo = AQ * (KST/2);                      // lo-plane offset in words
#pragma unroll
        for (int s = 0; s < 4; s++) {
            int c0 = s*8 + q;
            aQh[s][0] = sQw[(w16+g  )*36 + c0];
            aQh[s][1] = sQw[(w16+8+g)*36 + c0];
            aQh[s][2] = sQw[(w16+g  )*36 + c0 + 4];
            aQh[s][3] = sQw[(w16+8+g)*36 + c0 + 4];
            aQl[s][0] = sQw[lo + (w16+g  )*36 + c0];
            aQl[s][1] = sQw[lo + (w16+8+g)*36 + c0];
            aQl[s][2] = sQw[lo + (w16+g  )*36 + c0 + 4];
            aQl[s][3] = sQw[lo + (w16+8+g)*36 + c0 + 4];
        }
    }

    float accO[8][4] = {};
    float m0 = -1e30f, m1 = -1e30f, l0 = 0.f, l1 = 0.f;

    const int nkt = 2*qt + 2;
    for (int kt = 0; kt < nkt; kt++) {
        __syncthreads();    // P/V consumers done; (first iter: Q frag reads done)
        // load K hi/lo planes
        {
            int p = tid >> 7;
            int r = (tid & 127) >> 1;
            int half = tid & 1;
            const __nv_bfloat16* gsrc = (p ? Kl : Kh) + headoff + (size_t)(kt*AK + r)*Dd + half*32;
            __nv_bfloat16* dst = (p ? sKl : sKh) + r*KST + half*32;
#pragma unroll
            for (int i = 0; i < 4; i++) ((uint4*)dst)[i] = ((const uint4*)gsrc)[i];
        }
        // load V transposed (tf32-rounded)
        {
            int r = tid & 63;
            int c0 = (tid >> 6) * 16;
            const float* src = V + headoff + (size_t)(kt*AK + r)*Dd + c0;
#pragma unroll
            for (int i = 0; i < 4; i++) {
                float4 v = ((const float4*)src)[i];
                int d = c0 + i*4;
                sVt[(d+0)*VST + r] = tf32r(v.x);
                sVt[(d+1)*VST + r] = tf32r(v.y);
                sVt[(d+2)*VST + r] = tf32r(v.z);
                sVt[(d+3)*VST + r] = tf32r(v.w);
            }
        }
        __syncthreads();

        // S = (Qh+Ql) @ (Kh+Kl)^T  (drop ql*kl)
        float S[8][4] = {};
        const uint32_t* sKhw = (const uint32_t*)sKh;
        const uint32_t* sKlw = (const uint32_t*)sKl;
#pragma unroll
        for (int s = 0; s < 4; s++) {
            int c0 = s*8 + q;
#pragma unroll
            for (int ni = 0; ni < 8; ni++) {
                int n = ni*8 + g;
                uint32_t bh0 = sKhw[n*36 + c0], bh1 = sKhw[n*36 + c0 + 4];
                uint32_t bl0 = sKlw[n*36 + c0], bl1 = sKlw[n*36 + c0 + 4];
                MMA_BF16(S[ni], aQh[s], bh0, bh1);
                MMA_BF16(S[ni], aQh[s], bl0, bl1);
                MMA_BF16(S[ni], aQl[s], bh0, bh1);
            }
        }

        // scale + causal mask
        const bool need_mask = (kt >= 2*qt);
        const int r0g = qt*AQ + w16 + g, r1g = r0g + 8;
#pragma unroll
        for (int ni = 0; ni < 8; ni++) {
            S[ni][0] *= 0.125f; S[ni][1] *= 0.125f;
            S[ni][2] *= 0.125f; S[ni][3] *= 0.125f;
            if (need_mask) {
                int c = kt*AK + ni*8 + 2*q;
                if (c     > r0g) S[ni][0] = -1e30f;
                if (c + 1 > r0g) S[ni][1] = -1e30f;
                if (c     > r1g) S[ni][2] = -1e30f;
                if (c + 1 > r1g) S[ni][3] = -1e30f;
            }
        }

        // online softmax (rows g and g+8; reduce across quad lanes)
        float mx0 = -1e30f, mx1 = -1e30f;
#pragma unroll
        for (int ni = 0; ni < 8; ni++) {
            mx0 = fmaxf(mx0, fmaxf(S[ni][0], S[ni][1]));
            mx1 = fmaxf(mx1, fmaxf(S[ni][2], S[ni][3]));
        }
        mx0 = fmaxf(mx0, __shfl_xor_sync(0xffffffffu, mx0, 1));
        mx0 = fmaxf(mx0, __shfl_xor_sync(0xffffffffu, mx0, 2));
        mx1 = fmaxf(mx1, __shfl_xor_sync(0xffffffffu, mx1, 1));
        mx1 = fmaxf(mx1, __shfl_xor_sync(0xffffffffu, mx1, 2));
        float mn0 = fmaxf(m0, mx0), mn1 = fmaxf(m1, mx1);
        float cr0 = __expf(m0 - mn0), cr1 = __expf(m1 - mn1);
        m0 = mn0; m1 = mn1;
        float s0 = 0.f, s1 = 0.f;
#pragma unroll
        for (int ni = 0; ni < 8; ni++) {
            S[ni][0] = __expf(S[ni][0] - mn0);
            S[ni][1] = __expf(S[ni][1] - mn0);
            S[ni][2] = __expf(S[ni][2] - mn1);
            S[ni][3] = __expf(S[ni][3] - mn1);
            s0 += S[ni][0] + S[ni][1];
            s1 += S[ni][2] + S[ni][3];
        }
        s0 += __shfl_xor_sync(0xffffffffu, s0, 1);
        s0 += __shfl_xor_sync(0xffffffffu, s0, 2);
        s1 += __shfl_xor_sync(0xffffffffu, s1, 1);
        s1 += __shfl_xor_sync(0xffffffffu, s1, 2);
        l0 = l0*cr0 + s0;
        l1 = l1*cr1 + s1;
#pragma unroll
        for (int ni = 0; ni < 8; ni++) {
            accO[ni][0] *= cr0; accO[ni][1] *= cr0;
            accO[ni][2] *= cr1; accO[ni][3] *= cr1;
        }

        // stage P (tf32) into warp-private smem slice
#pragma unroll
        for (int ni = 0; ni < 8; ni++) {
            int c = ni*8 + 2*q;
            *(float2*)&sP[(w16+g  )*VST + c] = make_float2(tf32r(S[ni][0]), tf32r(S[ni][1]));
            *(float2*)&sP[(w16+8+g)*VST + c] = make_float2(tf32r(S[ni][2]), tf32r(S[ni][3]));
        }
        __syncwarp();

        // O += P @ V   (tf32)
#pragma unroll
        for (int kb = 0; kb < 8; kb++) {
            int k0 = kb*8;
            uint32_t aP[4];
            aP[0] = __float_as_uint(sP[(w16+g  )*VST + k0 + q]);
            aP[1] = __float_as_uint(sP[(w16+8+g)*VST + k0 + q]);
            aP[2] = __float_as_uint(sP[(w16+g  )*VST + k0 + q + 4]);
            aP[3] = __float_as_uint(sP[(w16+8+g)*VST + k0 + q + 4]);
#pragma unroll
            for (int ni = 0; ni < 8; ni++) {
                int d = ni*8 + g;
                uint32_t b0 = __float_as_uint(sVt[d*VST + k0 + q]);
                uint32_t b1 = __float_as_uint(sVt[d*VST + k0 + q + 4]);
                MMA_TF32(accO[ni], aP, b0, b1);
            }
        }
    }

    // epilogue: normalize, tf32-round (feeds tf32 O-projection), store
    float inv0 = 1.f / l0, inv1 = 1.f / l1;
    size_t base0 = headoff + (size_t)(qt*AQ + w16 + g) * Dd;
    size_t base1 = base0 + (size_t)8 * Dd;
#pragma unroll
    for (int ni = 0; ni < 8; ni++) {
        int c = ni*8 + 2*q;
        *(float2*)&O[base0 + c] = make_float2(tf32r(accO[ni][0]*inv0), tf32r(accO[ni][1]*inv0));
        *(float2*)&O[base1 + c] = make_float2(tf32r(accO[ni][2]*inv1), tf32r(accO[ni][3]*inv1));
    }
}

// ---------------- launch -------------------------------------------------------------
extern "C" void kernel_launch(void* const* d_in, const int* in_sizes, int n_in,
                              void* d_out, int out_size) {
    const float* x   = (const float*)d_in[0];
    const float* fc  = (const float*)d_in[1];
    const float* fs  = (const float*)d_in[2];
    const float* wq  = (const float*)d_in[4];
    const float* wqb = (const float*)d_in[5];
    const float* wk  = (const float*)d_in[6];
    const float* wv  = (const float*)d_in[7];
    const float* wo  = (const float*)d_in[8];
    const float* wob = (const float*)d_in[9];
    const float* lq1 = (const float*)d_in[10];
    const float* lq2 = (const float*)d_in[11];
    const float* lk1 = (const float*)d_in[12];
    const float* lk2 = (const float*)d_in[13];
    const float* lv1 = (const float*)d_in[14];
    const float* lv2 = (const float*)d_in[15];
    const float* lo1 = (const float*)d_in[16];
    const float* lo2 = (const float*)d_in[17];

    float *Wq, *Wk, *Wv, *Wo, *Xr, *Qp, *Kp, *Vp, *AO;
    __nv_bfloat16 *Qhp, *Qlp, *Khp, *Klp;
    cudaGetSymbolAddress((void**)&Wq, g_Wq);
    cudaGetSymbolAddress((void**)&Wk, g_Wk);
    cudaGetSymbolAddress((void**)&Wv, g_Wv);
    cudaGetSymbolAddress((void**)&Wo, g_Wo);
    cudaGetSymbolAddress((void**)&Xr, g_X);
    cudaGetSymbolAddress((void**)&Qp, g_Q);
    cudaGetSymbolAddress((void**)&Kp, g_K);
    cudaGetSymbolAddress((void**)&Vp, g_V);
    cudaGetSymbolAddress((void**)&AO, g_AO);
    cudaGetSymbolAddress((void**)&Qhp, g_Qh);
    cudaGetSymbolAddress((void**)&Qlp, g_Ql);
    cudaGetSymbolAddress((void**)&Khp, g_Kh);
    cudaGetSymbolAddress((void**)&Klp, g_Kl);

    cudaFuncSetAttribute(mma_gemm_kernel, cudaFuncAttributeMaxDynamicSharedMemorySize, GEMM_SMEM);
    cudaFuncSetAttribute(attn_mma_kernel, cudaFuncAttributeMaxDynamicSharedMemorySize, ATTN_SMEM);

    // 1. Fold LoRA into effective weights (tf32), round x
    build_weff_kernel<<<(Dd*Dd)/256, 256>>>(wq, lq1, lq2, Wq);
    build_weff_kernel<<<(Dd*Dd)/256, 256>>>(wk, lk1, lk2, Wk);
    build_weff_kernel<<<(Dd*Dd)/256, 256>>>(wv, lv1, lv2, Wv);
    build_weff_kernel<<<(Dd*Dd)/256, 256>>>(wo, lo1, lo2, Wo);
    round_x_kernel<<<(Mm*Dd/4)/256, 256>>>((const float4*)x, (float4*)Xr);

    // 2. Q/K/V projections (tf32 tensor cores)
    dim3 gg(Dd/BN, Mm/BM);
    mma_gemm_kernel<<<gg, 256, GEMM_SMEM>>>(Xr, Wq, wqb,    Qp);
    mma_gemm_kernel<<<gg, 256, GEMM_SMEM>>>(Xr, Wk, nullptr, Kp);
    mma_gemm_kernel<<<gg, 256, GEMM_SMEM>>>(Xr, Wv, nullptr, Vp);

    // 3. RoPE + bf16 hi/lo split of Q and K
    rope_split_kernel<<<(Mm*(Dd/2))/256, 256>>>(Qp, Kp, fc, fs, Qhp, Qlp, Khp, Klp);

    // 4. Tensor-core causal flash attention
    dim3 ga(Ss/AQ, Bb*Hh);
    attn_mma_kernel<<<ga, 256, ATTN_SMEM>>>(Qhp, Qlp, Khp, Klp, Vp, AO);

    // 5. Output projection into d_out
    mma_gemm_kernel<<<gg, 256, GEMM_SMEM>>>(AO, Wo, wob, (float*)d_out);
}

// round 4
// speedup vs baseline: 2.6512x; 1.0294x over previous
#include <cuda_runtime.h>
#include <cuda_bf16.h>
#include <math.h>
#include <stdint.h>

// Problem constants
#define Bb 2
#define Ss 4096
#define Dd 1024
#define Hh 16
#define HDh 64
#define Rr 16
#define Mm (Bb*Ss)            // 8192 rows

// ---------------- device scratch ----------------------------------------------------
__device__ float g_Wq[Dd*Dd];
__device__ float g_Wk[Dd*Dd];
__device__ float g_Wv[Dd*Dd];
__device__ float g_Wo[Dd*Dd];
__device__ float g_X [(size_t)Mm*Dd];
__device__ float g_Vt[(size_t)Mm*Dd];          // [b*16+h][64][4096] transposed V (tf32)
__device__ float g_AO[(size_t)Mm*Dd];
__device__ __nv_bfloat16 g_Qh[(size_t)Mm*Dd];
__device__ __nv_bfloat16 g_Ql[(size_t)Mm*Dd];
__device__ __nv_bfloat16 g_Kh[(size_t)Mm*Dd];
__device__ __nv_bfloat16 g_Kl[(size_t)Mm*Dd];

__device__ __forceinline__ float tf32r(float x) {
    float y;
    asm("cvt.rna.tf32.f32 %0, %1;" : "=f"(y) : "f"(x));
    return y;
}

// ---------------- W_eff = tf32( W + l2 @ l1 ), all 4 weights in one launch ----------
struct WeffArgs {
    const float* w[4]; const float* l1[4]; const float* l2[4]; float* out[4];
};
__global__ void build_weff4_kernel(WeffArgs a) {
    int wi  = blockIdx.x >> 12;                        // 4096 blocks per weight
    int idx = ((blockIdx.x & 4095) << 8) + threadIdx.x;
    int n = idx >> 10, k = idx & 1023;
    const float* l1 = a.l1[wi];
    const float* l2 = a.l2[wi];
    float acc = a.w[wi][idx];
#pragma unroll
    for (int r = 0; r < Rr; r++) acc += l2[n*Rr + r] * l1[r*Dd + k];
    a.out[wi][idx] = tf32r(acc);
}

__global__ void round_x_kernel(const float4* __restrict__ in, float4* __restrict__ out) {
    int i = blockIdx.x * blockDim.x + threadIdx.x;
    float4 v = in[i];
    out[i] = make_float4(tf32r(v.x), tf32r(v.y), tf32r(v.z), tf32r(v.w));
}

// ---------------- TF32 tensor-core GEMM, 3-stage cp.async, fused epilogues ----------
// MODE 0: C = A@W^T + bias (fp32)
// MODE 1: Q = rope(A@W^T + bias) -> bf16 hi/lo planes
// MODE 2: K = rope(A@W^T)        -> bf16 hi/lo planes
// MODE 3: Vt[(b*16+h)*64+d][s] = tf32r(A@W^T)
#define BM 128
#define BN 128
#define BK 32
#define SST 36
#define GSTAGES 3
#define GEMM_SMEM (GSTAGES * 2 * BM * SST * 4)

#define CP16(dst, src) asm volatile("cp.async.cg.shared.global [%0], [%1], 16;" :: "r"(dst), "l"(src))

template<int MODE>
__global__ __launch_bounds__(256) void mma_gemm_kernel(
    const float* __restrict__ A, const float* __restrict__ W,
    const float* __restrict__ bias, float* __restrict__ C,
    __nv_bfloat16* __restrict__ Ph, __nv_bfloat16* __restrict__ Pl,
    const float* __restrict__ fc, const float* __restrict__ fs)
{
    extern __shared__ float sm[];
    const int tid  = threadIdx.x;
    const int bm   = blockIdx.y * BM;
    const int bn   = blockIdx.x * BN;
    const int warp = tid >> 5, lane = tid & 31;
    const int g = lane >> 2;
    const int q = lane & 3;
    const int wm = (warp >> 1) * 32;
    const int wn = (warp & 1) * 64;

    uint32_t sm_sh = (uint32_t)__cvta_generic_to_shared(sm);
    float acc[2][8][4] = {};
    const int NIT = Dd / BK;   // 32

#define GLOAD_STAGE(ITS) do {                                              \
        int _k0 = (ITS) * BK;                                              \
        uint32_t _stg = (uint32_t)((ITS) % GSTAGES) * (2*BM*SST*4);        \
        _Pragma("unroll")                                                  \
        for (int _j = 0; _j < 4; _j++) {                                   \
            int _cl = tid + 256*_j;                                        \
            int _row = _cl >> 3, _kc = (_cl & 7) * 4;                      \
            uint32_t _so = _stg + (uint32_t)(_row*SST + _kc) * 4u;         \
            CP16(sm_sh + _so, A + (size_t)(bm + _row) * Dd + _k0 + _kc);   \
            CP16(sm_sh + BM*SST*4 + _so, W + (size_t)(bn + _row) * Dd + _k0 + _kc); \
        }                                                                  \
        asm volatile("cp.async.commit_group;");                            \
    } while (0)

    GLOAD_STAGE(0);
    GLOAD_STAGE(1);

    for (int it = 0; it < NIT; it++) {
        if (it + 2 < NIT) {
            GLOAD_STAGE(it + 2);
            asm volatile("cp.async.wait_group 2;");
        } else if (it + 1 < NIT) {
            asm volatile("cp.async.wait_group 1;");
        } else {
            asm volatile("cp.async.wait_group 0;");
        }
        __syncthreads();

        const float* cA = sm + (it % GSTAGES) * 2 * BM * SST;
        const float* cB = cA + BM * SST;

#pragma unroll
        for (int kk = 0; kk < 4; kk++) {
            const int kb = kk * 8;
            uint32_t af[2][4], bf[8][2];
#pragma unroll
            for (int mi = 0; mi < 2; mi++) {
                int m = wm + mi*16 + g;
                af[mi][0] = __float_as_uint(cA[m      *SST + kb + q]);
                af[mi][1] = __float_as_uint(cA[(m + 8)*SST + kb + q]);
                af[mi][2] = __float_as_uint(cA[m      *SST + kb + q + 4]);
                af[mi][3] = __float_as_uint(cA[(m + 8)*SST + kb + q + 4]);
            }
#pragma unroll
            for (int ni = 0; ni < 8; ni++) {
                int n = wn + ni*8 + g;
                bf[ni][0] = __float_as_uint(cB[n*SST + kb + q]);
                bf[ni][1] = __float_as_uint(cB[n*SST + kb + q + 4]);
            }
#pragma unroll
            for (int mi = 0; mi < 2; mi++)
#pragma unroll
                for (int ni = 0; ni < 8; ni++) {
                    asm volatile(
                        "mma.sync.aligned.m16n8k8.row.col.f32.tf32.tf32.f32 "
                        "{%0,%1,%2,%3}, {%4,%5,%6,%7}, {%8,%9}, {%0,%1,%2,%3};"
                        : "+f"(acc[mi][ni][0]), "+f"(acc[mi][ni][1]),
                          "+f"(acc[mi][ni][2]), "+f"(acc[mi][ni][3])
                        : "r"(af[mi][0]), "r"(af[mi][1]), "r"(af[mi][2]), "r"(af[mi][3]),
                          "r"(bf[ni][0]), "r"(bf[ni][1]));
                }
        }
        __syncthreads();
    }
#undef GLOAD_STAGE

    // ---------------- fused epilogues ----------------
    if (MODE == 0) {
#pragma unroll
        for (int mi = 0; mi < 2; mi++) {
            int r0 = bm + wm + mi*16 + g;
#pragma unroll
            for (int ni = 0; ni < 8; ni++) {
                int cn = bn + wn + ni*8 + q*2;
                float b0 = bias[cn], b1 = bias[cn+1];
                *(float2*)&C[(size_t)r0     *Dd + cn] = make_float2(acc[mi][ni][0]+b0, acc[mi][ni][1]+b1);
                *(float2*)&C[(size_t)(r0+8) *Dd + cn] = make_float2(acc[mi][ni][2]+b0, acc[mi][ni][3]+b1);
            }
        }
    } else if (MODE == 1 || MODE == 2) {
#pragma unroll
        for (int mi = 0; mi < 2; mi++) {
            int r0 = bm + wm + mi*16 + g;
            int s0 = r0 & (Ss-1), s1 = (r0+8) & (Ss-1);
#pragma unroll
            for (int ni = 0; ni < 8; ni++) {
                int cn = bn + wn + ni*8 + q*2;
                int p = (cn & 63) >> 1;
                float b0 = 0.f, b1 = 0.f;
                if (MODE == 1) { b0 = bias[cn]; b1 = bias[cn+1]; }
                float c0 = fc[s0*32+p], n0 = fs[s0*32+p];
                float c1 = fc[s1*32+p], n1 = fs[s1*32+p];
                float e0 = acc[mi][ni][0]+b0, o0 = acc[mi][ni][1]+b1;
                float e1 = acc[mi][ni][2]+b0, o1 = acc[mi][ni][3]+b1;
                float re0 = e0*c0 - o0*n0, im0 = e0*n0 + o0*c0;
                float re1 = e1*c1 - o1*n1, im1 = e1*n1 + o1*c1;
                __nv_bfloat16 hre0 = __float2bfloat16(re0);
                __nv_bfloat16 him0 = __float2bfloat16(im0);
                __nv_bfloat16 hre1 = __float2bfloat16(re1);
                __nv_bfloat16 him1 = __float2bfloat16(im1);
                __nv_bfloat16 lre0 = __float2bfloat16(re0 - __bfloat162float(hre0));
                __nv_bfloat16 lim0 = __float2bfloat16(im0 - __bfloat162float(him0));
                __nv_bfloat16 lre1 = __float2bfloat16(re1 - __bfloat162float(hre1));
                __nv_bfloat16 lim1 = __float2bfloat16(im1 - __bfloat162float(him1));
                *(__nv_bfloat162*)&Ph[(size_t)r0    *Dd + cn] = __nv_bfloat162(hre0, him0);
                *(__nv_bfloat162*)&Pl[(size_t)r0    *Dd + cn] = __nv_bfloat162(lre0, lim0);
                *(__nv_bfloat162*)&Ph[(size_t)(r0+8)*Dd + cn] = __nv_bfloat162(hre1, him1);
                *(__nv_bfloat162*)&Pl[(size_t)(r0+8)*Dd + cn] = __nv_bfloat162(lre1, lim1);
            }
        }
    } else {   // MODE 3: transposed tf32 V
#pragma unroll
        for (int mi = 0; mi < 2; mi++) {
            int r0 = bm + wm + mi*16 + g;
            int sl = r0 & (Ss-1);
            size_t bb = (size_t)(r0 >> 12);
#pragma unroll
            for (int ni = 0; ni < 8; ni++) {
                int cn = bn + wn + ni*8 + q*2;
                int hh = cn >> 6, dd = cn & 63;
                size_t vb = ((bb*Hh + hh)*HDh + dd) * (size_t)Ss;
                C[vb          + sl    ] = tf32r(acc[mi][ni][0]);
                C[vb + Ss     + sl    ] = tf32r(acc[mi][ni][1]);
                C[vb          + sl + 8] = tf32r(acc[mi][ni][2]);
                C[vb + Ss     + sl + 8] = tf32r(acc[mi][ni][3]);
            }
        }
    }
}

// ---------------- Tensor-core flash attention, cp.async pipelined --------------------
// 128 q x 64 k tiles, 8 warps x (16q x 64k). QK^T: bf16 hi/lo (3 MMAs), PV: tf32.
// K hi/lo + transposed V double-buffered via cp.async.
#define AQ 128
#define AK 64
#define KST 72            // bf16 stride for K planes / Q staging
#define VST 68            // fp32 stride for Vt and P
#define KPL_BYTES (AK*KST*2)                  // 9216 per plane
#define STG_BYTES (2*KPL_BYTES + AK*VST*4)    // 35840 per stage
#define OFF_PQ (2*STG_BYTES)                  // 71680
#define ATTN_SMEM (OFF_PQ + AQ*KST*2*2)       // +36864 = 108544

#define MMA_BF16(d, a, b0, b1) \
    asm volatile("mma.sync.aligned.m16n8k16.row.col.f32.bf16.bf16.f32 " \
        "{%0,%1,%2,%3}, {%4,%5,%6,%7}, {%8,%9}, {%0,%1,%2,%3};" \
        : "+f"(d[0]), "+f"(d[1]), "+f"(d[2]), "+f"(d[3]) \
        : "r"(a[0]), "r"(a[1]), "r"(a[2]), "r"(a[3]), "r"(b0), "r"(b1))

#define MMA_TF32(d, a, b0, b1) \
    asm volatile("mma.sync.aligned.m16n8k8.row.col.f32.tf32.tf32.f32 " \
        "{%0,%1,%2,%3}, {%4,%5,%6,%7}, {%8,%9}, {%0,%1,%2,%3};" \
        : "+f"(d[0]), "+f"(d[1]), "+f"(d[2]), "+f"(d[3]) \
        : "r"(a[0]), "r"(a[1]), "r"(a[2]), "r"(a[3]), "r"(b0), "r"(b1))

__global__ __launch_bounds__(256) void attn_mma_kernel(
    const __nv_bfloat16* __restrict__ Qh, const __nv_bfloat16* __restrict__ Ql,
    const __nv_bfloat16* __restrict__ Kh, const __nv_bfloat16* __restrict__ Kl,
    const float* __restrict__ Vt, float* __restrict__ O)
{
    extern __shared__ char smc[];
    uint32_t sm_sh = (uint32_t)__cvta_generic_to_shared(smc);
    float* sP = (float*)(smc + OFF_PQ);
    __nv_bfloat16* sQ = (__nv_bfloat16*)(smc + OFF_PQ);

    const int tid = threadIdx.x;
    const int warp = tid >> 5, lane = tid & 31;
    const int g = lane >> 2, q = lane & 3;
    const int qt = 31 - blockIdx.x;          // heavy tiles first
    const int bh = blockIdx.y;
    const int b = bh >> 4, h = bh & 15;
    const size_t headoff = (size_t)b * Ss * Dd + (size_t)h * HDh;
    const size_t vhead = (size_t)bh * HDh * Ss;
    const int w16 = warp * 16;

    // ---- stage Q hi/lo planes into smem, pull fragments ----
    {
        const int r = tid >> 1, half = tid & 1;
        const size_t goff = headoff + (size_t)(qt*AQ + r) * Dd + half*32;
        const uint4* gqh = (const uint4*)(Qh + goff);
        const uint4* gql = (const uint4*)(Ql + goff);
        uint4* s0 = (uint4*)(sQ + r*KST + half*32);
        uint4* s1 = (uint4*)(sQ + AQ*KST + r*KST + half*32);
#pragma unroll
        for (int i = 0; i < 4; i++) { s0[i] = gqh[i]; s1[i] = gql[i]; }
    }
    __syncthreads();

    uint32_t aQh[4][4], aQl[4][4];
    {
        const uint32_t* sQw = (const uint32_t*)sQ;
        const int lo = AQ * (KST/2);
#pragma unroll
        for (int s = 0; s < 4; s++) {
            int c0 = s*8 + q;
            aQh[s][0] = sQw[(w16+g  )*36 + c0];
            aQh[s][1] = sQw[(w16+8+g)*36 + c0];
            aQh[s][2] = sQw[(w16+g  )*36 + c0 + 4];
            aQh[s][3] = sQw[(w16+8+g)*36 + c0 + 4];
            aQl[s][0] = sQw[lo + (w16+g  )*36 + c0];
            aQl[s][1] = sQw[lo + (w16+8+g)*36 + c0];
            aQl[s][2] = sQw[lo + (w16+g  )*36 + c0 + 4];
            aQl[s][3] = sQw[lo + (w16+8+g)*36 + c0 + 4];
        }
    }

#define APREFETCH(KT) do {                                                          \
        uint32_t _stg = sm_sh + (uint32_t)((KT) & 1) * STG_BYTES;                   \
        {   /* K hi/lo planes */                                                    \
            int _p = tid >> 7;                                                      \
            int _r = (tid & 127) >> 1;                                              \
            int _half = tid & 1;                                                    \
            const __nv_bfloat16* _gs = (_p ? Kl : Kh) + headoff                     \
                + (size_t)((KT)*AK + _r)*Dd + _half*32;                             \
            uint32_t _dst = _stg + (_p ? KPL_BYTES : 0)                             \
                + (uint32_t)(_r*KST + _half*32)*2u;                                 \
            _Pragma("unroll")                                                       \
            for (int _i = 0; _i < 4; _i++)                                          \
                CP16(_dst + _i*16, (const char*)_gs + _i*16);                       \
        }                                                                           \
        {   /* V rows (already transposed + tf32) */                                \
            int _d = tid & 63;                                                      \
            int _c0 = (tid >> 6) * 16;                                              \
            const float* _gs = Vt + vhead + (size_t)_d*Ss + (KT)*AK + _c0;          \
            uint32_t _dst = _stg + 2*KPL_BYTES + (uint32_t)(_d*VST + _c0)*4u;       \
            _Pragma("unroll")                                                       \
            for (int _i = 0; _i < 4; _i++)                                          \
                CP16(_dst + _i*16, _gs + _i*4);                                     \
        }                                                                           \
        asm volatile("cp.async.commit_group;");                                     \
    } while (0)

    float accO[8][4] = {};
    float m0 = -1e30f, m1 = -1e30f, l0 = 0.f, l1 = 0.f;
    const int nkt = 2*qt + 2;

    APREFETCH(0);

    for (int kt = 0; kt < nkt; kt++) {
        __syncthreads();        // prior compute done before its buffer is reloaded
        if (kt + 1 < nkt) {
            APREFETCH(kt + 1);
            asm volatile("cp.async.wait_group 1;");
        } else {
            asm volatile("cp.async.wait_group 0;");
        }
        __syncthreads();        // cp.async data visible to all warps

        const char* stg = smc + (kt & 1) * STG_BYTES;
        const uint32_t* sKhw = (const uint32_t*)stg;
        const uint32_t* sKlw = (const uint32_t*)(stg + KPL_BYTES);
        const float* sVt = (const float*)(stg + 2*KPL_BYTES);

        // S = (Qh+Ql) @ (Kh+Kl)^T  (drop ql*kl)
        float S[8][4] = {};
#pragma unroll
        for (int s = 0; s < 4; s++) {
            int c0 = s*8 + q;
#pragma unroll
            for (int ni = 0; ni < 8; ni++) {
                int n = ni*8 + g;
                uint32_t bh0 = sKhw[n*36 + c0], bh1 = sKhw[n*36 + c0 + 4];
                uint32_t bl0 = sKlw[n*36 + c0], bl1 = sKlw[n*36 + c0 + 4];
                MMA_BF16(S[ni], aQh[s], bh0, bh1);
                MMA_BF16(S[ni], aQh[s], bl0, bl1);
                MMA_BF16(S[ni], aQl[s], bh0, bh1);
            }
        }

        // scale + causal mask
        const bool need_mask = (kt >= 2*qt);
        const int r0g = qt*AQ + w16 + g, r1g = r0g + 8;
#pragma unroll
        for (int ni = 0; ni < 8; ni++) {
            S[ni][0] *= 0.125f; S[ni][1] *= 0.125f;
            S[ni][2] *= 0.125f; S[ni][3] *= 0.125f;
            if (need_mask) {
                int c = kt*AK + ni*8 + 2*q;
                if (c     > r0g) S[ni][0] = -1e30f;
                if (c + 1 > r0g) S[ni][1] = -1e30f;
                if (c     > r1g) S[ni][2] = -1e30f;
                if (c + 1 > r1g) S[ni][3] = -1e30f;
            }
        }

        // online softmax
        float mx0 = -1e30f, mx1 = -1e30f;
#pragma unroll
        for (int ni = 0; ni < 8; ni++) {
            mx0 = fmaxf(mx0, fmaxf(S[ni][0], S[ni][1]));
            mx1 = fmaxf(mx1, fmaxf(S[ni][2], S[ni][3]));
        }
        mx0 = fmaxf(mx0, __shfl_xor_sync(0xffffffffu, mx0, 1));
        mx0 = fmaxf(mx0, __shfl_xor_sync(0xffffffffu, mx0, 2));
        mx1 = fmaxf(mx1, __shfl_xor_sync(0xffffffffu, mx1, 1));
        mx1 = fmaxf(mx1, __shfl_xor_sync(0xffffffffu, mx1, 2));
        float mn0 = fmaxf(m0, mx0), mn1 = fmaxf(m1, mx1);
        float cr0 = __expf(m0 - mn0), cr1 = __expf(m1 - mn1);
        m0 = mn0; m1 = mn1;
        float s0 = 0.f, s1 = 0.f;
#pragma unroll
        for (int ni = 0; ni < 8; ni++) {
            S[ni][0] = __expf(S[ni][0] - mn0);
            S[ni][1] = __expf(S[ni][1] - mn0);
            S[ni][2] = __expf(S[ni][2] - mn1);
            S[ni][3] = __expf(S[ni][3] - mn1);
            s0 += S[ni][0] + S[ni][1];
            s1 += S[ni][2] + S[ni][3];
        }
        s0 += __shfl_xor_sync(0xffffffffu, s0, 1);
        s0 += __shfl_xor_sync(0xffffffffu, s0, 2);
        s1 += __shfl_xor_sync(0xffffffffu, s1, 1);
        s1 += __shfl_xor_sync(0xffffffffu, s1, 2);
        l0 = l0*cr0 + s0;
        l1 = l1*cr1 + s1;
#pragma unroll
        for (int ni = 0; ni < 8; ni++) {
            accO[ni][0] *= cr0; accO[ni][1] *= cr0;
            accO[ni][2] *= cr1; accO[ni][3] *= cr1;
        }

        // stage P (tf32) into warp-private smem slice
#pragma unroll
        for (int ni = 0; ni < 8; ni++) {
            int c = ni*8 + 2*q;
            *(float2*)&sP[(w16+g  )*VST + c] = make_float2(tf32r(S[ni][0]), tf32r(S[ni][1]));
            *(float2*)&sP[(w16+8+g)*VST + c] = make_float2(tf32r(S[ni][2]), tf32r(S[ni][3]));
        }
        __syncwarp();

        // O += P @ V  (tf32)
#pragma unroll
        for (int kb = 0; kb < 8; kb++) {
            int k0 = kb*8;
            uint32_t aP[4];
            aP[0] = __float_as_uint(sP[(w16+g  )*VST + k0 + q]);
            aP[1] = __float_as_uint(sP[(w16+8+g)*VST + k0 + q]);
            aP[2] = __float_as_uint(sP[(w16+g  )*VST + k0 + q + 4]);
            aP[3] = __float_as_uint(sP[(w16+8+g)*VST + k0 + q + 4]);
#pragma unroll
            for (int ni = 0; ni < 8; ni++) {
                int d = ni*8 + g;
                uint32_t b0 = __float_as_uint(sVt[d*VST + k0 + q]);
                uint32_t b1 = __float_as_uint(sVt[d*VST + k0 + q + 4]);
                MMA_TF32(accO[ni], aP, b0, b1);
            }
        }
    }
#undef APREFETCH

    // epilogue: normalize, tf32-round (feeds tf32 O-projection), store
    float inv0 = 1.f / l0, inv1 = 1.f / l1;
    size_t base0 = headoff + (size_t)(qt*AQ + w16 + g) * Dd;
    size_t base1 = base0 + (size_t)8 * Dd;
#pragma unroll
    for (int ni = 0; ni < 8; ni++) {
        int c = ni*8 + 2*q;
        *(float2*)&O[base0 + c] = make_float2(tf32r(accO[ni][0]*inv0), tf32r(accO[ni][1]*inv0));
        *(float2*)&O[base1 + c] = make_float2(tf32r(accO[ni][2]*inv1), tf32r(accO[ni][3]*inv1));
    }
}

// ---------------- launch -------------------------------------------------------------
extern "C" void kernel_launch(void* const* d_in, const int* in_sizes, int n_in,
                              void* d_out, int out_size) {
    const float* x   = (const float*)d_in[0];
    const float* fc  = (const float*)d_in[1];
    const float* fs  = (const float*)d_in[2];
    const float* wq  = (const float*)d_in[4];
    const float* wqb = (const float*)d_in[5];
    const float* wk  = (const float*)d_in[6];
    const float* wv  = (const float*)d_in[7];
    const float* wo  = (const float*)d_in[8];
    const float* wob = (const float*)d_in[9];

    float *Wq, *Wk, *Wv, *Wo, *Xr, *Vtp, *AO;
    __nv_bfloat16 *Qhp, *Qlp, *Khp, *Klp;
    cudaGetSymbolAddress((void**)&Wq, g_Wq);
    cudaGetSymbolAddress((void**)&Wk, g_Wk);
    cudaGetSymbolAddress((void**)&Wv, g_Wv);
    cudaGetSymbolAddress((void**)&Wo, g_Wo);
    cudaGetSymbolAddress((void**)&Xr, g_X);
    cudaGetSymbolAddress((void**)&Vtp, g_Vt);
    cudaGetSymbolAddress((void**)&AO, g_AO);
    cudaGetSymbolAddress((void**)&Qhp, g_Qh);
    cudaGetSymbolAddress((void**)&Qlp, g_Ql);
    cudaGetSymbolAddress((void**)&Khp, g_Kh);
    cudaGetSymbolAddress((void**)&Klp, g_Kl);

    cudaFuncSetAttribute(mma_gemm_kernel<0>, cudaFuncAttributeMaxDynamicSharedMemorySize, GEMM_SMEM);
    cudaFuncSetAttribute(mma_gemm_kernel<1>, cudaFuncAttributeMaxDynamicSharedMemorySize, GEMM_SMEM);
    cudaFuncSetAttribute(mma_gemm_kernel<2>, cudaFuncAttributeMaxDynamicSharedMemorySize, GEMM_SMEM);
    cudaFuncSetAttribute(mma_gemm_kernel<3>, cudaFuncAttributeMaxDynamicSharedMemorySize, GEMM_SMEM);
    cudaFuncSetAttribute(attn_mma_kernel, cudaFuncAttributeMaxDynamicSharedMemorySize, ATTN_SMEM);

    // 1. Fold LoRA into the 4 effective weights (one launch); round x to tf32
    WeffArgs wa;
    wa.w[0]=wq; wa.l1[0]=(const float*)d_in[10]; wa.l2[0]=(const float*)d_in[11]; wa.out[0]=Wq;
    wa.w[1]=wk; wa.l1[1]=(const float*)d_in[12]; wa.l2[1]=(const float*)d_in[13]; wa.out[1]=Wk;
    wa.w[2]=wv; wa.l1[2]=(const float*)d_in[14]; wa.l2[2]=(const float*)d_in[15]; wa.out[2]=Wv;
    wa.w[3]=wo; wa.l1[3]=(const float*)d_in[16]; wa.l2[3]=(const float*)d_in[17]; wa.out[3]=Wo;
    build_weff4_kernel<<<4*4096, 256>>>(wa);
    round_x_kernel<<<(Mm*Dd/4)/256, 256>>>((const float4*)x, (float4*)Xr);

    // 2. Q/K/V projections with fused RoPE/split (Q,K) and transpose+round (V)
    dim3 gg(Dd/BN, Mm/BM);
    mma_gemm_kernel<1><<<gg, 256, GEMM_SMEM>>>(Xr, Wq, wqb, nullptr, Qhp, Qlp, fc, fs);
    mma_gemm_kernel<2><<<gg, 256, GEMM_SMEM>>>(Xr, Wk, nullptr, nullptr, Khp, Klp, fc, fs);
    mma_gemm_kernel<3><<<gg, 256, GEMM_SMEM>>>(Xr, Wv, nullptr, Vtp, nullptr, nullptr, nullptr, nullptr);

    // 3. Tensor-core causal flash attention (pipelined)
    dim3 ga(Ss/AQ, Bb*Hh);
    attn_mma_kernel<<<ga, 256, ATTN_SMEM>>>(Qhp, Qlp, Khp, Klp, Vtp, AO);

    // 4. Output projection into d_out
    mma_gemm_kernel<0><<<gg, 256, GEMM_SMEM>>>(AO, Wo, wob, (float*)d_out, nullptr, nullptr, nullptr, nullptr);
}

// round 6
// speedup vs baseline: 4.3491x; 1.6404x over previous
#include <cuda_runtime.h>
#include <cuda_fp16.h>
#include <math.h>
#include <stdint.h>

// Problem constants
#define Bb 2
#define Ss 4096
#define Dd 1024
#define Hh 16
#define HDh 64
#define Rr 16
#define Mm (Bb*Ss)            // 8192 rows

// ---------------- device scratch (all fp16 now) --------------------------------------
__device__ __half g_Wq[Dd*Dd];
__device__ __half g_Wk[Dd*Dd];
__device__ __half g_Wv[Dd*Dd];
__device__ __half g_Wo[Dd*Dd];
__device__ __half g_X [(size_t)Mm*Dd];
__device__ __half g_Qh[(size_t)Mm*Dd];
__device__ __half g_Kh[(size_t)Mm*Dd];
__device__ __half g_Kl[(size_t)Mm*Dd];
__device__ __half g_Vt[(size_t)Mm*Dd];        // [b*16+h][64][4096] transposed V (fp16)
__device__ __half g_AO[(size_t)Mm*Dd];

#define CP16(dst, src) asm volatile("cp.async.cg.shared.global [%0], [%1], 16;" :: "r"(dst), "l"(src))

__device__ __forceinline__ uint32_t h2u(__half2 h) { return *(uint32_t*)&h; }

#define MMA_F16(d, a, b0, b1) \
    asm volatile("mma.sync.aligned.m16n8k16.row.col.f32.f16.f16.f32 " \
        "{%0,%1,%2,%3}, {%4,%5,%6,%7}, {%8,%9}, {%0,%1,%2,%3};" \
        : "+f"(d[0]), "+f"(d[1]), "+f"(d[2]), "+f"(d[3]) \
        : "r"(a[0]), "r"(a[1]), "r"(a[2]), "r"(a[3]), "r"(b0), "r"(b1))

// ---------------- W_eff = fp16( W + l2 @ l1 ), all 4 weights in one launch ----------
struct WeffArgs {
    const float* w[4]; const float* l1[4]; const float* l2[4]; __half* out[4];
};
__global__ void build_weff4_kernel(WeffArgs a) {
    int wi  = blockIdx.x >> 12;
    int idx = ((blockIdx.x & 4095) << 8) + threadIdx.x;
    int n = idx >> 10, k = idx & 1023;
    const float* l1 = a.l1[wi];
    const float* l2 = a.l2[wi];
    float acc = a.w[wi][idx];
#pragma unroll
    for (int r = 0; r < Rr; r++) acc += l2[n*Rr + r] * l1[r*Dd + k];
    a.out[wi][idx] = __float2half(acc);
}

__global__ void round_x_kernel(const float4* __restrict__ in, uint2* __restrict__ out) {
    int i = blockIdx.x * blockDim.x + threadIdx.x;
    float4 v = in[i];
    out[i] = make_uint2(h2u(__floats2half2_rn(v.x, v.y)), h2u(__floats2half2_rn(v.z, v.w)));
}

// ---------------- FP16 tensor-core GEMM: C[M,1024] = A @ W^T, fused epilogues --------
// 128x128 block tile, BK=64 halves (128B rows), 3-stage cp.async, 256 threads
// (8 warps 4x2, warp tile 32x64). m16n8k16 fp16, fp32 accum. Stride 144B rows.
// MODE 0: C = D + bias (fp32)
// MODE 1: Qh = fp16(rope(D + bias))            (hi plane only)
// MODE 2: Kh/Kl = fp16 hi/lo of rope(D)
// MODE 3: Vt[(b*16+h)*64+d][s] = fp16(D)       (transposed V)
#define BM 128
#define BN 128
#define HBK 64
#define ROWB 144                         // bytes per smem row (64 halves + 8 pad)
#define HSTG (2*BM*ROWB)                 // 36864 per stage (A+W)
#define GSTAGES 3
#define GEMM_SMEM (GSTAGES*HSTG)         // 110592
#define NCH (Dd/HBK)                     // 16

template<int MODE>
__global__ __launch_bounds__(256) void hgemm_kernel(
    const __half* __restrict__ A, const __half* __restrict__ W,
    const float* __restrict__ bias, float* __restrict__ C,
    __half* __restrict__ Ph, __half* __restrict__ Pl, __half* __restrict__ Vt,
    const float* __restrict__ fc, const float* __restrict__ fs)
{
    extern __shared__ char smc[];
    uint32_t sm_sh;
    asm("{ .reg .u64 t; cvta.to.shared.u64 t, %1; cvt.u32.u64 %0, t; }" : "=r"(sm_sh) : "l"(smc));

    const int tid  = threadIdx.x;
    const int bm   = blockIdx.y * BM;
    const int bn   = blockIdx.x * BN;
    const int warp = tid >> 5, lane = tid & 31;
    const int g = lane >> 2;
    const int q = lane & 3;
    const int wm = (warp >> 1) * 32;
    const int wn = (warp & 1) * 64;

    float acc[2][8][4] = {};

#define HLOAD(CH) do {                                                      \
        uint32_t _stg = sm_sh + (uint32_t)((CH) % GSTAGES) * HSTG;          \
        _Pragma("unroll")                                                   \
        for (int _j = 0; _j < 4; _j++) {                                    \
            int _cl = tid + 256*_j;                                         \
            int _row = _cl >> 3, _seg = _cl & 7;                            \
            uint32_t _off = (uint32_t)(_row*ROWB + _seg*16);                \
            CP16(_stg + _off,            A + (size_t)(bm + _row)*Dd + (CH)*HBK + _seg*8); \
            CP16(_stg + BM*ROWB + _off,  W + (size_t)(bn + _row)*Dd + (CH)*HBK + _seg*8); \
        }                                                                   \
        asm volatile("cp.async.commit_group;");                             \
    } while (0)

    HLOAD(0);
    HLOAD(1);

    for (int it = 0; it < NCH; it++) {
        if (it + 2 < NCH) {
            HLOAD(it + 2);
            asm volatile("cp.async.wait_group 2;");
        } else if (it + 1 < NCH) {
            asm volatile("cp.async.wait_group 1;");
        } else {
            asm volatile("cp.async.wait_group 0;");
        }
        __syncthreads();

        const uint32_t* cA = (const uint32_t*)(smc + (it % GSTAGES)*HSTG);
        const uint32_t* cB = cA + BM*(ROWB/4);

#pragma unroll
        for (int kk = 0; kk < 4; kk++) {          // 4 x k16
            const int kb = kk * 8;
            uint32_t af[2][4], bf[8][2];
#pragma unroll
            for (int mi = 0; mi < 2; mi++) {
                int m = wm + mi*16 + g;
                af[mi][0] = cA[m      *36 + kb + q];
                af[mi][1] = cA[(m + 8)*36 + kb + q];
                af[mi][2] = cA[m      *36 + kb + q + 4];
                af[mi][3] = cA[(m + 8)*36 + kb + q + 4];
            }
#pragma unroll
            for (int ni = 0; ni < 8; ni++) {
                int n = wn + ni*8 + g;
                bf[ni][0] = cB[n*36 + kb + q];
                bf[ni][1] = cB[n*36 + kb + q + 4];
            }
#pragma unroll
            for (int mi = 0; mi < 2; mi++)
#pragma unroll
                for (int ni = 0; ni < 8; ni++)
                    MMA_F16(acc[mi][ni], af[mi], bf[ni][0], bf[ni][1]);
        }
        __syncthreads();
    }
#undef HLOAD

    // ---------------- fused epilogues ----------------
    if (MODE == 0) {
#pragma unroll
        for (int mi = 0; mi < 2; mi++) {
            int r0 = bm + wm + mi*16 + g;
#pragma unroll
            for (int ni = 0; ni < 8; ni++) {
                int cn = bn + wn + ni*8 + q*2;
                float b0 = bias[cn], b1 = bias[cn+1];
                *(float2*)&C[(size_t)r0     *Dd + cn] = make_float2(acc[mi][ni][0]+b0, acc[mi][ni][1]+b1);
                *(float2*)&C[(size_t)(r0+8) *Dd + cn] = make_float2(acc[mi][ni][2]+b0, acc[mi][ni][3]+b1);
            }
        }
    } else if (MODE == 1 || MODE == 2) {
#pragma unroll
        for (int mi = 0; mi < 2; mi++) {
            int r0 = bm + wm + mi*16 + g;
            int s0 = r0 & (Ss-1), s1 = (r0+8) & (Ss-1);
#pragma unroll
            for (int ni = 0; ni < 8; ni++) {
                int cn = bn + wn + ni*8 + q*2;
                int p = (cn & 63) >> 1;
                float b0 = 0.f, b1 = 0.f;
                if (MODE == 1) { b0 = bias[cn]; b1 = bias[cn+1]; }
                float c0 = fc[s0*32+p], n0 = fs[s0*32+p];
                float c1 = fc[s1*32+p], n1 = fs[s1*32+p];
                float e0 = acc[mi][ni][0]+b0, o0 = acc[mi][ni][1]+b1;
                float e1 = acc[mi][ni][2]+b0, o1 = acc[mi][ni][3]+b1;
                float re0 = e0*c0 - o0*n0, im0 = e0*n0 + o0*c0;
                float re1 = e1*c1 - o1*n1, im1 = e1*n1 + o1*c1;
                __half2 h0 = __floats2half2_rn(re0, im0);
                __half2 h1 = __floats2half2_rn(re1, im1);
                *(__half2*)&Ph[(size_t)r0    *Dd + cn] = h0;
                *(__half2*)&Ph[(size_t)(r0+8)*Dd + cn] = h1;
                if (MODE == 2) {
                    __half2 l0 = __floats2half2_rn(re0 - __half2float(__low2half(h0)),
                                                   im0 - __half2float(__high2half(h0)));
                    __half2 l1 = __floats2half2_rn(re1 - __half2float(__low2half(h1)),
                                                   im1 - __half2float(__high2half(h1)));
                    *(__half2*)&Pl[(size_t)r0    *Dd + cn] = l0;
                    *(__half2*)&Pl[(size_t)(r0+8)*Dd + cn] = l1;
                }
            }
        }
    } else {   // MODE 3: transposed fp16 V
#pragma unroll
        for (int mi = 0; mi < 2; mi++) {
            int r0 = bm + wm + mi*16 + g;
            int sl = r0 & (Ss-1);
            size_t bb = (size_t)(r0 >> 12);
#pragma unroll
            for (int ni = 0; ni < 8; ni++) {
                int cn = bn + wn + ni*8 + q*2;
                int hh = cn >> 6, dd = cn & 63;
                size_t vb = ((bb*Hh + hh)*HDh + dd) * (size_t)Ss;
                Vt[vb      + sl    ] = __float2half(acc[mi][ni][0]);
                Vt[vb + Ss + sl    ] = __float2half(acc[mi][ni][1]);
                Vt[vb      + sl + 8] = __float2half(acc[mi][ni][2]);
                Vt[vb + Ss + sl + 8] = __float2half(acc[mi][ni][3]);
            }
        }
    }
}

// ---------------- FP16 tensor-core flash attention, cp.async pipelined ---------------
// 128 q x 64 k tiles, 8 warps x (16q x 64k).
// QK^T: S = qh @ (kh + kl)^T  (2 fp16 MMAs per k16; ql term dropped)
// PV:   fp16 P @ fp16 V^T     (m16n8k16)
#define AQ 128
#define AK 64
#define KPL (AK*ROWB)                     // 9216 per 64x64-half plane (144B rows)
#define STG_BYTES (3*KPL)                 // Kh + Kl + V = 27648 per stage
#define OFF_PQ (2*STG_BYTES)              // 55296
#define ATTN_SMEM (OFF_PQ + AQ*ROWB)      // +18432 = 73728

__global__ __launch_bounds__(256) void attn_mma_kernel(
    const __half* __restrict__ Qh, const __half* __restrict__ Kh,
    const __half* __restrict__ Kl, const __half* __restrict__ Vt,
    __half* __restrict__ O)
{
    extern __shared__ char smc[];
    uint32_t sm_sh;
    asm("{ .reg .u64 t; cvta.to.shared.u64 t, %1; cvt.u32.u64 %0, t; }" : "=r"(sm_sh) : "l"(smc));
    uint32_t* sPw = (uint32_t*)(smc + OFF_PQ);
    __half* sQ = (__half*)(smc + OFF_PQ);

    const int tid = threadIdx.x;
    const int warp = tid >> 5, lane = tid & 31;
    const int g = lane >> 2, q = lane & 3;
    const int qt = 31 - blockIdx.x;          // heavy tiles first
    const int bh = blockIdx.y;
    const int b = bh >> 4, h = bh & 15;
    const size_t headoff = (size_t)b * Ss * Dd + (size_t)h * HDh;
    const size_t vhead = (size_t)bh * HDh * Ss;
    const int w16 = warp * 16;

    // ---- stage Q (hi plane only) into smem, pull fragments ----
    {
        const int r = tid >> 1, half = tid & 1;
        const __half* src = Qh + headoff + (size_t)(qt*AQ + r)*Dd + half*32;
        uint4* dst = (uint4*)(sQ + r*72 + half*32);
#pragma unroll
        for (int i = 0; i < 4; i++) dst[i] = ((const uint4*)src)[i];
    }
    __syncthreads();

    uint32_t aQ[4][4];
    {
        const uint32_t* sQw = (const uint32_t*)sQ;
#pragma unroll
        for (int s = 0; s < 4; s++) {
            int c0 = s*8 + q;
            aQ[s][0] = sQw[(w16+g  )*36 + c0];
            aQ[s][1] = sQw[(w16+8+g)*36 + c0];
            aQ[s][2] = sQw[(w16+g  )*36 + c0 + 4];
            aQ[s][3] = sQw[(w16+8+g)*36 + c0 + 4];
        }
    }

#define APREFETCH(KT) do {                                                          \
        uint32_t _stg = sm_sh + (uint32_t)((KT) & 1) * STG_BYTES;                   \
        {   /* K hi/lo planes: 2 planes x 64 rows x 128B */                         \
            int _p = tid >> 7;                                                      \
            int _r = (tid & 127) >> 1;                                              \
            int _half = tid & 1;                                                    \
            const __half* _gs = (_p ? Kl : Kh) + headoff                            \
                + (size_t)((KT)*AK + _r)*Dd + _half*32;                             \
            uint32_t _dst = _stg + (_p ? KPL : 0)                                   \
                + (uint32_t)(_r*ROWB + _half*64);                                   \
            _Pragma("unroll")                                                       \
            for (int _i = 0; _i < 4; _i++)                                          \
                CP16(_dst + _i*16, (const char*)_gs + _i*16);                       \
        }                                                                           \
        {   /* V: 64 d-rows x 128B (pre-transposed fp16) */                         \
            int _d = tid >> 2;                                                      \
            int _seg = tid & 3;                                                     \
            const __half* _gs = Vt + vhead + (size_t)_d*Ss + (KT)*AK + _seg*16;     \
            uint32_t _dst = _stg + 2*KPL + (uint32_t)(_d*ROWB + _seg*32);           \
            CP16(_dst,      _gs);                                                   \
            CP16(_dst + 16, _gs + 8);                                               \
        }                                                                           \
        asm volatile("cp.async.commit_group;");                                     \
    } while (0)

    float accO[8][4] = {};
    float m0 = -1e30f, m1 = -1e30f, l0 = 0.f, l1 = 0.f;
    const int nkt = 2*qt + 2;

    APREFETCH(0);

    for (int kt = 0; kt < nkt; kt++) {
        __syncthreads();
        if (kt + 1 < nkt) {
            APREFETCH(kt + 1);
            asm volatile("cp.async.wait_group 1;");
        } else {
            asm volatile("cp.async.wait_group 0;");
        }
        __syncthreads();

        const char* stg = smc + (kt & 1) * STG_BYTES;
        const uint32_t* sKhw = (const uint32_t*)stg;
        const uint32_t* sKlw = (const uint32_t*)(stg + KPL);
        const uint32_t* sVw  = (const uint32_t*)(stg + 2*KPL);

        // S = qh @ (kh + kl)^T
        float S[8][4] = {};
#pragma unroll
        for (int s = 0; s < 4; s++) {
            int c0 = s*8 + q;
#pragma unroll
            for (int ni = 0; ni < 8; ni++) {
                int n = ni*8 + g;
                uint32_t bh0 = sKhw[n*36 + c0], bh1 = sKhw[n*36 + c0 + 4];
                uint32_t bl0 = sKlw[n*36 + c0], bl1 = sKlw[n*36 + c0 + 4];
                MMA_F16(S[ni], aQ[s], bh0, bh1);
                MMA_F16(S[ni], aQ[s], bl0, bl1);
            }
        }

        // scale + causal mask
        const bool need_mask = (kt >= 2*qt);
        const int r0g = qt*AQ + w16 + g, r1g = r0g + 8;
#pragma unroll
        for (int ni = 0; ni < 8; ni++) {
            S[ni][0] *= 0.125f; S[ni][1] *= 0.125f;
            S[ni][2] *= 0.125f; S[ni][3] *= 0.125f;
            if (need_mask) {
                int c = kt*AK + ni*8 + 2*q;
                if (c     > r0g) S[ni][0] = -1e30f;
                if (c + 1 > r0g) S[ni][1] = -1e30f;
                if (c     > r1g) S[ni][2] = -1e30f;
                if (c + 1 > r1g) S[ni][3] = -1e30f;
            }
        }

        // online softmax
        float mx0 = -1e30f, mx1 = -1e30f;
#pragma unroll
        for (int ni = 0; ni < 8; ni++) {
            mx0 = fmaxf(mx0, fmaxf(S[ni][0], S[ni][1]));
            mx1 = fmaxf(mx1, fmaxf(S[ni][2], S[ni][3]));
        }
        mx0 = fmaxf(mx0, __shfl_xor_sync(0xffffffffu, mx0, 1));
        mx0 = fmaxf(mx0, __shfl_xor_sync(0xffffffffu, mx0, 2));
        mx1 = fmaxf(mx1, __shfl_xor_sync(0xffffffffu, mx1, 1));
        mx1 = fmaxf(mx1, __shfl_xor_sync(0xffffffffu, mx1, 2));
        float mn0 = fmaxf(m0, mx0), mn1 = fmaxf(m1, mx1);
        float cr0 = __expf(m0 - mn0), cr1 = __expf(m1 - mn1);
        m0 = mn0; m1 = mn1;
        float s0 = 0.f, s1 = 0.f;
#pragma unroll
        for (int ni = 0; ni < 8; ni++) {
            S[ni][0] = __expf(S[ni][0] - mn0);
            S[ni][1] = __expf(S[ni][1] - mn0);
            S[ni][2] = __expf(S[ni][2] - mn1);
            S[ni][3] = __expf(S[ni][3] - mn1);
            s0 += S[ni][0] + S[ni][1];
            s1 += S[ni][2] + S[ni][3];
        }
        s0 += __shfl_xor_sync(0xffffffffu, s0, 1);
        s0 += __shfl_xor_sync(0xffffffffu, s0, 2);
        s1 += __shfl_xor_sync(0xffffffffu, s1, 1);
        s1 += __shfl_xor_sync(0xffffffffu, s1, 2);
        l0 = l0*cr0 + s0;
        l1 = l1*cr1 + s1;
#pragma unroll
        for (int ni = 0; ni < 8; ni++) {
            accO[ni][0] *= cr0; accO[ni][1] *= cr0;
            accO[ni][2] *= cr1; accO[ni][3] *= cr1;
        }

        // stage P (fp16) into warp-private smem slice
#pragma unroll
        for (int ni = 0; ni < 8; ni++) {
            int wc = ni*4 + q;
            sPw[(w16+g  )*36 + wc] = h2u(__floats2half2_rn(S[ni][0], S[ni][1]));
            sPw[(w16+8+g)*36 + wc] = h2u(__floats2half2_rn(S[ni][2], S[ni][3]));
        }
        __syncwarp();

        // O += P @ V   (fp16, 4 x k16)
#pragma unroll
        for (int s = 0; s < 4; s++) {
            int c0 = s*8 + q;
            uint32_t aP[4];
            aP[0] = sPw[(w16+g  )*36 + c0];
            aP[1] = sPw[(w16+8+g)*36 + c0];
            aP[2] = sPw[(w16+g  )*36 + c0 + 4];
            aP[3] = sPw[(w16+8+g)*36 + c0 + 4];
#pragma unroll
            for (int ni = 0; ni < 8; ni++) {
                int d = ni*8 + g;
                uint32_t b0 = sVw[d*36 + c0], b1 = sVw[d*36 + c0 + 4];
                MMA_F16(accO[ni], aP, b0, b1);
            }
        }
    }
#undef APREFETCH

    // epilogue: normalize, fp16-round (feeds fp16 O-projection), store
    float inv0 = 1.f / l0, inv1 = 1.f / l1;
    size_t base0 = headoff + (size_t)(qt*AQ + w16 + g) * Dd;
    size_t base1 = base0 + (size_t)8 * Dd;
#pragma unroll
    for (int ni = 0; ni < 8; ni++) {
        int c = ni*8 + 2*q;
        *(__half2*)&O[base0 + c] = __floats2half2_rn(accO[ni][0]*inv0, accO[ni][1]*inv0);
        *(__half2*)&O[base1 + c] = __floats2half2_rn(accO[ni][2]*inv1, accO[ni][3]*inv1);
    }
}

// ---------------- launch -------------------------------------------------------------
extern "C" void kernel_launch(void* const* d_in, const int* in_sizes, int n_in,
                              void* d_out, int out_size) {
    const float* x   = (const float*)d_in[0];
    const float* fc  = (const float*)d_in[1];
    const float* fs  = (const float*)d_in[2];
    const float* wq  = (const float*)d_in[4];
    const float* wqb = (const float*)d_in[5];
    const float* wk  = (const float*)d_in[6];
    const float* wv  = (const float*)d_in[7];
    const float* wo  = (const float*)d_in[8];
    const float* wob = (const float*)d_in[9];

    __half *Wq, *Wk, *Wv, *Wo, *Xr, *Qhp, *Khp, *Klp, *Vtp, *AO;
    cudaGetSymbolAddress((void**)&Wq, g_Wq);
    cudaGetSymbolAddress((void**)&Wk, g_Wk);
    cudaGetSymbolAddress((void**)&Wv, g_Wv);
    cudaGetSymbolAddress((void**)&Wo, g_Wo);
    cudaGetSymbolAddress((void**)&Xr, g_X);
    cudaGetSymbolAddress((void**)&Qhp, g_Qh);
    cudaGetSymbolAddress((void**)&Khp, g_Kh);
    cudaGetSymbolAddress((void**)&Klp, g_Kl);
    cudaGetSymbolAddress((void**)&Vtp, g_Vt);
    cudaGetSymbolAddress((void**)&AO, g_AO);

    cudaFuncSetAttribute(hgemm_kernel<0>, cudaFuncAttributeMaxDynamicSharedMemorySize, GEMM_SMEM);
    cudaFuncSetAttribute(hgemm_kernel<1>, cudaFuncAttributeMaxDynamicSharedMemorySize, GEMM_SMEM);
    cudaFuncSetAttribute(hgemm_kernel<2>, cudaFuncAttributeMaxDynamicSharedMemorySize, GEMM_SMEM);
    cudaFuncSetAttribute(hgemm_kernel<3>, cudaFuncAttributeMaxDynamicSharedMemorySize, GEMM_SMEM);
    cudaFuncSetAttribute(attn_mma_kernel, cudaFuncAttributeMaxDynamicSharedMemorySize, ATTN_SMEM);

    // 1. Fold LoRA into the 4 effective weights (fp16); round x to fp16
    WeffArgs wa;
    wa.w[0]=wq; wa.l1[0]=(const float*)d_in[10]; wa.l2[0]=(const float*)d_in[11]; wa.out[0]=Wq;
    wa.w[1]=wk; wa.l1[1]=(const float*)d_in[12]; wa.l2[1]=(const float*)d_in[13]; wa.out[1]=Wk;
    wa.w[2]=wv; wa.l1[2]=(const float*)d_in[14]; wa.l2[2]=(const float*)d_in[15]; wa.out[2]=Wv;
    wa.w[3]=wo; wa.l1[3]=(const float*)d_in[16]; wa.l2[3]=(const float*)d_in[17]; wa.out[3]=Wo;
    build_weff4_kernel<<<4*4096, 256>>>(wa);
    round_x_kernel<<<(Mm*Dd/4)/256, 256>>>((const float4*)x, (uint2*)Xr);

    // 2. Q/K/V projections (fp16 MMA) with fused RoPE (Q hi; K hi/lo) and V transpose
    dim3 gg(Dd/BN, Mm/BM);
    hgemm_kernel<1><<<gg, 256, GEMM_SMEM>>>(Xr, Wq, wqb, nullptr, Qhp, nullptr, nullptr, fc, fs);
    hgemm_kernel<2><<<gg, 256, GEMM_SMEM>>>(Xr, Wk, nullptr, nullptr, Khp, Klp, nullptr, fc, fs);
    hgemm_kernel<3><<<gg, 256, GEMM_SMEM>>>(Xr, Wv, nullptr, nullptr, nullptr, nullptr, Vtp, nullptr, nullptr);

    // 3. FP16 tensor-core causal flash attention (pipelined)
    dim3 ga(Ss/AQ, Bb*Hh);
    attn_mma_kernel<<<ga, 256, ATTN_SMEM>>>(Qhp, Khp, Klp, Vtp, AO);

    // 4. Output projection into d_out (fp32 + bias)
    hgemm_kernel<0><<<gg, 256, GEMM_SMEM>>>(AO, Wo, wob, (float*)d_out, nullptr, nullptr, nullptr, nullptr, nullptr);
}

// round 7
// speedup vs baseline: 4.3497x; 1.0001x over previous
#include <cuda_runtime.h>
#include <cuda_fp16.h>
#include <math.h>
#include <stdint.h>

// Problem constants
#define Bb 2
#define Ss 4096
#define Dd 1024
#define Hh 16
#define HDh 64
#define Rr 16
#define Mm (Bb*Ss)            // 8192 rows

// ---------------- device scratch (all fp16) ------------------------------------------
__device__ __half g_Wq[Dd*Dd];
__device__ __half g_Wk[Dd*Dd];
__device__ __half g_Wv[Dd*Dd];
__device__ __half g_Wo[Dd*Dd];
__device__ __half g_X [(size_t)Mm*Dd];
__device__ __half g_Qh[(size_t)Mm*Dd];
__device__ __half g_Kh[(size_t)Mm*Dd];
__device__ __half g_Kl[(size_t)Mm*Dd];
__device__ __half g_Vt[(size_t)Mm*Dd];        // [b*16+h][64][4096] transposed V (fp16)
__device__ __half g_AO[(size_t)Mm*Dd];

#define CP16(dst, src) asm volatile("cp.async.cg.shared.global [%0], [%1], 16;" :: "r"(dst), "l"(src))

__device__ __forceinline__ uint32_t h2u(__half2 h) { return *(uint32_t*)&h; }

#define MMA_F16(d, a, b0, b1) \
    asm volatile("mma.sync.aligned.m16n8k16.row.col.f32.f16.f16.f32 " \
        "{%0,%1,%2,%3}, {%4,%5,%6,%7}, {%8,%9}, {%0,%1,%2,%3};" \
        : "+f"(d[0]), "+f"(d[1]), "+f"(d[2]), "+f"(d[3]) \
        : "r"(a[0]), "r"(a[1]), "r"(a[2]), "r"(a[3]), "r"(b0), "r"(b1))

#define LDSM4(r0, r1, r2, r3, addr) \
    asm volatile("ldmatrix.sync.aligned.m8n8.x4.shared.b16 {%0,%1,%2,%3}, [%4];" \
        : "=r"(r0), "=r"(r1), "=r"(r2), "=r"(r3) : "r"(addr))

// ---------------- W_eff = fp16( W + l2 @ l1 ), all 4 weights in one launch ----------
struct WeffArgs {
    const float* w[4]; const float* l1[4]; const float* l2[4]; __half* out[4];
};
__global__ void build_weff4_kernel(WeffArgs a) {
    int wi  = blockIdx.x >> 12;
    int idx = ((blockIdx.x & 4095) << 8) + threadIdx.x;
    int n = idx >> 10, k = idx & 1023;
    const float* l1 = a.l1[wi];
    const float* l2 = a.l2[wi];
    float acc = a.w[wi][idx];
#pragma unroll
    for (int r = 0; r < Rr; r++) acc += l2[n*Rr + r] * l1[r*Dd + k];
    a.out[wi][idx] = __float2half(acc);
}

__global__ void round_x_kernel(const float4* __restrict__ in, uint2* __restrict__ out) {
    int i = blockIdx.x * blockDim.x + threadIdx.x;
    float4 v = in[i];
    out[i] = make_uint2(h2u(__floats2half2_rn(v.x, v.y)), h2u(__floats2half2_rn(v.z, v.w)));
}

// ---------------- FP16 tensor-core GEMM (ldmatrix fragment loads) --------------------
#define BM 128
#define BN 128
#define HBK 64
#define ROWB 144
#define HSTG (2*BM*ROWB)
#define GSTAGES 3
#define GEMM_SMEM (GSTAGES*HSTG)
#define NCH (Dd/HBK)

template<int MODE>
__global__ __launch_bounds__(256) void hgemm_kernel(
    const __half* __restrict__ A, const __half* __restrict__ W,
    const float* __restrict__ bias, float* __restrict__ C,
    __half* __restrict__ Ph, __half* __restrict__ Pl, __half* __restrict__ Vt,
    const float* __restrict__ fc, const float* __restrict__ fs)
{
    extern __shared__ char smc[];
    uint32_t sm_sh;
    asm("{ .reg .u64 t; cvta.to.shared.u64 t, %1; cvt.u32.u64 %0, t; }" : "=r"(sm_sh) : "l"(smc));

    const int tid  = threadIdx.x;
    const int bm   = blockIdx.y * BM;
    const int bn   = blockIdx.x * BN;
    const int warp = tid >> 5, lane = tid & 31;
    const int g = lane >> 2;
    const int q = lane & 3;
    const int wm = (warp >> 1) * 32;
    const int wn = (warp & 1) * 64;
    // ldmatrix per-lane offset: row (lane&15), +16B for upper-half matrices
    const uint32_t laneoff = (uint32_t)((lane & 15) * ROWB + ((lane >> 4) << 4));

    float acc[2][8][4] = {};

#define HLOAD(CH) do {                                                      \
        uint32_t _stg = sm_sh + (uint32_t)((CH) % GSTAGES) * HSTG;          \
        _Pragma("unroll")                                                   \
        for (int _j = 0; _j < 4; _j++) {                                    \
            int _cl = tid + 256*_j;                                         \
            int _row = _cl >> 3, _seg = _cl & 7;                            \
            uint32_t _off = (uint32_t)(_row*ROWB + _seg*16);                \
            CP16(_stg + _off,            A + (size_t)(bm + _row)*Dd + (CH)*HBK + _seg*8); \
            CP16(_stg + BM*ROWB + _off,  W + (size_t)(bn + _row)*Dd + (CH)*HBK + _seg*8); \
        }                                                                   \
        asm volatile("cp.async.commit_group;");                             \
    } while (0)

    HLOAD(0);
    HLOAD(1);

    for (int it = 0; it < NCH; it++) {
        if (it + 2 < NCH) {
            HLOAD(it + 2);
            asm volatile("cp.async.wait_group 2;");
        } else if (it + 1 < NCH) {
            asm volatile("cp.async.wait_group 1;");
        } else {
            asm volatile("cp.async.wait_group 0;");
        }
        __syncthreads();

        uint32_t stg = sm_sh + (uint32_t)(it % GSTAGES) * HSTG;
        uint32_t aA = stg + (uint32_t)wm*ROWB + laneoff;
        uint32_t aB = stg + BM*ROWB + (uint32_t)wn*ROWB + laneoff;

#pragma unroll
        for (int kk = 0; kk < 4; kk++) {          // 4 x k16 (32B per row per kk)
            uint32_t af[2][4], bf[8][2];
            LDSM4(af[0][0], af[0][1], af[0][2], af[0][3], aA + kk*32);
            LDSM4(af[1][0], af[1][1], af[1][2], af[1][3], aA + 16*ROWB + kk*32);
#pragma unroll
            for (int p = 0; p < 4; p++) {
                uint32_t r0, r1, r2, r3;
                LDSM4(r0, r1, r2, r3, aB + p*16*ROWB + kk*32);
                bf[2*p][0] = r0; bf[2*p+1][0] = r1;
                bf[2*p][1] = r2; bf[2*p+1][1] = r3;
            }
#pragma unroll
            for (int mi = 0; mi < 2; mi++)
#pragma unroll
                for (int ni = 0; ni < 8; ni++)
                    MMA_F16(acc[mi][ni], af[mi], bf[ni][0], bf[ni][1]);
        }
        __syncthreads();
    }
#undef HLOAD

    // ---------------- fused epilogues ----------------
    if (MODE == 0) {
#pragma unroll
        for (int mi = 0; mi < 2; mi++) {
            int r0 = bm + wm + mi*16 + g;
#pragma unroll
            for (int ni = 0; ni < 8; ni++) {
                int cn = bn + wn + ni*8 + q*2;
                float b0 = bias[cn], b1 = bias[cn+1];
                *(float2*)&C[(size_t)r0     *Dd + cn] = make_float2(acc[mi][ni][0]+b0, acc[mi][ni][1]+b1);
                *(float2*)&C[(size_t)(r0+8) *Dd + cn] = make_float2(acc[mi][ni][2]+b0, acc[mi][ni][3]+b1);
            }
        }
    } else if (MODE == 1 || MODE == 2) {
#pragma unroll
        for (int mi = 0; mi < 2; mi++) {
            int r0 = bm + wm + mi*16 + g;
            int s0 = r0 & (Ss-1), s1 = (r0+8) & (Ss-1);
#pragma unroll
            for (int ni = 0; ni < 8; ni++) {
                int cn = bn + wn + ni*8 + q*2;
                int p = (cn & 63) >> 1;
                float b0 = 0.f, b1 = 0.f;
                if (MODE == 1) { b0 = bias[cn]; b1 = bias[cn+1]; }
                float c0 = fc[s0*32+p], n0 = fs[s0*32+p];
                float c1 = fc[s1*32+p], n1 = fs[s1*32+p];
                float e0 = acc[mi][ni][0]+b0, o0 = acc[mi][ni][1]+b1;
                float e1 = acc[mi][ni][2]+b0, o1 = acc[mi][ni][3]+b1;
                float re0 = e0*c0 - o0*n0, im0 = e0*n0 + o0*c0;
                float re1 = e1*c1 - o1*n1, im1 = e1*n1 + o1*c1;
                __half2 h0 = __floats2half2_rn(re0, im0);
                __half2 h1 = __floats2half2_rn(re1, im1);
                *(__half2*)&Ph[(size_t)r0    *Dd + cn] = h0;
                *(__half2*)&Ph[(size_t)(r0+8)*Dd + cn] = h1;
                if (MODE == 2) {
                    __half2 l0 = __floats2half2_rn(re0 - __half2float(__low2half(h0)),
                                                   im0 - __half2float(__high2half(h0)));
                    __half2 l1 = __floats2half2_rn(re1 - __half2float(__low2half(h1)),
                                                   im1 - __half2float(__high2half(h1)));
                    *(__half2*)&Pl[(size_t)r0    *Dd + cn] = l0;
                    *(__half2*)&Pl[(size_t)(r0+8)*Dd + cn] = l1;
                }
            }
        }
    } else {   // MODE 3: transposed fp16 V
#pragma unroll
        for (int mi = 0; mi < 2; mi++) {
            int r0 = bm + wm + mi*16 + g;
            int sl = r0 & (Ss-1);
            size_t bb = (size_t)(r0 >> 12);
#pragma unroll
            for (int ni = 0; ni < 8; ni++) {
                int cn = bn + wn + ni*8 + q*2;
                int hh = cn >> 6, dd = cn & 63;
                size_t vb = ((bb*Hh + hh)*HDh + dd) * (size_t)Ss;
                Vt[vb      + sl    ] = __float2half(acc[mi][ni][0]);
                Vt[vb + Ss + sl    ] = __float2half(acc[mi][ni][1]);
                Vt[vb      + sl + 8] = __float2half(acc[mi][ni][2]);
                Vt[vb + Ss + sl + 8] = __float2half(acc[mi][ni][3]);
            }
        }
    }
}

// ---------------- FP16 flash attention (ldmatrix fragment loads) ---------------------
#define AQ 128
#define AK 64
#define KPL (AK*ROWB)
#define STG_BYTES (3*KPL)
#define OFF_PQ (2*STG_BYTES)
#define ATTN_SMEM (OFF_PQ + AQ*ROWB)

__global__ __launch_bounds__(256) void attn_mma_kernel(
    const __half* __restrict__ Qh, const __half* __restrict__ Kh,
    const __half* __restrict__ Kl, const __half* __restrict__ Vt,
    __half* __restrict__ O)
{
    extern __shared__ char smc[];
    uint32_t sm_sh;
    asm("{ .reg .u64 t; cvta.to.shared.u64 t, %1; cvt.u32.u64 %0, t; }" : "=r"(sm_sh) : "l"(smc));
    uint32_t* sPw = (uint32_t*)(smc + OFF_PQ);
    __half* sQ = (__half*)(smc + OFF_PQ);

    const int tid = threadIdx.x;
    const int warp = tid >> 5, lane = tid & 31;
    const int g = lane >> 2, q = lane & 3;
    const int qt = 31 - blockIdx.x;          // heavy tiles first
    const int bh = blockIdx.y;
    const int b = bh >> 4, h = bh & 15;
    const size_t headoff = (size_t)b * Ss * Dd + (size_t)h * HDh;
    const size_t vhead = (size_t)bh * HDh * Ss;
    const int w16 = warp * 16;
    const uint32_t laneoff = (uint32_t)((lane & 15) * ROWB + ((lane >> 4) << 4));

    // ---- stage Q (hi plane) into smem, pull fragments via ldmatrix ----
    {
        const int r = tid >> 1, half = tid & 1;
        const __half* src = Qh + headoff + (size_t)(qt*AQ + r)*Dd + half*32;
        uint4* dst = (uint4*)(sQ + r*72 + half*32);
#pragma unroll
        for (int i = 0; i < 4; i++) dst[i] = ((const uint4*)src)[i];
    }
    __syncthreads();

    uint32_t aQ[4][4];
    {
        uint32_t qb = sm_sh + OFF_PQ + (uint32_t)w16*ROWB + laneoff;
#pragma unroll
        for (int s = 0; s < 4; s++)
            LDSM4(aQ[s][0], aQ[s][1], aQ[s][2], aQ[s][3], qb + s*32);
    }

#define APREFETCH(KT) do {                                                          \
        uint32_t _stg = sm_sh + (uint32_t)((KT) & 1) * STG_BYTES;                   \
        {                                                                           \
            int _p = tid >> 7;                                                      \
            int _r = (tid & 127) >> 1;                                              \
            int _half = tid & 1;                                                    \
            const __half* _gs = (_p ? Kl : Kh) + headoff                            \
                + (size_t)((KT)*AK + _r)*Dd + _half*32;                             \
            uint32_t _dst = _stg + (_p ? KPL : 0)                                   \
                + (uint32_t)(_r*ROWB + _half*64);                                   \
            _Pragma("unroll")                                                       \
            for (int _i = 0; _i < 4; _i++)                                          \
                CP16(_dst + _i*16, (const char*)_gs + _i*16);                       \
        }                                                                           \
        {                                                                           \
            int _d = tid >> 2;                                                      \
            int _seg = tid & 3;                                                     \
            const __half* _gs = Vt + vhead + (size_t)_d*Ss + (KT)*AK + _seg*16;     \
            uint32_t _dst = _stg + 2*KPL + (uint32_t)(_d*ROWB + _seg*32);           \
            CP16(_dst,      _gs);                                                   \
            CP16(_dst + 16, _gs + 8);                                               \
        }                                                                           \
        asm volatile("cp.async.commit_group;");                                     \
    } while (0)

    float accO[8][4] = {};
    float m0 = -1e30f, m1 = -1e30f, l0 = 0.f, l1 = 0.f;
    const int nkt = 2*qt + 2;

    APREFETCH(0);

    for (int kt = 0; kt < nkt; kt++) {
        __syncthreads();
        if (kt + 1 < nkt) {
            APREFETCH(kt + 1);
            asm volatile("cp.async.wait_group 1;");
        } else {
            asm volatile("cp.async.wait_group 0;");
        }
        __syncthreads();

        uint32_t stg = sm_sh + (uint32_t)(kt & 1) * STG_BYTES;
        uint32_t aKh = stg + laneoff;
        uint32_t aKl = aKh + KPL;
        uint32_t aV  = aKh + 2*KPL;
        uint32_t aP  = sm_sh + OFF_PQ + (uint32_t)w16*ROWB + laneoff;

        // S = qh @ (kh + kl)^T
        float S[8][4] = {};
#pragma unroll
        for (int s = 0; s < 4; s++) {
            uint32_t bh[8][2], bl[8][2];
#pragma unroll
            for (int p = 0; p < 4; p++) {
                uint32_t r0, r1, r2, r3;
                LDSM4(r0, r1, r2, r3, aKh + p*16*ROWB + s*32);
                bh[2*p][0] = r0; bh[2*p+1][0] = r1; bh[2*p][1] = r2; bh[2*p+1][1] = r3;
                LDSM4(r0, r1, r2, r3, aKl + p*16*ROWB + s*32);
                bl[2*p][0] = r0; bl[2*p+1][0] = r1; bl[2*p][1] = r2; bl[2*p+1][1] = r3;
            }
#pragma unroll
            for (int ni = 0; ni < 8; ni++) {
                MMA_F16(S[ni], aQ[s], bh[ni][0], bh[ni][1]);
                MMA_F16(S[ni], aQ[s], bl[ni][0], bl[ni][1]);
            }
        }

        // scale + causal mask
        const bool need_mask = (kt >= 2*qt);
        const int r0g = qt*AQ + w16 + g, r1g = r0g + 8;
#pragma unroll
        for (int ni = 0; ni < 8; ni++) {
            S[ni][0] *= 0.125f; S[ni][1] *= 0.125f;
            S[ni][2] *= 0.125f; S[ni][3] *= 0.125f;
            if (need_mask) {
                int c = kt*AK + ni*8 + 2*q;
                if (c     > r0g) S[ni][0] = -1e30f;
                if (c + 1 > r0g) S[ni][1] = -1e30f;
                if (c     > r1g) S[ni][2] = -1e30f;
                if (c + 1 > r1g) S[ni][3] = -1e30f;
            }
        }

        // online softmax
        float mx0 = -1e30f, mx1 = -1e30f;
#pragma unroll
        for (int ni = 0; ni < 8; ni++) {
            mx0 = fmaxf(mx0, fmaxf(S[ni][0], S[ni][1]));
            mx1 = fmaxf(mx1, fmaxf(S[ni][2], S[ni][3]));
        }
        mx0 = fmaxf(mx0, __shfl_xor_sync(0xffffffffu, mx0, 1));
        mx0 = fmaxf(mx0, __shfl_xor_sync(0xffffffffu, mx0, 2));
        mx1 = fmaxf(mx1, __shfl_xor_sync(0xffffffffu, mx1, 1));
        mx1 = fmaxf(mx1, __shfl_xor_sync(0xffffffffu, mx1, 2));
        float mn0 = fmaxf(m0, mx0), mn1 = fmaxf(m1, mx1);
        float cr0 = __expf(m0 - mn0), cr1 = __expf(m1 - mn1);
        m0 = mn0; m1 = mn1;
        float s0 = 0.f, s1 = 0.f;
#pragma unroll
        for (int ni = 0; ni < 8; ni++) {
            S[ni][0] = __expf(S[ni][0] - mn0);
            S[ni][1] = __expf(S[ni][1] - mn0);
            S[ni][2] = __expf(S[ni][2] - mn1);
            S[ni][3] = __expf(S[ni][3] - mn1);
            s0 += S[ni][0] + S[ni][1];
            s1 += S[ni][2] + S[ni][3];
        }
        s0 += __shfl_xor_sync(0xffffffffu, s0, 1);
        s0 += __shfl_xor_sync(0xffffffffu, s0, 2);
        s1 += __shfl_xor_sync(0xffffffffu, s1, 1);
        s1 += __shfl_xor_sync(0xffffffffu, s1, 2);
        l0 = l0*cr0 + s0;
        l1 = l1*cr1 + s1;
#pragma unroll
        for (int ni = 0; ni < 8; ni++) {
            accO[ni][0] *= cr0; accO[ni][1] *= cr0;
            accO[ni][2] *= cr1; accO[ni][3] *= cr1;
        }

        // stage P (fp16) into warp-private smem slice
#pragma unroll
        for (int ni = 0; ni < 8; ni++) {
            int wc = ni*4 + q;
            sPw[(w16+g  )*36 + wc] = h2u(__floats2half2_rn(S[ni][0], S[ni][1]));
            sPw[(w16+8+g)*36 + wc] = h2u(__floats2half2_rn(S[ni][2], S[ni][3]));
        }
        __syncwarp();

        // O += P @ V   (fp16, 4 x k16)
#pragma unroll
        for (int s = 0; s < 4; s++) {
            uint32_t ap[4];
            LDSM4(ap[0], ap[1], ap[2], ap[3], aP + s*32);
            uint32_t bv[8][2];
#pragma unroll
            for (int p = 0; p < 4; p++) {
                uint32_t r0, r1, r2, r3;
                LDSM4(r0, r1, r2, r3, aV + p*16*ROWB + s*32);
                bv[2*p][0] = r0; bv[2*p+1][0] = r1; bv[2*p][1] = r2; bv[2*p+1][1] = r3;
            }
#pragma unroll
            for (int ni = 0; ni < 8; ni++)
                MMA_F16(accO[ni], ap, bv[ni][0], bv[ni][1]);
        }
    }
#undef APREFETCH

    // epilogue: normalize, fp16-round (feeds fp16 O-projection), store
    float inv0 = 1.f / l0, inv1 = 1.f / l1;
    size_t base0 = headoff + (size_t)(qt*AQ + w16 + g) * Dd;
    size_t base1 = base0 + (size_t)8 * Dd;
#pragma unroll
    for (int ni = 0; ni < 8; ni++) {
        int c = ni*8 + 2*q;
        *(__half2*)&O[base0 + c] = __floats2half2_rn(accO[ni][0]*inv0, accO[ni][1]*inv0);
        *(__half2*)&O[base1 + c] = __floats2half2_rn(accO[ni][2]*inv1, accO[ni][3]*inv1);
    }
}

// ---------------- launch -------------------------------------------------------------
extern "C" void kernel_launch(void* const* d_in, const int* in_sizes, int n_in,
                              void* d_out, int out_size) {
    const float* x   = (const float*)d_in[0];
    const float* fc  = (const float*)d_in[1];
    const float* fs  = (const float*)d_in[2];
    const float* wq  = (const float*)d_in[4];
    const float* wqb = (const float*)d_in[5];
    const float* wk  = (const float*)d_in[6];
    const float* wv  = (const float*)d_in[7];
    const float* wo  = (const float*)d_in[8];
    const float* wob = (const float*)d_in[9];

    __half *Wq, *Wk, *Wv, *Wo, *Xr, *Qhp, *Khp, *Klp, *Vtp, *AO;
    cudaGetSymbolAddress((void**)&Wq, g_Wq);
    cudaGetSymbolAddress((void**)&Wk, g_Wk);
    cudaGetSymbolAddress((void**)&Wv, g_Wv);
    cudaGetSymbolAddress((void**)&Wo, g_Wo);
    cudaGetSymbolAddress((void**)&Xr, g_X);
    cudaGetSymbolAddress((void**)&Qhp, g_Qh);
    cudaGetSymbolAddress((void**)&Khp, g_Kh);
    cudaGetSymbolAddress((void**)&Klp, g_Kl);
    cudaGetSymbolAddress((void**)&Vtp, g_Vt);
    cudaGetSymbolAddress((void**)&AO, g_AO);

    cudaFuncSetAttribute(hgemm_kernel<0>, cudaFuncAttributeMaxDynamicSharedMemorySize, GEMM_SMEM);
    cudaFuncSetAttribute(hgemm_kernel<1>, cudaFuncAttributeMaxDynamicSharedMemorySize, GEMM_SMEM);
    cudaFuncSetAttribute(hgemm_kernel<2>, cudaFuncAttributeMaxDynamicSharedMemorySize, GEMM_SMEM);
    cudaFuncSetAttribute(hgemm_kernel<3>, cudaFuncAttributeMaxDynamicSharedMemorySize, GEMM_SMEM);
    cudaFuncSetAttribute(attn_mma_kernel, cudaFuncAttributeMaxDynamicSharedMemorySize, ATTN_SMEM);

    // 1. Fold LoRA into the 4 effective weights (fp16); round x to fp16
    WeffArgs wa;
    wa.w[0]=wq; wa.l1[0]=(const float*)d_in[10]; wa.l2[0]=(const float*)d_in[11]; wa.out[0]=Wq;
    wa.w[1]=wk; wa.l1[1]=(const float*)d_in[12]; wa.l2[1]=(const float*)d_in[13]; wa.out[1]=Wk;
    wa.w[2]=wv; wa.l1[2]=(const float*)d_in[14]; wa.l2[2]=(const float*)d_in[15]; wa.out[2]=Wv;
    wa.w[3]=wo; wa.l1[3]=(const float*)d_in[16]; wa.l2[3]=(const float*)d_in[17]; wa.out[3]=Wo;
    build_weff4_kernel<<<4*4096, 256>>>(wa);
    round_x_kernel<<<(Mm*Dd/4)/256, 256>>>((const float4*)x, (uint2*)Xr);

    // 2. Q/K/V projections (fp16 MMA) with fused RoPE (Q hi; K hi/lo) and V transpose
    dim3 gg(Dd/BN, Mm/BM);
    hgemm_kernel<1><<<gg, 256, GEMM_SMEM>>>(Xr, Wq, wqb, nullptr, Qhp, nullptr, nullptr, fc, fs);
    hgemm_kernel<2><<<gg, 256, GEMM_SMEM>>>(Xr, Wk, nullptr, nullptr, Khp, Klp, nullptr, fc, fs);
    hgemm_kernel<3><<<gg, 256, GEMM_SMEM>>>(Xr, Wv, nullptr, nullptr, nullptr, nullptr, Vtp, nullptr, nullptr);

    // 3. FP16 tensor-core causal flash attention (pipelined)
    dim3 ga(Ss/AQ, Bb*Hh);
    attn_mma_kernel<<<ga, 256, ATTN_SMEM>>>(Qhp, Khp, Klp, Vtp, AO);

    // 4. Output projection into d_out (fp32 + bias)
    hgemm_kernel<0><<<gg, 256, GEMM_SMEM>>>(AO, Wo, wob, (float*)d_out, nullptr, nullptr, nullptr, nullptr, nullptr);
}

// round 8
// speedup vs baseline: 5.2140x; 1.1987x over previous
#include <cuda_runtime.h>
#include <cuda_fp16.h>
#include <math.h>
#include <stdint.h>

// Problem constants
#define Bb 2
#define Ss 4096
#define Dd 1024
#define Hh 16
#define HDh 64
#define Rr 16
#define Mm (Bb*Ss)            // 8192 rows

// ---------------- device scratch (all fp16) ------------------------------------------
__device__ __half g_Wq[Dd*Dd];
__device__ __half g_Wk[Dd*Dd];
__device__ __half g_Wv[Dd*Dd];
__device__ __half g_Wo[Dd*Dd];
__device__ __half g_X [(size_t)Mm*Dd];
__device__ __half g_Qh[(size_t)Mm*Dd];
__device__ __half g_Kh[(size_t)Mm*Dd];
__device__ __half g_Vt[(size_t)Mm*Dd];        // [b*16+h][64][4096] transposed V (fp16)
__device__ __half g_AO[(size_t)Mm*Dd];

#define CP16(dst, src) asm volatile("cp.async.cg.shared.global [%0], [%1], 16;" :: "r"(dst), "l"(src))

__device__ __forceinline__ uint32_t h2u(__half2 h) { return *(uint32_t*)&h; }

#define MMA_F16(d, a, b0, b1) \
    asm volatile("mma.sync.aligned.m16n8k16.row.col.f32.f16.f16.f32 " \
        "{%0,%1,%2,%3}, {%4,%5,%6,%7}, {%8,%9}, {%0,%1,%2,%3};" \
        : "+f"(d[0]), "+f"(d[1]), "+f"(d[2]), "+f"(d[3]) \
        : "r"(a[0]), "r"(a[1]), "r"(a[2]), "r"(a[3]), "r"(b0), "r"(b1))

#define LDSM4(r0, r1, r2, r3, addr) \
    asm volatile("ldmatrix.sync.aligned.m8n8.x4.shared.b16 {%0,%1,%2,%3}, [%4];" \
        : "=r"(r0), "=r"(r1), "=r"(r2), "=r"(r3) : "r"(addr))

// ---------------- W_eff = fp16( W + l2 @ l1 ), all 4 weights in one launch ----------
struct WeffArgs {
    const float* w[4]; const float* l1[4]; const float* l2[4]; __half* out[4];
};
__global__ void build_weff4_kernel(WeffArgs a) {
    int wi  = blockIdx.x >> 12;
    int idx = ((blockIdx.x & 4095) << 8) + threadIdx.x;
    int n = idx >> 10, k = idx & 1023;
    const float* l1 = a.l1[wi];
    const float* l2 = a.l2[wi];
    float acc = a.w[wi][idx];
#pragma unroll
    for (int r = 0; r < Rr; r++) acc += l2[n*Rr + r] * l1[r*Dd + k];
    a.out[wi][idx] = __float2half(acc);
}

__global__ void round_x_kernel(const float4* __restrict__ in, uint2* __restrict__ out) {
    int i = blockIdx.x * blockDim.x + threadIdx.x;
    float4 v = in[i];
    out[i] = make_uint2(h2u(__floats2half2_rn(v.x, v.y)), h2u(__floats2half2_rn(v.z, v.w)));
}

// ---------------- FP16 tensor-core GEMM (single-barrier 3-stage pipeline) ------------
// MODE 0: C = D + bias (fp32)
// MODE 1: Qh = fp16(rope(D + bias))
// MODE 2: Kh = fp16(rope(D))
// MODE 3: Vt[(b*16+h)*64+d][s] = fp16(D)   (transposed V)
#define BM 128
#define BN 128
#define HBK 64
#define ROWB 144
#define HSTG (2*BM*ROWB)
#define GSTAGES 3
#define GEMM_SMEM (GSTAGES*HSTG)
#define NCH (Dd/HBK)

template<int MODE>
__global__ __launch_bounds__(256) void hgemm_kernel(
    const __half* __restrict__ A, const __half* __restrict__ W,
    const float* __restrict__ bias, float* __restrict__ C,
    __half* __restrict__ Ph, __half* __restrict__ Vt,
    const float* __restrict__ fc, const float* __restrict__ fs)
{
    extern __shared__ char smc[];
    uint32_t sm_sh;
    asm("{ .reg .u64 t; cvta.to.shared.u64 t, %1; cvt.u32.u64 %0, t; }" : "=r"(sm_sh) : "l"(smc));

    const int tid  = threadIdx.x;
    const int bm   = blockIdx.y * BM;
    const int bn   = blockIdx.x * BN;
    const int warp = tid >> 5, lane = tid & 31;
    const int g = lane >> 2;
    const int q = lane & 3;
    const int wm = (warp >> 1) * 32;
    const int wn = (warp & 1) * 64;
    const uint32_t laneoff = (uint32_t)((lane & 15) * ROWB + ((lane >> 4) << 4));

    float acc[2][8][4] = {};

#define HLOAD(CH) do {                                                      \
        uint32_t _stg = sm_sh + (uint32_t)((CH) % GSTAGES) * HSTG;          \
        _Pragma("unroll")                                                   \
        for (int _j = 0; _j < 4; _j++) {                                    \
            int _cl = tid + 256*_j;                                         \
            int _row = _cl >> 3, _seg = _cl & 7;                            \
            uint32_t _off = (uint32_t)(_row*ROWB + _seg*16);                \
            CP16(_stg + _off,            A + (size_t)(bm + _row)*Dd + (CH)*HBK + _seg*8); \
            CP16(_stg + BM*ROWB + _off,  W + (size_t)(bn + _row)*Dd + (CH)*HBK + _seg*8); \
        }                                                                   \
        asm volatile("cp.async.commit_group;");                             \
    } while (0)

    HLOAD(0);
    HLOAD(1);

    for (int it = 0; it < NCH; it++) {
        if (it + 1 < NCH) asm volatile("cp.async.wait_group 1;");
        else              asm volatile("cp.async.wait_group 0;");
        __syncthreads();
        if (it + 2 < NCH) HLOAD(it + 2);   // writes slot drained at iter it-1

        uint32_t stg = sm_sh + (uint32_t)(it % GSTAGES) * HSTG;
        uint32_t aA = stg + (uint32_t)wm*ROWB + laneoff;
        uint32_t aB = stg + BM*ROWB + (uint32_t)wn*ROWB + laneoff;

#pragma unroll
        for (int kk = 0; kk < 4; kk++) {
            uint32_t af[2][4], bf[8][2];
            LDSM4(af[0][0], af[0][1], af[0][2], af[0][3], aA + kk*32);
            LDSM4(af[1][0], af[1][1], af[1][2], af[1][3], aA + 16*ROWB + kk*32);
#pragma unroll
            for (int p = 0; p < 4; p++) {
                uint32_t r0, r1, r2, r3;
                LDSM4(r0, r1, r2, r3, aB + p*16*ROWB + kk*32);
                bf[2*p][0] = r0; bf[2*p+1][0] = r1;
                bf[2*p][1] = r2; bf[2*p+1][1] = r3;
            }
#pragma unroll
            for (int mi = 0; mi < 2; mi++)
#pragma unroll
                for (int ni = 0; ni < 8; ni++)
                    MMA_F16(acc[mi][ni], af[mi], bf[ni][0], bf[ni][1]);
        }
    }
#undef HLOAD

    // ---------------- fused epilogues ----------------
    if (MODE == 0) {
#pragma unroll
        for (int mi = 0; mi < 2; mi++) {
            int r0 = bm + wm + mi*16 + g;
#pragma unroll
            for (int ni = 0; ni < 8; ni++) {
                int cn = bn + wn + ni*8 + q*2;
                float b0 = bias[cn], b1 = bias[cn+1];
                *(float2*)&C[(size_t)r0     *Dd + cn] = make_float2(acc[mi][ni][0]+b0, acc[mi][ni][1]+b1);
                *(float2*)&C[(size_t)(r0+8) *Dd + cn] = make_float2(acc[mi][ni][2]+b0, acc[mi][ni][3]+b1);
            }
        }
    } else if (MODE == 1 || MODE == 2) {
#pragma unroll
        for (int mi = 0; mi < 2; mi++) {
            int r0 = bm + wm + mi*16 + g;
            int s0 = r0 & (Ss-1), s1 = (r0+8) & (Ss-1);
#pragma unroll
            for (int ni = 0; ni < 8; ni++) {
                int cn = bn + wn + ni*8 + q*2;
                int p = (cn & 63) >> 1;
                float b0 = 0.f, b1 = 0.f;
                if (MODE == 1) { b0 = bias[cn]; b1 = bias[cn+1]; }
                float c0 = fc[s0*32+p], n0 = fs[s0*32+p];
                float c1 = fc[s1*32+p], n1 = fs[s1*32+p];
                float e0 = acc[mi][ni][0]+b0, o0 = acc[mi][ni][1]+b1;
                float e1 = acc[mi][ni][2]+b0, o1 = acc[mi][ni][3]+b1;
                *(__half2*)&Ph[(size_t)r0    *Dd + cn] = __floats2half2_rn(e0*c0 - o0*n0, e0*n0 + o0*c0);
                *(__half2*)&Ph[(size_t)(r0+8)*Dd + cn] = __floats2half2_rn(e1*c1 - o1*n1, e1*n1 + o1*c1);
            }
        }
    } else {   // MODE 3: transposed fp16 V
#pragma unroll
        for (int mi = 0; mi < 2; mi++) {
            int r0 = bm + wm + mi*16 + g;
            int sl = r0 & (Ss-1);
            size_t bb = (size_t)(r0 >> 12);
#pragma unroll
            for (int ni = 0; ni < 8; ni++) {
                int cn = bn + wn + ni*8 + q*2;
                int hh = cn >> 6, dd = cn & 63;
                size_t vb = ((bb*Hh + hh)*HDh + dd) * (size_t)Ss;
                Vt[vb      + sl    ] = __float2half(acc[mi][ni][0]);
                Vt[vb + Ss + sl    ] = __float2half(acc[mi][ni][1]);
                Vt[vb      + sl + 8] = __float2half(acc[mi][ni][2]);
                Vt[vb + Ss + sl + 8] = __float2half(acc[mi][ni][3]);
            }
        }
    }
}

// ---------------- FP16 flash attention: single K plane, 3-stage, 1 barrier/iter ------
#define AQ 128
#define AK 64
#define KPL (AK*ROWB)                     // 9216 per 64x64-half plane
#define STG_BYTES (2*KPL)                 // Kh + V = 18432 per stage
#define ASTAGES 3
#define OFF_PQ (ASTAGES*STG_BYTES)        // 55296
#define ATTN_SMEM (OFF_PQ + AQ*ROWB)      // +18432 = 73728

__global__ __launch_bounds__(256) void attn_mma_kernel(
    const __half* __restrict__ Qh, const __half* __restrict__ Kh,
    const __half* __restrict__ Vt, __half* __restrict__ O)
{
    extern __shared__ char smc[];
    uint32_t sm_sh;
    asm("{ .reg .u64 t; cvta.to.shared.u64 t, %1; cvt.u32.u64 %0, t; }" : "=r"(sm_sh) : "l"(smc));
    uint32_t* sPw = (uint32_t*)(smc + OFF_PQ);
    __half* sQ = (__half*)(smc + OFF_PQ);

    const int tid = threadIdx.x;
    const int warp = tid >> 5, lane = tid & 31;
    const int g = lane >> 2, q = lane & 3;
    const int qt = 31 - blockIdx.x;          // heavy tiles first
    const int bh = blockIdx.y;
    const int b = bh >> 4, h = bh & 15;
    const size_t headoff = (size_t)b * Ss * Dd + (size_t)h * HDh;
    const size_t vhead = (size_t)bh * HDh * Ss;
    const int w16 = warp * 16;
    const uint32_t laneoff = (uint32_t)((lane & 15) * ROWB + ((lane >> 4) << 4));

    // ---- stage Q into smem, pull fragments via ldmatrix ----
    {
        const int r = tid >> 1, half = tid & 1;
        const __half* src = Qh + headoff + (size_t)(qt*AQ + r)*Dd + half*32;
        uint4* dst = (uint4*)(sQ + r*72 + half*32);
#pragma unroll
        for (int i = 0; i < 4; i++) dst[i] = ((const uint4*)src)[i];
    }
    __syncthreads();

    uint32_t aQ[4][4];
    {
        uint32_t qb = sm_sh + OFF_PQ + (uint32_t)w16*ROWB + laneoff;
#pragma unroll
        for (int s = 0; s < 4; s++)
            LDSM4(aQ[s][0], aQ[s][1], aQ[s][2], aQ[s][3], qb + s*32);
    }
    __syncthreads();   // all Q fragments pulled before P staging overwrites sQ

#define APREFETCH(KT) do {                                                          \
        uint32_t _stg = sm_sh + (uint32_t)((KT) % ASTAGES) * STG_BYTES;             \
        int _pl = tid >> 7;                 /* 0: K plane, 1: V plane */            \
        int _r = (tid & 127) >> 1;                                                  \
        int _half = tid & 1;                                                        \
        const __half* _gs;                                                          \
        if (_pl == 0) _gs = Kh + headoff + (size_t)((KT)*AK + _r)*Dd + _half*32;    \
        else          _gs = Vt + vhead + (size_t)_r*Ss + (KT)*AK + _half*32;        \
        uint32_t _dst = _stg + (_pl ? KPL : 0) + (uint32_t)(_r*ROWB + _half*64);    \
        _Pragma("unroll")                                                           \
        for (int _i = 0; _i < 4; _i++)                                              \
            CP16(_dst + _i*16, (const char*)_gs + _i*16);                           \
        asm volatile("cp.async.commit_group;");                                     \
    } while (0)

    float accO[8][4] = {};
    float m0 = -1e30f, m1 = -1e30f, l0 = 0.f, l1 = 0.f;
    const int nkt = 2*qt + 2;

    APREFETCH(0);
    APREFETCH(1);

    for (int kt = 0; kt < nkt; kt++) {
        if (kt + 1 < nkt) asm volatile("cp.async.wait_group 1;");
        else              asm volatile("cp.async.wait_group 0;");
        __syncthreads();
        if (kt + 2 < nkt) APREFETCH(kt + 2);   // writes slot drained at iter kt-1

        uint32_t stg = sm_sh + (uint32_t)(kt % ASTAGES) * STG_BYTES;
        uint32_t aK = stg + laneoff;
        uint32_t aV = aK + KPL;
        uint32_t aP = sm_sh + OFF_PQ + (uint32_t)w16*ROWB + laneoff;

        // S = q @ k^T  (single fp16 plane)
        float S[8][4] = {};
#pragma unroll
        for (int s = 0; s < 4; s++) {
            uint32_t bk[8][2];
#pragma unroll
            for (int p = 0; p < 4; p++) {
                uint32_t r0, r1, r2, r3;
                LDSM4(r0, r1, r2, r3, aK + p*16*ROWB + s*32);
                bk[2*p][0] = r0; bk[2*p+1][0] = r1; bk[2*p][1] = r2; bk[2*p+1][1] = r3;
            }
#pragma unroll
            for (int ni = 0; ni < 8; ni++)
                MMA_F16(S[ni], aQ[s], bk[ni][0], bk[ni][1]);
        }

        // scale + causal mask
        const bool need_mask = (kt >= 2*qt);
        const int r0g = qt*AQ + w16 + g, r1g = r0g + 8;
#pragma unroll
        for (int ni = 0; ni < 8; ni++) {
            S[ni][0] *= 0.125f; S[ni][1] *= 0.125f;
            S[ni][2] *= 0.125f; S[ni][3] *= 0.125f;
            if (need_mask) {
                int c = kt*AK + ni*8 + 2*q;
                if (c     > r0g) S[ni][0] = -1e30f;
                if (c + 1 > r0g) S[ni][1] = -1e30f;
                if (c     > r1g) S[ni][2] = -1e30f;
                if (c + 1 > r1g) S[ni][3] = -1e30f;
            }
        }

        // online softmax
        float mx0 = -1e30f, mx1 = -1e30f;
#pragma unroll
        for (int ni = 0; ni < 8; ni++) {
            mx0 = fmaxf(mx0, fmaxf(S[ni][0], S[ni][1]));
            mx1 = fmaxf(mx1, fmaxf(S[ni][2], S[ni][3]));
        }
        mx0 = fmaxf(mx0, __shfl_xor_sync(0xffffffffu, mx0, 1));
        mx0 = fmaxf(mx0, __shfl_xor_sync(0xffffffffu, mx0, 2));
        mx1 = fmaxf(mx1, __shfl_xor_sync(0xffffffffu, mx1, 1));
        mx1 = fmaxf(mx1, __shfl_xor_sync(0xffffffffu, mx1, 2));
        float mn0 = fmaxf(m0, mx0), mn1 = fmaxf(m1, mx1);
        float cr0 = __expf(m0 - mn0), cr1 = __expf(m1 - mn1);
        m0 = mn0; m1 = mn1;
        float s0 = 0.f, s1 = 0.f;
#pragma unroll
        for (int ni = 0; ni < 8; ni++) {
            S[ni][0] = __expf(S[ni][0] - mn0);
            S[ni][1] = __expf(S[ni][1] - mn0);
            S[ni][2] = __expf(S[ni][2] - mn1);
            S[ni][3] = __expf(S[ni][3] - mn1);
            s0 += S[ni][0] + S[ni][1];
            s1 += S[ni][2] + S[ni][3];
        }
        s0 += __shfl_xor_sync(0xffffffffu, s0, 1);
        s0 += __shfl_xor_sync(0xffffffffu, s0, 2);
        s1 += __shfl_xor_sync(0xffffffffu, s1, 1);
        s1 += __shfl_xor_sync(0xffffffffu, s1, 2);
        l0 = l0*cr0 + s0;
        l1 = l1*cr1 + s1;
#pragma unroll
        for (int ni = 0; ni < 8; ni++) {
            accO[ni][0] *= cr0; accO[ni][1] *= cr0;
            accO[ni][2] *= cr1; accO[ni][3] *= cr1;
        }

        // stage P (fp16) into warp-private smem slice
#pragma unroll
        for (int ni = 0; ni < 8; ni++) {
            int wc = ni*4 + q;
            sPw[(w16+g  )*36 + wc] = h2u(__floats2half2_rn(S[ni][0], S[ni][1]));
            sPw[(w16+8+g)*36 + wc] = h2u(__floats2half2_rn(S[ni][2], S[ni][3]));
        }
        __syncwarp();

        // O += P @ V   (fp16, 4 x k16)
#pragma unroll
        for (int s = 0; s < 4; s++) {
            uint32_t ap[4];
            LDSM4(ap[0], ap[1], ap[2], ap[3], aP + s*32);
            uint32_t bv[8][2];
#pragma unroll
            for (int p = 0; p < 4; p++) {
                uint32_t r0, r1, r2, r3;
                LDSM4(r0, r1, r2, r3, aV + p*16*ROWB + s*32);
                bv[2*p][0] = r0; bv[2*p+1][0] = r1; bv[2*p][1] = r2; bv[2*p+1][1] = r3;
            }
#pragma unroll
            for (int ni = 0; ni < 8; ni++)
                MMA_F16(accO[ni], ap, bv[ni][0], bv[ni][1]);
        }
    }
#undef APREFETCH

    // epilogue: normalize, fp16-round (feeds fp16 O-projection), store
    float inv0 = 1.f / l0, inv1 = 1.f / l1;
    size_t base0 = headoff + (size_t)(qt*AQ + w16 + g) * Dd;
    size_t base1 = base0 + (size_t)8 * Dd;
#pragma unroll
    for (int ni = 0; ni < 8; ni++) {
        int c = ni*8 + 2*q;
        *(__half2*)&O[base0 + c] = __floats2half2_rn(accO[ni][0]*inv0, accO[ni][1]*inv0);
        *(__half2*)&O[base1 + c] = __floats2half2_rn(accO[ni][2]*inv1, accO[ni][3]*inv1);
    }
}

// ---------------- launch -------------------------------------------------------------
extern "C" void kernel_launch(void* const* d_in, const int* in_sizes, int n_in,
                              void* d_out, int out_size) {
    const float* x   = (const float*)d_in[0];
    const float* fc  = (const float*)d_in[1];
    const float* fs  = (const float*)d_in[2];
    const float* wq  = (const float*)d_in[4];
    const float* wqb = (const float*)d_in[5];
    const float* wk  = (const float*)d_in[6];
    const float* wv  = (const float*)d_in[7];
    const float* wo  = (const float*)d_in[8];
    const float* wob = (const float*)d_in[9];

    __half *Wq, *Wk, *Wv, *Wo, *Xr, *Qhp, *Khp, *Vtp, *AO;
    cudaGetSymbolAddress((void**)&Wq, g_Wq);
    cudaGetSymbolAddress((void**)&Wk, g_Wk);
    cudaGetSymbolAddress((void**)&Wv, g_Wv);
    cudaGetSymbolAddress((void**)&Wo, g_Wo);
    cudaGetSymbolAddress((void**)&Xr, g_X);
    cudaGetSymbolAddress((void**)&Qhp, g_Qh);
    cudaGetSymbolAddress((void**)&Khp, g_Kh);
    cudaGetSymbolAddress((void**)&Vtp, g_Vt);
    cudaGetSymbolAddress((void**)&AO, g_AO);

    cudaFuncSetAttribute(hgemm_kernel<0>, cudaFuncAttributeMaxDynamicSharedMemorySize, GEMM_SMEM);
    cudaFuncSetAttribute(hgemm_kernel<1>, cudaFuncAttributeMaxDynamicSharedMemorySize, GEMM_SMEM);
    cudaFuncSetAttribute(hgemm_kernel<2>, cudaFuncAttributeMaxDynamicSharedMemorySize, GEMM_SMEM);
    cudaFuncSetAttribute(hgemm_kernel<3>, cudaFuncAttributeMaxDynamicSharedMemorySize, GEMM_SMEM);
    cudaFuncSetAttribute(attn_mma_kernel, cudaFuncAttributeMaxDynamicSharedMemorySize, ATTN_SMEM);

    // 1. Fold LoRA into the 4 effective weights (fp16); round x to fp16
    WeffArgs wa;
    wa.w[0]=wq; wa.l1[0]=(const float*)d_in[10]; wa.l2[0]=(const float*)d_in[11]; wa.out[0]=Wq;
    wa.w[1]=wk; wa.l1[1]=(const float*)d_in[12]; wa.l2[1]=(const float*)d_in[13]; wa.out[1]=Wk;
    wa.w[2]=wv; wa.l1[2]=(const float*)d_in[14]; wa.l2[2]=(const float*)d_in[15]; wa.out[2]=Wv;
    wa.w[3]=wo; wa.l1[3]=(const float*)d_in[16]; wa.l2[3]=(const float*)d_in[17]; wa.out[3]=Wo;
    build_weff4_kernel<<<4*4096, 256>>>(wa);
    round_x_kernel<<<(Mm*Dd/4)/256, 256>>>((const float4*)x, (uint2*)Xr);

    // 2. Q/K/V projections (fp16 MMA) with fused RoPE (Q, K) and V transpose
    dim3 gg(Dd/BN, Mm/BM);
    hgemm_kernel<1><<<gg, 256, GEMM_SMEM>>>(Xr, Wq, wqb, nullptr, Qhp, nullptr, fc, fs);
    hgemm_kernel<2><<<gg, 256, GEMM_SMEM>>>(Xr, Wk, nullptr, nullptr, Khp, nullptr, fc, fs);
    hgemm_kernel<3><<<gg, 256, GEMM_SMEM>>>(Xr, Wv, nullptr, nullptr, nullptr, Vtp, nullptr, nullptr);

    // 3. FP16 tensor-core causal flash attention (3-stage, 1 barrier/iter)
    dim3 ga(Ss/AQ, Bb*Hh);
    attn_mma_kernel<<<ga, 256, ATTN_SMEM>>>(Qhp, Khp, Vtp, AO);

    // 4. Output projection into d_out (fp32 + bias)
    hgemm_kernel<0><<<gg, 256, GEMM_SMEM>>>(AO, Wo, wob, (float*)d_out, nullptr, nullptr, nullptr, nullptr);
}

// round 9
// speedup vs baseline: 5.4836x; 1.0517x over previous
#include <cuda_runtime.h>
#include <cuda_fp16.h>
#include <math.h>
#include <stdint.h>

// Problem constants
#define Bb 2
#define Ss 4096
#define Dd 1024
#define Hh 16
#define HDh 64
#define Rr 16
#define Mm (Bb*Ss)            // 8192 rows

// ---------------- device scratch (all fp16) ------------------------------------------
__device__ __half g_Wq[Dd*Dd];
__device__ __half g_Wk[Dd*Dd];
__device__ __half g_Wv[Dd*Dd];
__device__ __half g_Wo[Dd*Dd];
__device__ __half g_X [(size_t)Mm*Dd];
__device__ __half g_Qh[(size_t)Mm*Dd];
__device__ __half g_Kh[(size_t)Mm*Dd];
__device__ __half g_Vt[(size_t)Mm*Dd];        // [b*16+h][64][4096] transposed V (fp16)
__device__ __half g_AO[(size_t)Mm*Dd];

#define CP16(dst, src) asm volatile("cp.async.cg.shared.global [%0], [%1], 16;" :: "r"(dst), "l"(src))

__device__ __forceinline__ uint32_t h2u(__half2 h) { return *(uint32_t*)&h; }
__device__ __forceinline__ float ex2f(float x) {
    float y; asm("ex2.approx.f32 %0, %1;" : "=f"(y) : "f"(x)); return y;
}

#define MMA_F16(d, a, b0, b1) \
    asm volatile("mma.sync.aligned.m16n8k16.row.col.f32.f16.f16.f32 " \
        "{%0,%1,%2,%3}, {%4,%5,%6,%7}, {%8,%9}, {%0,%1,%2,%3};" \
        : "+f"(d[0]), "+f"(d[1]), "+f"(d[2]), "+f"(d[3]) \
        : "r"(a[0]), "r"(a[1]), "r"(a[2]), "r"(a[3]), "r"(b0), "r"(b1))

#define LDSM4(r0, r1, r2, r3, addr) \
    asm volatile("ldmatrix.sync.aligned.m8n8.x4.shared.b16 {%0,%1,%2,%3}, [%4];" \
        : "=r"(r0), "=r"(r1), "=r"(r2), "=r"(r3) : "r"(addr))

// ---------------- W_eff = fp16( W + l2 @ l1 ), all 4 weights in one launch ----------
struct WeffArgs {
    const float* w[4]; const float* l1[4]; const float* l2[4]; __half* out[4];
};
__global__ void build_weff4_kernel(WeffArgs a) {
    int wi  = blockIdx.x >> 12;
    int idx = ((blockIdx.x & 4095) << 8) + threadIdx.x;
    int n = idx >> 10, k = idx & 1023;
    const float* l1 = a.l1[wi];
    const float* l2 = a.l2[wi];
    float acc = a.w[wi][idx];
#pragma unroll
    for (int r = 0; r < Rr; r++) acc += l2[n*Rr + r] * l1[r*Dd + k];
    a.out[wi][idx] = __float2half(acc);
}

__global__ void round_x_kernel(const float4* __restrict__ in, uint2* __restrict__ out) {
    int i = blockIdx.x * blockDim.x + threadIdx.x;
    float4 v = in[i];
    out[i] = make_uint2(h2u(__floats2half2_rn(v.x, v.y)), h2u(__floats2half2_rn(v.z, v.w)));
}

// ---------------- FP16 tensor-core GEMM (single-barrier 3-stage pipeline) ------------
// MODE 0: C = D + bias (fp32)
// MODE 1: Qh = fp16( rope(D + bias) * 0.125*log2(e) )   (scale folded for exp2 softmax)
// MODE 2: Kh = fp16(rope(D))
// MODE 3: Vt[(b*16+h)*64+d][s] = fp16(D)   (transposed V)
#define BM 128
#define BN 128
#define HBK 64
#define ROWB 144
#define HSTG (2*BM*ROWB)
#define GSTAGES 3
#define GEMM_SMEM (GSTAGES*HSTG)
#define NCH (Dd/HBK)
#define SCALE_Q 0.18033688011112042f      // 0.125 * log2(e)

template<int MODE>
__global__ __launch_bounds__(256) void hgemm_kernel(
    const __half* __restrict__ A, const __half* __restrict__ W,
    const float* __restrict__ bias, float* __restrict__ C,
    __half* __restrict__ Ph, __half* __restrict__ Vt,
    const float* __restrict__ fc, const float* __restrict__ fs)
{
    extern __shared__ char smc[];
    uint32_t sm_sh;
    asm("{ .reg .u64 t; cvta.to.shared.u64 t, %1; cvt.u32.u64 %0, t; }" : "=r"(sm_sh) : "l"(smc));

    const int tid  = threadIdx.x;
    const int bm   = blockIdx.y * BM;
    const int bn   = blockIdx.x * BN;
    const int warp = tid >> 5, lane = tid & 31;
    const int g = lane >> 2;
    const int q = lane & 3;
    const int wm = (warp >> 1) * 32;
    const int wn = (warp & 1) * 64;
    const uint32_t laneoff = (uint32_t)((lane & 15) * ROWB + ((lane >> 4) << 4));

    float acc[2][8][4] = {};

#define HLOAD(CH) do {                                                      \
        uint32_t _stg = sm_sh + (uint32_t)((CH) % GSTAGES) * HSTG;          \
        _Pragma("unroll")                                                   \
        for (int _j = 0; _j < 4; _j++) {                                    \
            int _cl = tid + 256*_j;                                         \
            int _row = _cl >> 3, _seg = _cl & 7;                            \
            uint32_t _off = (uint32_t)(_row*ROWB + _seg*16);                \
            CP16(_stg + _off,            A + (size_t)(bm + _row)*Dd + (CH)*HBK + _seg*8); \
            CP16(_stg + BM*ROWB + _off,  W + (size_t)(bn + _row)*Dd + (CH)*HBK + _seg*8); \
        }                                                                   \
        asm volatile("cp.async.commit_group;");                             \
    } while (0)

    HLOAD(0);
    HLOAD(1);

    for (int it = 0; it < NCH; it++) {
        if (it + 1 < NCH) asm volatile("cp.async.wait_group 1;");
        else              asm volatile("cp.async.wait_group 0;");
        __syncthreads();
        if (it + 2 < NCH) HLOAD(it + 2);

        uint32_t stg = sm_sh + (uint32_t)(it % GSTAGES) * HSTG;
        uint32_t aA = stg + (uint32_t)wm*ROWB + laneoff;
        uint32_t aB = stg + BM*ROWB + (uint32_t)wn*ROWB + laneoff;

#pragma unroll
        for (int kk = 0; kk < 4; kk++) {
            uint32_t af[2][4], bf[8][2];
            LDSM4(af[0][0], af[0][1], af[0][2], af[0][3], aA + kk*32);
            LDSM4(af[1][0], af[1][1], af[1][2], af[1][3], aA + 16*ROWB + kk*32);
#pragma unroll
            for (int p = 0; p < 4; p++) {
                uint32_t r0, r1, r2, r3;
                LDSM4(r0, r1, r2, r3, aB + p*16*ROWB + kk*32);
                bf[2*p][0] = r0; bf[2*p+1][0] = r1;
                bf[2*p][1] = r2; bf[2*p+1][1] = r3;
            }
#pragma unroll
            for (int mi = 0; mi < 2; mi++)
#pragma unroll
                for (int ni = 0; ni < 8; ni++)
                    MMA_F16(acc[mi][ni], af[mi], bf[ni][0], bf[ni][1]);
        }
    }
#undef HLOAD

    // ---------------- fused epilogues ----------------
    if (MODE == 0) {
#pragma unroll
        for (int mi = 0; mi < 2; mi++) {
            int r0 = bm + wm + mi*16 + g;
#pragma unroll
            for (int ni = 0; ni < 8; ni++) {
                int cn = bn + wn + ni*8 + q*2;
                float b0 = bias[cn], b1 = bias[cn+1];
                *(float2*)&C[(size_t)r0     *Dd + cn] = make_float2(acc[mi][ni][0]+b0, acc[mi][ni][1]+b1);
                *(float2*)&C[(size_t)(r0+8) *Dd + cn] = make_float2(acc[mi][ni][2]+b0, acc[mi][ni][3]+b1);
            }
        }
    } else if (MODE == 1 || MODE == 2) {
#pragma unroll
        for (int mi = 0; mi < 2; mi++) {
            int r0 = bm + wm + mi*16 + g;
            int s0 = r0 & (Ss-1), s1 = (r0+8) & (Ss-1);
#pragma unroll
            for (int ni = 0; ni < 8; ni++) {
                int cn = bn + wn + ni*8 + q*2;
                int p = (cn & 63) >> 1;
                float b0 = 0.f, b1 = 0.f;
                if (MODE == 1) { b0 = bias[cn]; b1 = bias[cn+1]; }
                float c0 = fc[s0*32+p], n0 = fs[s0*32+p];
                float c1 = fc[s1*32+p], n1 = fs[s1*32+p];
                float e0 = acc[mi][ni][0]+b0, o0 = acc[mi][ni][1]+b1;
                float e1 = acc[mi][ni][2]+b0, o1 = acc[mi][ni][3]+b1;
                float re0 = e0*c0 - o0*n0, im0 = e0*n0 + o0*c0;
                float re1 = e1*c1 - o1*n1, im1 = e1*n1 + o1*c1;
                if (MODE == 1) { re0 *= SCALE_Q; im0 *= SCALE_Q; re1 *= SCALE_Q; im1 *= SCALE_Q; }
                *(__half2*)&Ph[(size_t)r0    *Dd + cn] = __floats2half2_rn(re0, im0);
                *(__half2*)&Ph[(size_t)(r0+8)*Dd + cn] = __floats2half2_rn(re1, im1);
            }
        }
    } else {   // MODE 3: transposed fp16 V
#pragma unroll
        for (int mi = 0; mi < 2; mi++) {
            int r0 = bm + wm + mi*16 + g;
            int sl = r0 & (Ss-1);
            size_t bb = (size_t)(r0 >> 12);
#pragma unroll
            for (int ni = 0; ni < 8; ni++) {
                int cn = bn + wn + ni*8 + q*2;
                int hh = cn >> 6, dd = cn & 63;
                size_t vb = ((bb*Hh + hh)*HDh + dd) * (size_t)Ss;
                Vt[vb      + sl    ] = __float2half(acc[mi][ni][0]);
                Vt[vb + Ss + sl    ] = __float2half(acc[mi][ni][1]);
                Vt[vb      + sl + 8] = __float2half(acc[mi][ni][2]);
                Vt[vb + Ss + sl + 8] = __float2half(acc[mi][ni][3]);
            }
        }
    }
}

// ---------------- FP16 flash attention: register P, exp2 softmax, 4-stage ------------
#define AQ 128
#define AK 64
#define KPL (AK*ROWB)                     // 9216 per 64x64-half plane
#define STG_BYTES (2*KPL)                 // Kh + V = 18432 per stage
#define ASTAGES 4
#define OFF_Q (ASTAGES*STG_BYTES)         // 73728
#define ATTN_SMEM (OFF_Q + AQ*ROWB)       // +18432 = 92160

__global__ __launch_bounds__(256) void attn_mma_kernel(
    const __half* __restrict__ Qh, const __half* __restrict__ Kh,
    const __half* __restrict__ Vt, __half* __restrict__ O)
{
    extern __shared__ char smc[];
    uint32_t sm_sh;
    asm("{ .reg .u64 t; cvta.to.shared.u64 t, %1; cvt.u32.u64 %0, t; }" : "=r"(sm_sh) : "l"(smc));
    __half* sQ = (__half*)(smc + OFF_Q);

    const int tid = threadIdx.x;
    const int warp = tid >> 5, lane = tid & 31;
    const int g = lane >> 2, q = lane & 3;
    const int qt = 31 - blockIdx.x;          // heavy tiles first
    const int bh = blockIdx.y;
    const int b = bh >> 4, h = bh & 15;
    const size_t headoff = (size_t)b * Ss * Dd + (size_t)h * HDh;
    const size_t vhead = (size_t)bh * HDh * Ss;
    const int w16 = warp * 16;
    const uint32_t laneoff = (uint32_t)((lane & 15) * ROWB + ((lane >> 4) << 4));

    // ---- stage Q into smem, pull fragments via ldmatrix ----
    {
        const int r = tid >> 1, half = tid & 1;
        const __half* src = Qh + headoff + (size_t)(qt*AQ + r)*Dd + half*32;
        uint4* dst = (uint4*)(sQ + r*72 + half*32);
#pragma unroll
        for (int i = 0; i < 4; i++) dst[i] = ((const uint4*)src)[i];
    }
    __syncthreads();

    uint32_t aQ[4][4];
    {
        uint32_t qb = sm_sh + OFF_Q + (uint32_t)w16*ROWB + laneoff;
#pragma unroll
        for (int s = 0; s < 4; s++)
            LDSM4(aQ[s][0], aQ[s][1], aQ[s][2], aQ[s][3], qb + s*32);
    }

#define APREFETCH(KT) do {                                                          \
        uint32_t _stg = sm_sh + (uint32_t)((KT) % ASTAGES) * STG_BYTES;             \
        int _pl = tid >> 7;                 /* 0: K plane, 1: V plane */            \
        int _r = (tid & 127) >> 1;                                                  \
        int _half = tid & 1;                                                        \
        const __half* _gs;                                                          \
        if (_pl == 0) _gs = Kh + headoff + (size_t)((KT)*AK + _r)*Dd + _half*32;    \
        else          _gs = Vt + vhead + (size_t)_r*Ss + (KT)*AK + _half*32;        \
        uint32_t _dst = _stg + (_pl ? KPL : 0) + (uint32_t)(_r*ROWB + _half*64);    \
        _Pragma("unroll")                                                           \
        for (int _i = 0; _i < 4; _i++)                                              \
            CP16(_dst + _i*16, (const char*)_gs + _i*16);                           \
        asm volatile("cp.async.commit_group;");                                     \
    } while (0)

    float accO[8][4] = {};
    float m0 = -1e30f, m1 = -1e30f, l0 = 0.f, l1 = 0.f;
    const int nkt = 2*qt + 2;

    APREFETCH(0);
    APREFETCH(1);
    if (2 < nkt) APREFETCH(2);

    for (int kt = 0; kt < nkt; kt++) {
        if (kt + 3 <= nkt)      asm volatile("cp.async.wait_group 2;");
        else if (kt + 2 == nkt) asm volatile("cp.async.wait_group 1;");
        else                    asm volatile("cp.async.wait_group 0;");
        __syncthreads();
        if (kt + 3 < nkt) APREFETCH(kt + 3);   // writes slot drained at iter kt-1

        uint32_t stg = sm_sh + (uint32_t)(kt % ASTAGES) * STG_BYTES;
        uint32_t aK = stg + laneoff;
        uint32_t aV = aK + KPL;

        // S = q @ k^T  (Q pre-scaled by 0.125*log2e -> S in log2 domain)
        float S[8][4] = {};
#pragma unroll
        for (int s = 0; s < 4; s++) {
            uint32_t bk[8][2];
#pragma unroll
            for (int p = 0; p < 4; p++) {
                uint32_t r0, r1, r2, r3;
                LDSM4(r0, r1, r2, r3, aK + p*16*ROWB + s*32);
                bk[2*p][0] = r0; bk[2*p+1][0] = r1; bk[2*p][1] = r2; bk[2*p+1][1] = r3;
            }
#pragma unroll
            for (int ni = 0; ni < 8; ni++)
                MMA_F16(S[ni], aQ[s], bk[ni][0], bk[ni][1]);
        }

        // causal mask (only the last two tiles touch the diagonal)
        if (kt >= 2*qt) {
            const int r0g = qt*AQ + w16 + g, r1g = r0g + 8;
#pragma unroll
            for (int ni = 0; ni < 8; ni++) {
                int c = kt*AK + ni*8 + 2*q;
                if (c     > r0g) S[ni][0] = -1e30f;
                if (c + 1 > r0g) S[ni][1] = -1e30f;
                if (c     > r1g) S[ni][2] = -1e30f;
                if (c + 1 > r1g) S[ni][3] = -1e30f;
            }
        }

        // online softmax in log2 domain
        float mx0 = -1e30f, mx1 = -1e30f;
#pragma unroll
        for (int ni = 0; ni < 8; ni++) {
            mx0 = fmaxf(mx0, fmaxf(S[ni][0], S[ni][1]));
            mx1 = fmaxf(mx1, fmaxf(S[ni][2], S[ni][3]));
        }
        mx0 = fmaxf(mx0, __shfl_xor_sync(0xffffffffu, mx0, 1));
        mx0 = fmaxf(mx0, __shfl_xor_sync(0xffffffffu, mx0, 2));
        mx1 = fmaxf(mx1, __shfl_xor_sync(0xffffffffu, mx1, 1));
        mx1 = fmaxf(mx1, __shfl_xor_sync(0xffffffffu, mx1, 2));
        float mn0 = fmaxf(m0, mx0), mn1 = fmaxf(m1, mx1);
        if (__any_sync(0xffffffffu, (mn0 > m0) || (mn1 > m1))) {
            float cr0 = ex2f(m0 - mn0), cr1 = ex2f(m1 - mn1);
            m0 = mn0; m1 = mn1;
            l0 *= cr0; l1 *= cr1;
#pragma unroll
            for (int ni = 0; ni < 8; ni++) {
                accO[ni][0] *= cr0; accO[ni][1] *= cr0;
                accO[ni][2] *= cr1; accO[ni][3] *= cr1;
            }
        }
        float s0 = 0.f, s1 = 0.f;
#pragma unroll
        for (int ni = 0; ni < 8; ni++) {
            S[ni][0] = ex2f(S[ni][0] - m0);
            S[ni][1] = ex2f(S[ni][1] - m0);
            S[ni][2] = ex2f(S[ni][2] - m1);
            S[ni][3] = ex2f(S[ni][3] - m1);
            s0 += S[ni][0] + S[ni][1];
            s1 += S[ni][2] + S[ni][3];
        }
        s0 += __shfl_xor_sync(0xffffffffu, s0, 1);
        s0 += __shfl_xor_sync(0xffffffffu, s0, 2);
        s1 += __shfl_xor_sync(0xffffffffu, s1, 1);
        s1 += __shfl_xor_sync(0xffffffffu, s1, 2);
        l0 += s0;
        l1 += s1;

        // O += P @ V  — P taken directly from S registers (C-frag == A-frag layout)
#pragma unroll
        for (int s = 0; s < 4; s++) {
            uint32_t ap[4];
            ap[0] = h2u(__floats2half2_rn(S[2*s  ][0], S[2*s  ][1]));
            ap[1] = h2u(__floats2half2_rn(S[2*s  ][2], S[2*s  ][3]));
            ap[2] = h2u(__floats2half2_rn(S[2*s+1][0], S[2*s+1][1]));
            ap[3] = h2u(__floats2half2_rn(S[2*s+1][2], S[2*s+1][3]));
            uint32_t bv[8][2];
#pragma unroll
            for (int p = 0; p < 4; p++) {
                uint32_t r0, r1, r2, r3;
                LDSM4(r0, r1, r2, r3, aV + p*16*ROWB + s*32);
                bv[2*p][0] = r0; bv[2*p+1][0] = r1; bv[2*p][1] = r2; bv[2*p+1][1] = r3;
            }
#pragma unroll
            for (int ni = 0; ni < 8; ni++)
                MMA_F16(accO[ni], ap, bv[ni][0], bv[ni][1]);
        }
    }
#undef APREFETCH

    // epilogue: normalize, fp16-round (feeds fp16 O-projection), store
    float inv0 = 1.f / l0, inv1 = 1.f / l1;
    size_t base0 = headoff + (size_t)(qt*AQ + w16 + g) * Dd;
    size_t base1 = base0 + (size_t)8 * Dd;
#pragma unroll
    for (int ni = 0; ni < 8; ni++) {
        int c = ni*8 + 2*q;
        *(__half2*)&O[base0 + c] = __floats2half2_rn(accO[ni][0]*inv0, accO[ni][1]*inv0);
        *(__half2*)&O[base1 + c] = __floats2half2_rn(accO[ni][2]*inv1, accO[ni][3]*inv1);
    }
}

// ---------------- launch -------------------------------------------------------------
extern "C" void kernel_launch(void* const* d_in, const int* in_sizes, int n_in,
                              void* d_out, int out_size) {
    const float* x   = (const float*)d_in[0];
    const float* fc  = (const float*)d_in[1];
    const float* fs  = (const float*)d_in[2];
    const float* wq  = (const float*)d_in[4];
    const float* wqb = (const float*)d_in[5];
    const float* wk  = (const float*)d_in[6];
    const float* wv  = (const float*)d_in[7];
    const float* wo  = (const float*)d_in[8];
    const float* wob = (const float*)d_in[9];

    __half *Wq, *Wk, *Wv, *Wo, *Xr, *Qhp, *Khp, *Vtp, *AO;
    cudaGetSymbolAddress((void**)&Wq, g_Wq);
    cudaGetSymbolAddress((void**)&Wk, g_Wk);
    cudaGetSymbolAddress((void**)&Wv, g_Wv);
    cudaGetSymbolAddress((void**)&Wo, g_Wo);
    cudaGetSymbolAddress((void**)&Xr, g_X);
    cudaGetSymbolAddress((void**)&Qhp, g_Qh);
    cudaGetSymbolAddress((void**)&Khp, g_Kh);
    cudaGetSymbolAddress((void**)&Vtp, g_Vt);
    cudaGetSymbolAddress((void**)&AO, g_AO);

    cudaFuncSetAttribute(hgemm_kernel<0>, cudaFuncAttributeMaxDynamicSharedMemorySize, GEMM_SMEM);
    cudaFuncSetAttribute(hgemm_kernel<1>, cudaFuncAttributeMaxDynamicSharedMemorySize, GEMM_SMEM);
    cudaFuncSetAttribute(hgemm_kernel<2>, cudaFuncAttributeMaxDynamicSharedMemorySize, GEMM_SMEM);
    cudaFuncSetAttribute(hgemm_kernel<3>, cudaFuncAttributeMaxDynamicSharedMemorySize, GEMM_SMEM);
    cudaFuncSetAttribute(attn_mma_kernel, cudaFuncAttributeMaxDynamicSharedMemorySize, ATTN_SMEM);

    // 1. Fold LoRA into the 4 effective weights (fp16); round x to fp16
    WeffArgs wa;
    wa.w[0]=wq; wa.l1[0]=(const float*)d_in[10]; wa.l2[0]=(const float*)d_in[11]; wa.out[0]=Wq;
    wa.w[1]=wk; wa.l1[1]=(const float*)d_in[12]; wa.l2[1]=(const float*)d_in[13]; wa.out[1]=Wk;
    wa.w[2]=wv; wa.l1[2]=(const float*)d_in[14]; wa.l2[2]=(const float*)d_in[15]; wa.out[2]=Wv;
    wa.w[3]=wo; wa.l1[3]=(const float*)d_in[16]; wa.l2[3]=(const float*)d_in[17]; wa.out[3]=Wo;
    build_weff4_kernel<<<4*4096, 256>>>(wa);
    round_x_kernel<<<(Mm*Dd/4)/256, 256>>>((const float4*)x, (uint2*)Xr);

    // 2. Q/K/V projections (fp16 MMA) with fused RoPE (+scale on Q) and V transpose
    dim3 gg(Dd/BN, Mm/BM);
    hgemm_kernel<1><<<gg, 256, GEMM_SMEM>>>(Xr, Wq, wqb, nullptr, Qhp, nullptr, fc, fs);
    hgemm_kernel<2><<<gg, 256, GEMM_SMEM>>>(Xr, Wk, nullptr, nullptr, Khp, nullptr, fc, fs);
    hgemm_kernel<3><<<gg, 256, GEMM_SMEM>>>(Xr, Wv, nullptr, nullptr, nullptr, Vtp, nullptr, nullptr);

    // 3. FP16 flash attention (register P, exp2 softmax, 4-stage pipeline)
    dim3 ga(Ss/AQ, Bb*Hh);
    attn_mma_kernel<<<ga, 256, ATTN_SMEM>>>(Qhp, Khp, Vtp, AO);

    // 4. Output projection into d_out (fp32 + bias)
    hgemm_kernel<0><<<gg, 256, GEMM_SMEM>>>(AO, Wo, wob, (float*)d_out, nullptr, nullptr, nullptr, nullptr);
}

// round 10
// speedup vs baseline: 5.8988x; 1.0757x over previous
#include <cuda_runtime.h>
#include <cuda_fp16.h>
#include <math.h>
#include <stdint.h>

// Problem constants
#define Bb 2
#define Ss 4096
#define Dd 1024
#define Hh 16
#define HDh 64
#define Rr 16
#define Mm (Bb*Ss)            // 8192 rows

// ---------------- device scratch (all fp16) ------------------------------------------
__device__ __half g_Wq[Dd*Dd];
__device__ __half g_Wk[Dd*Dd];
__device__ __half g_Wv[Dd*Dd];
__device__ __half g_Wo[Dd*Dd];
__device__ __half g_X [(size_t)Mm*Dd];
__device__ __half g_Qh[(size_t)Mm*Dd];
__device__ __half g_Kh[(size_t)Mm*Dd];
__device__ __half g_Vt[(size_t)Mm*Dd];        // [b*16+h][64][4096] transposed V (fp16)
__device__ __half g_AO[(size_t)Mm*Dd];

#define CP16(dst, src) asm volatile("cp.async.cg.shared.global [%0], [%1], 16;" :: "r"(dst), "l"(src))

__device__ __forceinline__ uint32_t h2u(__half2 h) { return *(uint32_t*)&h; }
__device__ __forceinline__ float ex2f(float x) {
    float y; asm("ex2.approx.f32 %0, %1;" : "=f"(y) : "f"(x)); return y;
}

#define MMA_F16(d, a, b0, b1) \
    asm volatile("mma.sync.aligned.m16n8k16.row.col.f32.f16.f16.f32 " \
        "{%0,%1,%2,%3}, {%4,%5,%6,%7}, {%8,%9}, {%0,%1,%2,%3};" \
        : "+f"(d[0]), "+f"(d[1]), "+f"(d[2]), "+f"(d[3]) \
        : "r"(a[0]), "r"(a[1]), "r"(a[2]), "r"(a[3]), "r"(b0), "r"(b1))

#define LDSM4(r0, r1, r2, r3, addr) \
    asm volatile("ldmatrix.sync.aligned.m8n8.x4.shared.b16 {%0,%1,%2,%3}, [%4];" \
        : "=r"(r0), "=r"(r1), "=r"(r2), "=r"(r3) : "r"(addr))

// ---------------- W_eff = fp16( W + l2 @ l1 ), all 4 weights in one launch ----------
struct WeffArgs {
    const float* w[4]; const float* l1[4]; const float* l2[4]; __half* out[4];
};
__global__ void build_weff4_kernel(WeffArgs a) {
    int wi  = blockIdx.x >> 12;
    int idx = ((blockIdx.x & 4095) << 8) + threadIdx.x;
    int n = idx >> 10, k = idx & 1023;
    const float* l1 = a.l1[wi];
    const float* l2 = a.l2[wi];
    float acc = a.w[wi][idx];
#pragma unroll
    for (int r = 0; r < Rr; r++) acc += l2[n*Rr + r] * l1[r*Dd + k];
    a.out[wi][idx] = __float2half(acc);
}

__global__ void round_x_kernel(const float4* __restrict__ in, uint2* __restrict__ out) {
    int i = blockIdx.x * blockDim.x + threadIdx.x;
    float4 v = in[i];
    out[i] = make_uint2(h2u(__floats2half2_rn(v.x, v.y)), h2u(__floats2half2_rn(v.z, v.w)));
}

// ---------------- GEMM tiling constants ----------------------------------------------
#define BM 128
#define BN 128
#define HBK 64
#define ROWB 144
#define HSTG (2*BM*ROWB)
#define GSTAGES 3
#define GEMM_SMEM (GSTAGES*HSTG)
#define NCH (Dd/HBK)
#define SCALE_Q 0.18033688011112042f      // 0.125 * log2(e)

#define HLOAD(CH, Ap, Wp) do {                                              \
        uint32_t _stg = sm_sh + (uint32_t)((CH) % GSTAGES) * HSTG;          \
        _Pragma("unroll")                                                   \
        for (int _j = 0; _j < 4; _j++) {                                    \
            int _cl = tid + 256*_j;                                         \
            int _row = _cl >> 3, _seg = _cl & 7;                            \
            uint32_t _off = (uint32_t)(_row*ROWB + _seg*16);                \
            CP16(_stg + _off,            (Ap) + (size_t)(bm + _row)*Dd + (CH)*HBK + _seg*8); \
            CP16(_stg + BM*ROWB + _off,  (Wp) + (size_t)(bn + _row)*Dd + (CH)*HBK + _seg*8); \
        }                                                                   \
        asm volatile("cp.async.commit_group;");                             \
    } while (0)

#define GEMM_MAINLOOP(Ap, Wp)                                               \
    HLOAD(0, Ap, Wp);                                                       \
    HLOAD(1, Ap, Wp);                                                       \
    for (int it = 0; it < NCH; it++) {                                      \
        if (it + 1 < NCH) asm volatile("cp.async.wait_group 1;");           \
        else              asm volatile("cp.async.wait_group 0;");           \
        __syncthreads();                                                    \
        if (it + 2 < NCH) HLOAD(it + 2, Ap, Wp);                            \
        uint32_t stg = sm_sh + (uint32_t)(it % GSTAGES) * HSTG;             \
        uint32_t aA = stg + (uint32_t)wm*ROWB + laneoff;                    \
        uint32_t aB = stg + BM*ROWB + (uint32_t)wn*ROWB + laneoff;          \
        _Pragma("unroll")                                                   \
        for (int kk = 0; kk < 4; kk++) {                                    \
            uint32_t af[2][4], bf[8][2];                                    \
            LDSM4(af[0][0], af[0][1], af[0][2], af[0][3], aA + kk*32);      \
            LDSM4(af[1][0], af[1][1], af[1][2], af[1][3], aA + 16*ROWB + kk*32); \
            _Pragma("unroll")                                               \
            for (int p = 0; p < 4; p++) {                                   \
                uint32_t r0, r1, r2, r3;                                    \
                LDSM4(r0, r1, r2, r3, aB + p*16*ROWB + kk*32);              \
                bf[2*p][0] = r0; bf[2*p+1][0] = r1;                         \
                bf[2*p][1] = r2; bf[2*p+1][1] = r3;                         \
            }                                                               \
            _Pragma("unroll")                                               \
            for (int mi = 0; mi < 2; mi++)                                  \
                _Pragma("unroll")                                           \
                for (int ni = 0; ni < 8; ni++)                              \
                    MMA_F16(acc[mi][ni], af[mi], bf[ni][0], bf[ni][1]);     \
        }                                                                   \
    }

// ---------------- merged Q/K/V projection kernel (blockIdx.z selects) ----------------
__global__ __launch_bounds__(256) void qkv_gemm_kernel(
    const __half* __restrict__ X,
    const __half* __restrict__ Wq, const __half* __restrict__ Wk, const __half* __restrict__ Wv,
    const float* __restrict__ wqb,
    __half* __restrict__ Qh, __half* __restrict__ Kh, __half* __restrict__ Vt,
    const float* __restrict__ fc, const float* __restrict__ fs)
{
    extern __shared__ char smc[];
    uint32_t sm_sh;
    asm("{ .reg .u64 t; cvta.to.shared.u64 t, %1; cvt.u32.u64 %0, t; }" : "=r"(sm_sh) : "l"(smc));

    const int tid  = threadIdx.x;
    const int bm   = blockIdx.y * BM;
    const int bn   = blockIdx.x * BN;
    const int z    = blockIdx.z;              // 0=Q, 1=K, 2=V
    const int warp = tid >> 5, lane = tid & 31;
    const int g = lane >> 2;
    const int q = lane & 3;
    const int wm = (warp >> 1) * 32;
    const int wn = (warp & 1) * 64;
    const uint32_t laneoff = (uint32_t)((lane & 15) * ROWB + ((lane >> 4) << 4));

    const __half* W = (z == 0) ? Wq : (z == 1) ? Wk : Wv;
    float acc[2][8][4] = {};

    GEMM_MAINLOOP(X, W)

    if (z < 2) {          // Q or K: RoPE (+bias,+scale for Q) -> fp16
#pragma unroll
        for (int mi = 0; mi < 2; mi++) {
            int r0 = bm + wm + mi*16 + g;
            int s0 = r0 & (Ss-1), s1 = (r0+8) & (Ss-1);
            __half* Ph = (z == 0) ? Qh : Kh;
#pragma unroll
            for (int ni = 0; ni < 8; ni++) {
                int cn = bn + wn + ni*8 + q*2;
                int p = (cn & 63) >> 1;
                float b0 = 0.f, b1 = 0.f;
                if (z == 0) { b0 = wqb[cn]; b1 = wqb[cn+1]; }
                float c0 = fc[s0*32+p], n0 = fs[s0*32+p];
                float c1 = fc[s1*32+p], n1 = fs[s1*32+p];
                float e0 = acc[mi][ni][0]+b0, o0 = acc[mi][ni][1]+b1;
                float e1 = acc[mi][ni][2]+b0, o1 = acc[mi][ni][3]+b1;
                float re0 = e0*c0 - o0*n0, im0 = e0*n0 + o0*c0;
                float re1 = e1*c1 - o1*n1, im1 = e1*n1 + o1*c1;
                if (z == 0) { re0 *= SCALE_Q; im0 *= SCALE_Q; re1 *= SCALE_Q; im1 *= SCALE_Q; }
                *(__half2*)&Ph[(size_t)r0    *Dd + cn] = __floats2half2_rn(re0, im0);
                *(__half2*)&Ph[(size_t)(r0+8)*Dd + cn] = __floats2half2_rn(re1, im1);
            }
        }
    } else {              // V: transposed fp16
#pragma unroll
        for (int mi = 0; mi < 2; mi++) {
            int r0 = bm + wm + mi*16 + g;
            int sl = r0 & (Ss-1);
            size_t bb = (size_t)(r0 >> 12);
#pragma unroll
            for (int ni = 0; ni < 8; ni++) {
                int cn = bn + wn + ni*8 + q*2;
                int hh = cn >> 6, dd = cn & 63;
                size_t vb = ((bb*Hh + hh)*HDh + dd) * (size_t)Ss;
                Vt[vb      + sl    ] = __float2half(acc[mi][ni][0]);
                Vt[vb + Ss + sl    ] = __float2half(acc[mi][ni][1]);
                Vt[vb      + sl + 8] = __float2half(acc[mi][ni][2]);
                Vt[vb + Ss + sl + 8] = __float2half(acc[mi][ni][3]);
            }
        }
    }
}

// ---------------- output projection kernel (fp32 + bias into d_out) ------------------
__global__ __launch_bounds__(256) void oproj_gemm_kernel(
    const __half* __restrict__ A, const __half* __restrict__ W,
    const float* __restrict__ bias, float* __restrict__ C)
{
    extern __shared__ char smc[];
    uint32_t sm_sh;
    asm("{ .reg .u64 t; cvta.to.shared.u64 t, %1; cvt.u32.u64 %0, t; }" : "=r"(sm_sh) : "l"(smc));

    const int tid  = threadIdx.x;
    const int bm   = blockIdx.y * BM;
    const int bn   = blockIdx.x * BN;
    const int warp = tid >> 5, lane = tid & 31;
    const int g = lane >> 2;
    const int q = lane & 3;
    const int wm = (warp >> 1) * 32;
    const int wn = (warp & 1) * 64;
    const uint32_t laneoff = (uint32_t)((lane & 15) * ROWB + ((lane >> 4) << 4));

    float acc[2][8][4] = {};

    GEMM_MAINLOOP(A, W)

#pragma unroll
    for (int mi = 0; mi < 2; mi++) {
        int r0 = bm + wm + mi*16 + g;
#pragma unroll
        for (int ni = 0; ni < 8; ni++) {
            int cn = bn + wn + ni*8 + q*2;
            float b0 = bias[cn], b1 = bias[cn+1];
            *(float2*)&C[(size_t)r0     *Dd + cn] = make_float2(acc[mi][ni][0]+b0, acc[mi][ni][1]+b1);
            *(float2*)&C[(size_t)(r0+8) *Dd + cn] = make_float2(acc[mi][ni][2]+b0, acc[mi][ni][3]+b1);
        }
    }
}

// ---------------- FP16 flash attention: register P, deferred l-reduce ---------------
#define AQ 128
#define AK 64
#define KPL (AK*ROWB)                     // 9216 per 64x64-half plane
#define STG_BYTES (2*KPL)                 // Kh + V = 18432 per stage
#define ASTAGES 4
#define OFF_Q (ASTAGES*STG_BYTES)         // 73728
#define ATTN_SMEM (OFF_Q + AQ*ROWB)       // +18432 = 92160

__global__ __launch_bounds__(256) void attn_mma_kernel(
    const __half* __restrict__ Qh, const __half* __restrict__ Kh,
    const __half* __restrict__ Vt, __half* __restrict__ O)
{
    extern __shared__ char smc[];
    uint32_t sm_sh;
    asm("{ .reg .u64 t; cvta.to.shared.u64 t, %1; cvt.u32.u64 %0, t; }" : "=r"(sm_sh) : "l"(smc));
    __half* sQ = (__half*)(smc + OFF_Q);

    const int tid = threadIdx.x;
    const int warp = tid >> 5, lane = tid & 31;
    const int g = lane >> 2, q = lane & 3;
    const int qt = 31 - blockIdx.x;          // heavy tiles first
    const int bh = blockIdx.y;
    const int b = bh >> 4, h = bh & 15;
    const size_t headoff = (size_t)b * Ss * Dd + (size_t)h * HDh;
    const size_t vhead = (size_t)bh * HDh * Ss;
    const int w16 = warp * 16;
    const uint32_t laneoff = (uint32_t)((lane & 15) * ROWB + ((lane >> 4) << 4));

    // ---- stage Q into smem, pull fragments via ldmatrix ----
    {
        const int r = tid >> 1, half = tid & 1;
        const __half* src = Qh + headoff + (size_t)(qt*AQ + r)*Dd + half*32;
        uint4* dst = (uint4*)(sQ + r*72 + half*32);
#pragma unroll
        for (int i = 0; i < 4; i++) dst[i] = ((const uint4*)src)[i];
    }
    __syncthreads();

    uint32_t aQ[4][4];
    {
        uint32_t qb = sm_sh + OFF_Q + (uint32_t)w16*ROWB + laneoff;
#pragma unroll
        for (int s = 0; s < 4; s++)
            LDSM4(aQ[s][0], aQ[s][1], aQ[s][2], aQ[s][3], qb + s*32);
    }

#define APREFETCH(KT) do {                                                          \
        uint32_t _stg = sm_sh + (uint32_t)((KT) % ASTAGES) * STG_BYTES;             \
        int _pl = tid >> 7;                 /* 0: K plane, 1: V plane */            \
        int _r = (tid & 127) >> 1;                                                  \
        int _half = tid & 1;                                                        \
        const __half* _gs;                                                          \
        if (_pl == 0) _gs = Kh + headoff + (size_t)((KT)*AK + _r)*Dd + _half*32;    \
        else          _gs = Vt + vhead + (size_t)_r*Ss + (KT)*AK + _half*32;        \
        uint32_t _dst = _stg + (_pl ? KPL : 0) + (uint32_t)(_r*ROWB + _half*64);    \
        _Pragma("unroll")                                                           \
        for (int _i = 0; _i < 4; _i++)                                              \
            CP16(_dst + _i*16, (const char*)_gs + _i*16);                           \
        asm volatile("cp.async.commit_group;");                                     \
    } while (0)

    float accO[8][4] = {};
    float m0 = -1e30f, m1 = -1e30f, l0 = 0.f, l1 = 0.f;   // l0,l1: per-lane partials
    const int nkt = 2*qt + 2;

    APREFETCH(0);
    APREFETCH(1);
    if (2 < nkt) APREFETCH(2);

    for (int kt = 0; kt < nkt; kt++) {
        if (kt + 3 <= nkt)      asm volatile("cp.async.wait_group 2;");
        else if (kt + 2 == nkt) asm volatile("cp.async.wait_group 1;");
        else                    asm volatile("cp.async.wait_group 0;");
        __syncthreads();
        if (kt + 3 < nkt) APREFETCH(kt + 3);

        uint32_t stg = sm_sh + (uint32_t)(kt % ASTAGES) * STG_BYTES;
        uint32_t aK = stg + laneoff;
        uint32_t aV = aK + KPL;

        // S = q @ k^T  (Q pre-scaled by 0.125*log2e -> S in log2 domain)
        float S[8][4] = {};
#pragma unroll
        for (int s = 0; s < 4; s++) {
            uint32_t bk[8][2];
#pragma unroll
            for (int p = 0; p < 4; p++) {
                uint32_t r0, r1, r2, r3;
                LDSM4(r0, r1, r2, r3, aK + p*16*ROWB + s*32);
                bk[2*p][0] = r0; bk[2*p+1][0] = r1; bk[2*p][1] = r2; bk[2*p+1][1] = r3;
            }
#pragma unroll
            for (int ni = 0; ni < 8; ni++)
                MMA_F16(S[ni], aQ[s], bk[ni][0], bk[ni][1]);
        }

        // hoist V fragments for s=0 — independent of softmax, drains during MUFU work
        uint32_t bv0[8][2];
#pragma unroll
        for (int p = 0; p < 4; p++) {
            uint32_t r0, r1, r2, r3;
            LDSM4(r0, r1, r2, r3, aV + p*16*ROWB);
            bv0[2*p][0] = r0; bv0[2*p+1][0] = r1; bv0[2*p][1] = r2; bv0[2*p+1][1] = r3;
        }

        // causal mask (only the last two tiles touch the diagonal)
        if (kt >= 2*qt) {
            const int r0g = qt*AQ + w16 + g, r1g = r0g + 8;
#pragma unroll
            for (int ni = 0; ni < 8; ni++) {
                int c = kt*AK + ni*8 + 2*q;
                if (c     > r0g) S[ni][0] = -1e30f;
                if (c + 1 > r0g) S[ni][1] = -1e30f;
                if (c     > r1g) S[ni][2] = -1e30f;
                if (c + 1 > r1g) S[ni][3] = -1e30f;
            }
        }

        // online softmax in log2 domain (l kept as per-lane partials)
        float mx0 = -1e30f, mx1 = -1e30f;
#pragma unroll
        for (int ni = 0; ni < 8; ni++) {
            mx0 = fmaxf(mx0, fmaxf(S[ni][0], S[ni][1]));
            mx1 = fmaxf(mx1, fmaxf(S[ni][2], S[ni][3]));
        }
        mx0 = fmaxf(mx0, __shfl_xor_sync(0xffffffffu, mx0, 1));
        mx0 = fmaxf(mx0, __shfl_xor_sync(0xffffffffu, mx0, 2));
        mx1 = fmaxf(mx1, __shfl_xor_sync(0xffffffffu, mx1, 1));
        mx1 = fmaxf(mx1, __shfl_xor_sync(0xffffffffu, mx1, 2));
        float mn0 = fmaxf(m0, mx0), mn1 = fmaxf(m1, mx1);
        if (__any_sync(0xffffffffu, (mn0 > m0) || (mn1 > m1))) {
            float cr0 = ex2f(m0 - mn0), cr1 = ex2f(m1 - mn1);
            m0 = mn0; m1 = mn1;
            l0 *= cr0; l1 *= cr1;
#pragma unroll
            for (int ni = 0; ni < 8; ni++) {
                accO[ni][0] *= cr0; accO[ni][1] *= cr0;
                accO[ni][2] *= cr1; accO[ni][3] *= cr1;
            }
        }
#pragma unroll
        for (int ni = 0; ni < 8; ni++) {
            S[ni][0] = ex2f(S[ni][0] - m0);
            S[ni][1] = ex2f(S[ni][1] - m0);
            S[ni][2] = ex2f(S[ni][2] - m1);
            S[ni][3] = ex2f(S[ni][3] - m1);
            l0 += S[ni][0] + S[ni][1];
            l1 += S[ni][2] + S[ni][3];
        }

        // O += P @ V  — P taken directly from S registers (C-frag == A-frag layout)
#pragma unroll
        for (int s = 0; s < 4; s++) {
            uint32_t ap[4];
            ap[0] = h2u(__floats2half2_rn(S[2*s  ][0], S[2*s  ][1]));
            ap[1] = h2u(__floats2half2_rn(S[2*s  ][2], S[2*s  ][3]));
            ap[2] = h2u(__floats2half2_rn(S[2*s+1][0], S[2*s+1][1]));
            ap[3] = h2u(__floats2half2_rn(S[2*s+1][2], S[2*s+1][3]));
            if (s == 0) {
#pragma unroll
                for (int ni = 0; ni < 8; ni++)
                    MMA_F16(accO[ni], ap, bv0[ni][0], bv0[ni][1]);
            } else {
                uint32_t bv[8][2];
#pragma unroll
                for (int p = 0; p < 4; p++) {
                    uint32_t r0, r1, r2, r3;
                    LDSM4(r0, r1, r2, r3, aV + p*16*ROWB + s*32);
                    bv[2*p][0] = r0; bv[2*p+1][0] = r1; bv[2*p][1] = r2; bv[2*p+1][1] = r3;
                }
#pragma unroll
                for (int ni = 0; ni < 8; ni++)
                    MMA_F16(accO[ni], ap, bv[ni][0], bv[ni][1]);
            }
        }
    }
#undef APREFETCH

    // epilogue: reduce l partials across the quad, normalize, store fp16
    l0 += __shfl_xor_sync(0xffffffffu, l0, 1);
    l0 += __shfl_xor_sync(0xffffffffu, l0, 2);
    l1 += __shfl_xor_sync(0xffffffffu, l1, 1);
    l1 += __shfl_xor_sync(0xffffffffu, l1, 2);
    float inv0 = 1.f / l0, inv1 = 1.f / l1;
    size_t base0 = headoff + (size_t)(qt*AQ + w16 + g) * Dd;
    size_t base1 = base0 + (size_t)8 * Dd;
#pragma unroll
    for (int ni = 0; ni < 8; ni++) {
        int c = ni*8 + 2*q;
        *(__half2*)&O[base0 + c] = __floats2half2_rn(accO[ni][0]*inv0, accO[ni][1]*inv0);
        *(__half2*)&O[base1 + c] = __floats2half2_rn(accO[ni][2]*inv1, accO[ni][3]*inv1);
    }
}

// ---------------- launch -------------------------------------------------------------
extern "C" void kernel_launch(void* const* d_in, const int* in_sizes, int n_in,
                              void* d_out, int out_size) {
    const float* x   = (const float*)d_in[0];
    const float* fc  = (const float*)d_in[1];
    const float* fs  = (const float*)d_in[2];
    const float* wq  = (const float*)d_in[4];
    const float* wqb = (const float*)d_in[5];
    const float* wk  = (const float*)d_in[6];
    const float* wv  = (const float*)d_in[7];
    const float* wo  = (const float*)d_in[8];
    const float* wob = (const float*)d_in[9];

    __half *Wq, *Wk, *Wv, *Wo, *Xr, *Qhp, *Khp, *Vtp, *AO;
    cudaGetSymbolAddress((void**)&Wq, g_Wq);
    cudaGetSymbolAddress((void**)&Wk, g_Wk);
    cudaGetSymbolAddress((void**)&Wv, g_Wv);
    cudaGetSymbolAddress((void**)&Wo, g_Wo);
    cudaGetSymbolAddress((void**)&Xr, g_X);
    cudaGetSymbolAddress((void**)&Qhp, g_Qh);
    cudaGetSymbolAddress((void**)&Khp, g_Kh);
    cudaGetSymbolAddress((void**)&Vtp, g_Vt);
    cudaGetSymbolAddress((void**)&AO, g_AO);

    cudaFuncSetAttribute(qkv_gemm_kernel, cudaFuncAttributeMaxDynamicSharedMemorySize, GEMM_SMEM);
    cudaFuncSetAttribute(oproj_gemm_kernel, cudaFuncAttributeMaxDynamicSharedMemorySize, GEMM_SMEM);
    cudaFuncSetAttribute(attn_mma_kernel, cudaFuncAttributeMaxDynamicSharedMemorySize, ATTN_SMEM);

    // 1. Fold LoRA into the 4 effective weights (fp16); round x to fp16
    WeffArgs wa;
    wa.w[0]=wq; wa.l1[0]=(const float*)d_in[10]; wa.l2[0]=(const float*)d_in[11]; wa.out[0]=Wq;
    wa.w[1]=wk; wa.l1[1]=(const float*)d_in[12]; wa.l2[1]=(const float*)d_in[13]; wa.out[1]=Wk;
    wa.w[2]=wv; wa.l1[2]=(const float*)d_in[14]; wa.l2[2]=(const float*)d_in[15]; wa.out[2]=Wv;
    wa.w[3]=wo; wa.l1[3]=(const float*)d_in[16]; wa.l2[3]=(const float*)d_in[17]; wa.out[3]=Wo;
    build_weff4_kernel<<<4*4096, 256>>>(wa);
    round_x_kernel<<<(Mm*Dd/4)/256, 256>>>((const float4*)x, (uint2*)Xr);

    // 2. Q/K/V projections in ONE launch (z selects weight + epilogue)
    dim3 gq(Dd/BN, Mm/BM, 3);
    qkv_gemm_kernel<<<gq, 256, GEMM_SMEM>>>(Xr, Wq, Wk, Wv, wqb, Qhp, Khp, Vtp, fc, fs);

    // 3. FP16 flash attention (register P, exp2 softmax, deferred l-reduce)
    dim3 ga(Ss/AQ, Bb*Hh);
    attn_mma_kernel<<<ga, 256, ATTN_SMEM>>>(Qhp, Khp, Vtp, AO);

    // 4. Output projection into d_out (fp32 + bias)
    dim3 gg(Dd/BN, Mm/BM);
    oproj_gemm_kernel<<<gg, 256, GEMM_SMEM>>>(AO, Wo, wob, (float*)d_out);
}